// round 3
// baseline (speedup 1.0000x reference)
#include <cuda_runtime.h>
#include <math.h>

// Problem constants
#define NTOK 2048
#define HIDN 2048
#define NH   16
#define NKV  4
#define DH   128
#define HD   (NH*DH)     // 2048
#define KVD  (NKV*DH)    // 512
#define CH   64
#define NCH  (NTOK/CH)   // 32

// ---------------- scratch (static device globals; no allocation) -------------
__device__ float g_q   [NTOK*HD];      // raw q
__device__ float g_sq  [NTOK*HD];      // roped q
__device__ float g_qs  [NTOK*HD];      // softmax q
__device__ float g_k   [NTOK*KVD];     // raw k (== g)
__device__ float g_sk  [NTOK*KVD];     // roped k
__device__ float g_ks  [NTOK*KVD];     // softmax k
__device__ float g_gl  [NTOK*KVD];     // logsigmoid(g)/16
__device__ float g_v   [NTOK*KVD];     // raw v
__device__ float g_lam [NTOK*KVD];     // within-chunk cumulative exp(gl)
__device__ float g_kdl [NTOK*KVD];     // ks / lam
__device__ float g_dS  [NKV*NCH*DH*DH];// per-chunk delta state, then S_start (in place)
__device__ float g_ltot[NKV*NCH*DH];   // per-chunk total decay
__device__ float g_attn[NTOK*HD];      // attention branch output y
__device__ float g_gla [NTOK*HD];      // GLA branch output

// =============================================================================
// SGEMM: C = op(A) @ B, row-major. 128x128 tile, BK=16, 256 thr, 8x8 microtile.
// If A2 != null, the A operand is 0.5*(A + A2) (combine epilogue fused into the
// Wo GEMM). blockIdx.z selects (B0,C0) or (B1,C1) so k and v projections run in
// one launch.
// =============================================================================
__global__ void __launch_bounds__(256) sgemm_kernel(
    const float* __restrict__ A, const float* __restrict__ A2,
    const float* __restrict__ B0, float* __restrict__ C0,
    const float* __restrict__ B1, float* __restrict__ C1,
    int N, int K)
{
    const float* B = (blockIdx.z == 0) ? B0 : B1;
    float*       C = (blockIdx.z == 0) ? C0 : C1;

    __shared__ float As[16][132];
    __shared__ float Bs[16][132];

    const int bm = blockIdx.y * 128;
    const int bn = blockIdx.x * 128;
    const int tid = threadIdx.x;
    const int tx = tid & 15, ty = tid >> 4;

    const int arow = tid >> 2, acol = (tid & 3) << 2;   // A: 128x16 tile
    const int brow = tid >> 5, bcol = (tid & 31) << 2;  // B: 16x128 tile

    float acc[8][8];
#pragma unroll
    for (int i = 0; i < 8; i++)
#pragma unroll
        for (int j = 0; j < 8; j++) acc[i][j] = 0.0f;

    for (int k0 = 0; k0 < K; k0 += 16) {
#pragma unroll
        for (int i = 0; i < 2; i++) {
            int r = arow + i * 64;
            float4 a = *(const float4*)&A[(size_t)(bm + r) * K + k0 + acol];
            if (A2 != nullptr) {
                float4 a2 = *(const float4*)&A2[(size_t)(bm + r) * K + k0 + acol];
                a.x = 0.5f * (a.x + a2.x);
                a.y = 0.5f * (a.y + a2.y);
                a.z = 0.5f * (a.z + a2.z);
                a.w = 0.5f * (a.w + a2.w);
            }
            As[acol + 0][r] = a.x;
            As[acol + 1][r] = a.y;
            As[acol + 2][r] = a.z;
            As[acol + 3][r] = a.w;
        }
#pragma unroll
        for (int i = 0; i < 2; i++) {
            int r = brow + i * 8;
            *(float4*)&Bs[r][bcol] = *(const float4*)&B[(size_t)(k0 + r) * N + bn + bcol];
        }
        __syncthreads();

#pragma unroll
        for (int kk = 0; kk < 16; kk++) {
            float a[8], b[8];
            *(float4*)&a[0] = *(const float4*)&As[kk][ty * 8];
            *(float4*)&a[4] = *(const float4*)&As[kk][ty * 8 + 4];
            *(float4*)&b[0] = *(const float4*)&Bs[kk][tx * 8];
            *(float4*)&b[4] = *(const float4*)&Bs[kk][tx * 8 + 4];
#pragma unroll
            for (int i = 0; i < 8; i++)
#pragma unroll
                for (int j = 0; j < 8; j++) acc[i][j] += a[i] * b[j];
        }
        __syncthreads();
    }

#pragma unroll
    for (int i = 0; i < 8; i++) {
        int row = bm + ty * 8 + i;
        float4 o0 = make_float4(acc[i][0], acc[i][1], acc[i][2], acc[i][3]);
        float4 o1 = make_float4(acc[i][4], acc[i][5], acc[i][6], acc[i][7]);
        *(float4*)&C[(size_t)row * N + bn + tx * 8]     = o0;
        *(float4*)&C[(size_t)row * N + bn + tx * 8 + 4] = o1;
    }
}

// =============================================================================
// prep_q: per (token, head) row of 128: softmax -> g_qs, RoPE -> g_sq
// =============================================================================
__global__ void __launch_bounds__(128) prep_q_kernel()
{
    const int t = blockIdx.x, h = blockIdx.y;
    const int j = threadIdx.x;
    const int base = t * HD + h * DH;
    const float x = g_q[base + j];

    __shared__ float row[128];
    __shared__ float red[4];
    row[j] = x;

    float m = x;
#pragma unroll
    for (int o = 16; o; o >>= 1) m = fmaxf(m, __shfl_xor_sync(0xffffffffu, m, o));
    const int w = j >> 5;
    if ((j & 31) == 0) red[w] = m;
    __syncthreads();
    m = fmaxf(fmaxf(red[0], red[1]), fmaxf(red[2], red[3]));

    float e = expf(x - m);
    float s = e;
#pragma unroll
    for (int o = 16; o; o >>= 1) s += __shfl_xor_sync(0xffffffffu, s, o);
    __syncthreads();
    if ((j & 31) == 0) red[w] = s;
    __syncthreads();
    const float denom = red[0] + red[1] + red[2] + red[3];
    g_qs[base + j] = e / denom;

    if (j < 64) {
        float inv_freq = (float)pow(10000.0, -(double)(2 * j) / 128.0);
        float fr = (float)t * inv_freq;                  // fp32 rounding like ref
        double ang = (double)fr;
        float cs = (float)cos(ang);
        float sn = (float)sin(ang);
        float x1 = row[j], x2 = row[j + 64];
        g_sq[base + j]      = x1 * cs - x2 * sn;
        g_sq[base + j + 64] = x2 * cs + x1 * sn;
    }
}

// =============================================================================
// prep_k: per (token, kv-head): softmax -> g_ks, RoPE -> g_sk, logsig/16 -> g_gl
// =============================================================================
__global__ void __launch_bounds__(128) prep_k_kernel()
{
    const int t = blockIdx.x, kvh = blockIdx.y;
    const int j = threadIdx.x;
    const int base = t * KVD + kvh * DH;
    const float x = g_k[base + j];

    __shared__ float row[128];
    __shared__ float red[4];
    row[j] = x;

    float m = x;
#pragma unroll
    for (int o = 16; o; o >>= 1) m = fmaxf(m, __shfl_xor_sync(0xffffffffu, m, o));
    const int w = j >> 5;
    if ((j & 31) == 0) red[w] = m;
    __syncthreads();
    m = fmaxf(fmaxf(red[0], red[1]), fmaxf(red[2], red[3]));

    float e = expf(x - m);
    float s = e;
#pragma unroll
    for (int o = 16; o; o >>= 1) s += __shfl_xor_sync(0xffffffffu, s, o);
    __syncthreads();
    if ((j & 31) == 0) red[w] = s;
    __syncthreads();
    const float denom = red[0] + red[1] + red[2] + red[3];
    g_ks[base + j] = e / denom;

    // stable log-sigmoid: min(x,0) - log1p(exp(-|x|)), divided by 16
    float lsig = fminf(x, 0.0f) - log1pf(expf(-fabsf(x)));
    g_gl[base + j] = lsig * 0.0625f;

    if (j < 64) {
        float inv_freq = (float)pow(10000.0, -(double)(2 * j) / 128.0);
        float fr = (float)t * inv_freq;
        double ang = (double)fr;
        float cs = (float)cos(ang);
        float sn = (float)sin(ang);
        float x1 = row[j], x2 = row[j + 64];
        g_sk[base + j]      = x1 * cs - x2 * sn;
        g_sk[base + j + 64] = x2 * cs + x1 * sn;
    }
}

// =============================================================================
// GLA pass 1: per (chunk, kv-head): within-chunk gate prefix -> lam, kdl = ks/lam,
// kw = kdl * lam_end, dS = kw^T @ V (128x128, inner 64). State is per-KV-head.
// =============================================================================
__global__ void __launch_bounds__(256) gla_pass1_kernel()
{
    extern __shared__ float sm1[];
    float* G   = sm1;              // [64][132] : gl, then kw
    float* LAM = G   + 64 * 132;   // [64][132]
    float* V   = LAM + 64 * 132;   // [64][132]

    const int c = blockIdx.x, kvh = blockIdx.y;
    const int tid = threadIdx.x;

    for (int idx = tid; idx < CH * DH; idx += 256) {
        int r = idx >> 7, d = idx & 127;
        int gbase = (c * CH + r) * KVD + kvh * DH + d;
        G[r * 132 + d] = g_gl[gbase];
        V[r * 132 + d] = g_v[gbase];
    }
    __syncthreads();

    if (tid < 128) {
        float cum = 0.0f;
#pragma unroll 4
        for (int t = 0; t < CH; t++) {
            cum += G[t * 132 + tid];
            LAM[t * 132 + tid] = expf(cum);
        }
        g_ltot[(kvh * NCH + c) * DH + tid] = LAM[63 * 132 + tid];
    }
    __syncthreads();

    for (int idx = tid; idx < CH * DH; idx += 256) {
        int r = idx >> 7, d = idx & 127;
        int gbase = (c * CH + r) * KVD + kvh * DH + d;
        float lam = LAM[r * 132 + d];
        float kdl = g_ks[gbase] / lam;
        g_kdl[gbase] = kdl;
        g_lam[gbase] = lam;
        G[r * 132 + d] = kdl * LAM[63 * 132 + d];   // kw
    }
    __syncthreads();

    const int tx = tid & 15, ty = tid >> 4;
    float acc[8][8];
#pragma unroll
    for (int i = 0; i < 8; i++)
#pragma unroll
        for (int j = 0; j < 8; j++) acc[i][j] = 0.0f;

    for (int s = 0; s < CH; s++) {
        float a[8], b[8];
        *(float4*)&a[0] = *(const float4*)&G[s * 132 + ty * 8];
        *(float4*)&a[4] = *(const float4*)&G[s * 132 + ty * 8 + 4];
        *(float4*)&b[0] = *(const float4*)&V[s * 132 + tx * 8];
        *(float4*)&b[4] = *(const float4*)&V[s * 132 + tx * 8 + 4];
#pragma unroll
        for (int i = 0; i < 8; i++)
#pragma unroll
            for (int j = 0; j < 8; j++) acc[i][j] += a[i] * b[j];
    }

    float* dS = g_dS + (size_t)(kvh * NCH + c) * DH * DH;
#pragma unroll
    for (int i = 0; i < 8; i++) {
        *(float4*)&dS[(ty * 8 + i) * DH + tx * 8]     = make_float4(acc[i][0], acc[i][1], acc[i][2], acc[i][3]);
        *(float4*)&dS[(ty * 8 + i) * DH + tx * 8 + 4] = make_float4(acc[i][4], acc[i][5], acc[i][6], acc[i][7]);
    }
}

// =============================================================================
// GLA pass 2: sequential scan over chunks (in-place on g_dS):
//   S_start[0]=0; S_start[c] = ltot[c-1]*S_start[c-1] + dS[c-1]
// grid (NKV, DH), 128 threads (one per d')
// =============================================================================
__global__ void __launch_bounds__(128) gla_scan_kernel()
{
    const int kvh = blockIdx.x, d = blockIdx.y;
    const int dp = threadIdx.x;
    float s = 0.0f;
    for (int c = 0; c < NCH; c++) {
        size_t idx = ((size_t)(kvh * NCH + c) * DH + d) * DH + dp;
        float tmp = g_dS[idx];
        float lt = g_ltot[(kvh * NCH + c) * DH + d];
        g_dS[idx] = s;
        s = s * lt + tmp;
    }
}

// =============================================================================
// GLA pass 3: per (chunk, head):
//   O = (qs*lam) @ S_start + tril((qs*lam)@(ks/lam)^T) @ V   -> g_gla
// =============================================================================
__global__ void __launch_bounds__(256) gla_pass3_kernel()
{
    extern __shared__ float sm3[];
    float* QT = sm3;               // [128][65]  (qs*lam transposed: [d][t])
    float* KT = QT + 128 * 65;     // [128][65]  (kdl transposed)
    float* Ss = KT + 128 * 65;     // [128][132] (S_start)
    float* Vs = Ss + 128 * 132;    // [64][132]
    float* AT = Vs + 64 * 132;     // [64][65]   (A transposed: [s][t])

    const int c = blockIdx.x, h = blockIdx.y;
    const int kvh = h >> 2;
    const int tid = threadIdx.x;

    for (int idx = tid; idx < CH * DH; idx += 256) {
        int r = idx >> 7, d = idx & 127;
        int kb = (c * CH + r) * KVD + kvh * DH + d;
        float lam = g_lam[kb];
        QT[d * 65 + r] = g_qs[(c * CH + r) * HD + h * DH + d] * lam;
        KT[d * 65 + r] = g_kdl[kb];
        Vs[r * 132 + d] = g_v[kb];
    }
    const float* Sg = g_dS + (size_t)(kvh * NCH + c) * DH * DH;
    for (int idx = tid; idx < DH * DH; idx += 256) {
        int r = idx >> 7, d = idx & 127;
        Ss[r * 132 + d] = Sg[r * DH + d];
    }
    __syncthreads();

    const int tx = tid & 15, ty = tid >> 4;

    // inter-chunk: O[t][d'] = sum_d QT[d][t] * Ss[d][d']
    float O[4][8];
#pragma unroll
    for (int i = 0; i < 4; i++)
#pragma unroll
        for (int j = 0; j < 8; j++) O[i][j] = 0.0f;

    for (int dd = 0; dd < DH; dd++) {
        float a[4], b[8];
#pragma unroll
        for (int i = 0; i < 4; i++) a[i] = QT[dd * 65 + ty * 4 + i];
        *(float4*)&b[0] = *(const float4*)&Ss[dd * 132 + tx * 8];
        *(float4*)&b[4] = *(const float4*)&Ss[dd * 132 + tx * 8 + 4];
#pragma unroll
        for (int i = 0; i < 4; i++)
#pragma unroll
            for (int j = 0; j < 8; j++) O[i][j] += a[i] * b[j];
    }

    // intra-chunk score: A[t][s] = sum_d QT[d][t] * KT[d][s], masked s<=t
    float Aacc[4][4];
#pragma unroll
    for (int i = 0; i < 4; i++)
#pragma unroll
        for (int j = 0; j < 4; j++) Aacc[i][j] = 0.0f;

    for (int dd = 0; dd < DH; dd++) {
        float a[4], b[4];
#pragma unroll
        for (int i = 0; i < 4; i++) a[i] = QT[dd * 65 + ty * 4 + i];
#pragma unroll
        for (int j = 0; j < 4; j++) b[j] = KT[dd * 65 + tx * 4 + j];
#pragma unroll
        for (int i = 0; i < 4; i++)
#pragma unroll
            for (int j = 0; j < 4; j++) Aacc[i][j] += a[i] * b[j];
    }
#pragma unroll
    for (int i = 0; i < 4; i++)
#pragma unroll
        for (int j = 0; j < 4; j++) {
            int t = ty * 4 + i, s = tx * 4 + j;
            AT[s * 65 + t] = (s <= t) ? Aacc[i][j] : 0.0f;
        }
    __syncthreads();

    for (int s = 0; s < CH; s++) {
        float a[4], b[8];
#pragma unroll
        for (int i = 0; i < 4; i++) a[i] = AT[s * 65 + ty * 4 + i];
        *(float4*)&b[0] = *(const float4*)&Vs[s * 132 + tx * 8];
        *(float4*)&b[4] = *(const float4*)&Vs[s * 132 + tx * 8 + 4];
#pragma unroll
        for (int i = 0; i < 4; i++)
#pragma unroll
            for (int j = 0; j < 8; j++) O[i][j] += a[i] * b[j];
    }

#pragma unroll
    for (int i = 0; i < 4; i++) {
        int t = c * CH + ty * 4 + i;
        *(float4*)&g_gla[t * HD + h * DH + tx * 8]     = make_float4(O[i][0], O[i][1], O[i][2], O[i][3]);
        *(float4*)&g_gla[t * HD + h * DH + tx * 8 + 4] = make_float4(O[i][4], O[i][5], O[i][6], O[i][7]);
    }
}

// =============================================================================
// Causal flash attention (fp32). block = (q-tile of 64, head). 256 threads.
// =============================================================================
__global__ void __launch_bounds__(256) attn_kernel()
{
    extern __shared__ float smA[];
    float* QsT = smA;               // [128][65]  Q transposed: [k][r]
    float* KsT = QsT + 128 * 65;    // [128][65]
    float* Vs  = KsT + 128 * 65;    // [64][132]
    float* PT  = Vs  + 64 * 132;    // [64][65]   P transposed: [s][r]

    const int qt = blockIdx.x, h = blockIdx.y;
    const int kvh = h >> 2;
    const int tid = threadIdx.x;
    const int tx = tid & 15, ty = tid >> 4;
    const float scale = 0.08838834764831845f;   // 128^-0.5

    for (int idx = tid; idx < 64 * 128; idx += 256) {
        int r = idx >> 7, d = idx & 127;
        QsT[d * 65 + r] = g_sq[(qt * 64 + r) * HD + h * DH + d];
    }

    float m_i[4], l_i[4], O[4][8];
#pragma unroll
    for (int i = 0; i < 4; i++) { m_i[i] = -1e30f; l_i[i] = 0.0f; }
#pragma unroll
    for (int i = 0; i < 4; i++)
#pragma unroll
        for (int j = 0; j < 8; j++) O[i][j] = 0.0f;

    for (int kt = 0; kt <= qt; kt++) {
        __syncthreads();
        for (int idx = tid; idx < 64 * 128; idx += 256) {
            int r = idx >> 7, d = idx & 127;
            int kb = (kt * 64 + r) * KVD + kvh * DH + d;
            KsT[d * 65 + r] = g_sk[kb];
            Vs[r * 132 + d] = g_v[kb];
        }
        __syncthreads();

        float sacc[4][4];
#pragma unroll
        for (int i = 0; i < 4; i++)
#pragma unroll
            for (int j = 0; j < 4; j++) sacc[i][j] = 0.0f;

        for (int k = 0; k < 128; k++) {
            float a[4], b[4];
#pragma unroll
            for (int i = 0; i < 4; i++) a[i] = QsT[k * 65 + ty * 4 + i];
#pragma unroll
            for (int j = 0; j < 4; j++) b[j] = KsT[k * 65 + tx * 4 + j];
#pragma unroll
            for (int i = 0; i < 4; i++)
#pragma unroll
                for (int j = 0; j < 4; j++) sacc[i][j] += a[i] * b[j];
        }

        const bool diag = (kt == qt);
#pragma unroll
        for (int i = 0; i < 4; i++) {
            int r = ty * 4 + i;
            float rowmax = -1e30f;
#pragma unroll
            for (int j = 0; j < 4; j++) {
                float s = sacc[i][j] * scale;
                if (diag && (tx * 4 + j) > r) s = -1e30f;
                sacc[i][j] = s;
                rowmax = fmaxf(rowmax, s);
            }
#pragma unroll
            for (int o = 1; o < 16; o <<= 1)
                rowmax = fmaxf(rowmax, __shfl_xor_sync(0xffffffffu, rowmax, o));
            float mnew = fmaxf(m_i[i], rowmax);
            float alpha = expf(m_i[i] - mnew);
            float rowsum = 0.0f;
#pragma unroll
            for (int j = 0; j < 4; j++) {
                float p = expf(sacc[i][j] - mnew);
                sacc[i][j] = p;
                rowsum += p;
            }
#pragma unroll
            for (int o = 1; o < 16; o <<= 1)
                rowsum += __shfl_xor_sync(0xffffffffu, rowsum, o);
            l_i[i] = l_i[i] * alpha + rowsum;
            m_i[i] = mnew;
#pragma unroll
            for (int j = 0; j < 8; j++) O[i][j] *= alpha;
#pragma unroll
            for (int j = 0; j < 4; j++)
                PT[(tx * 4 + j) * 65 + r] = sacc[i][j];
        }
        __syncthreads();

        for (int s = 0; s < 64; s++) {
            float a[4], b[8];
#pragma unroll
            for (int i = 0; i < 4; i++) a[i] = PT[s * 65 + ty * 4 + i];
            *(float4*)&b[0] = *(const float4*)&Vs[s * 132 + tx * 8];
            *(float4*)&b[4] = *(const float4*)&Vs[s * 132 + tx * 8 + 4];
#pragma unroll
            for (int i = 0; i < 4; i++)
#pragma unroll
                for (int j = 0; j < 8; j++) O[i][j] += a[i] * b[j];
        }
    }

#pragma unroll
    for (int i = 0; i < 4; i++) {
        float inv = 1.0f / l_i[i];
        int t = qt * 64 + ty * 4 + i;
        float4 o0 = make_float4(O[i][0]*inv, O[i][1]*inv, O[i][2]*inv, O[i][3]*inv);
        float4 o1 = make_float4(O[i][4]*inv, O[i][5]*inv, O[i][6]*inv, O[i][7]*inv);
        *(float4*)&g_attn[t * HD + h * DH + tx * 8]     = o0;
        *(float4*)&g_attn[t * HD + h * DH + tx * 8 + 4] = o1;
    }
}

// =============================================================================
// host launcher
// =============================================================================
extern "C" void kernel_launch(void* const* d_in, const int* in_sizes, int n_in,
                              void* d_out, int out_size)
{
    (void)in_sizes; (void)n_in; (void)out_size;
    const float* hs = (const float*)d_in[0];
    const float* Wq = (const float*)d_in[1];
    const float* Wk = (const float*)d_in[2];
    const float* Wv = (const float*)d_in[3];
    const float* Wo = (const float*)d_in[4];
    float* out = (float*)d_out;

    float *p_q, *p_k, *p_v, *p_attn, *p_gla;
    cudaGetSymbolAddress((void**)&p_q,    g_q);
    cudaGetSymbolAddress((void**)&p_k,    g_k);
    cudaGetSymbolAddress((void**)&p_v,    g_v);
    cudaGetSymbolAddress((void**)&p_attn, g_attn);
    cudaGetSymbolAddress((void**)&p_gla,  g_gla);

    const int smem1 = 3 * 64 * 132 * 4;                                   // 101376
    const int smem3 = (2 * 128 * 65 + 128 * 132 + 64 * 132 + 64 * 65) * 4; // 184576
    const int smemA = (2 * 128 * 65 + 64 * 132 + 64 * 65) * 4;             // 116992
    cudaFuncSetAttribute(gla_pass1_kernel, cudaFuncAttributeMaxDynamicSharedMemorySize, smem1);
    cudaFuncSetAttribute(gla_pass3_kernel, cudaFuncAttributeMaxDynamicSharedMemorySize, smem3);
    cudaFuncSetAttribute(attn_kernel,      cudaFuncAttributeMaxDynamicSharedMemorySize, smemA);

    // 1. q = hs @ Wq  (2048x2048x2048)
    sgemm_kernel<<<dim3(16, 16, 1), 256>>>(hs, nullptr, Wq, p_q, Wq, p_q, HD, HIDN);
    // 2. k = hs @ Wk, v = hs @ Wv (z picks)
    sgemm_kernel<<<dim3(4, 16, 2), 256>>>(hs, nullptr, Wk, p_k, Wv, p_v, KVD, HIDN);
    // 3. prep: softmax / rope / gates
    prep_q_kernel<<<dim3(NTOK, NH), 128>>>();
    prep_k_kernel<<<dim3(NTOK, NKV), 128>>>();
    // 4. GLA chunked
    gla_pass1_kernel<<<dim3(NCH, NKV), 256, smem1>>>();
    gla_scan_kernel<<<dim3(NKV, DH), 128>>>();
    gla_pass3_kernel<<<dim3(NCH, NH), 256, smem3>>>();
    // 5. causal flash attention
    attn_kernel<<<dim3(NTOK / 64, NH), 256, smemA>>>();
    // 6. out = (0.5*(y + o_gla)) @ Wo
    sgemm_kernel<<<dim3(16, 16, 1), 256>>>(p_attn, p_gla, Wo, out, Wo, out, HIDN, HD);
}

// round 4
// speedup vs baseline: 2.0033x; 2.0033x over previous
#include <cuda_runtime.h>
#include <math.h>

// Problem constants
#define NTOK 2048
#define HIDN 2048
#define NH   16
#define NKV  4
#define DH   128
#define HD   (NH*DH)     // 2048
#define KVD  (NKV*DH)    // 512
#define CH   64
#define NCH  (NTOK/CH)   // 32

// ---------------- scratch (static device globals; no allocation) -------------
__device__ float g_q   [NTOK*HD];      // raw q
__device__ float g_sq  [NTOK*HD];      // roped q
__device__ float g_qs  [NTOK*HD];      // softmax q
__device__ float g_k   [NTOK*KVD];     // raw k (== g)
__device__ float g_sk  [NTOK*KVD];     // roped k
__device__ float g_ks  [NTOK*KVD];     // softmax k
__device__ float g_gl  [NTOK*KVD];     // logsigmoid(g)/16
__device__ float g_v   [NTOK*KVD];     // raw v
__device__ float g_lam [NTOK*KVD];     // within-chunk cumulative exp(gl)
__device__ float g_kdl [NTOK*KVD];     // ks / lam
__device__ float g_dS  [NKV*NCH*DH*DH];// per-chunk delta state, then S_start
__device__ float g_ltot[NKV*NCH*DH];   // per-chunk total decay
__device__ float g_attn[NTOK*HD];      // attention branch output y
__device__ float g_gla [NTOK*HD];      // GLA branch output

// ---------------- tf32 mma helpers ------------------------------------------
__device__ __forceinline__ unsigned f2tf(float x) {
    unsigned r;
    asm("cvt.rna.tf32.f32 %0, %1;" : "=r"(r) : "f"(x));
    return r;
}

__device__ __forceinline__ void mma_tf32(float c[4], const unsigned a[4],
                                         unsigned b0, unsigned b1) {
    asm volatile(
        "mma.sync.aligned.m16n8k8.row.col.f32.tf32.tf32.f32 "
        "{%0,%1,%2,%3}, {%4,%5,%6,%7}, {%8,%9}, {%0,%1,%2,%3};"
        : "+f"(c[0]), "+f"(c[1]), "+f"(c[2]), "+f"(c[3])
        : "r"(a[0]), "r"(a[1]), "r"(a[2]), "r"(a[3]), "r"(b0), "r"(b1));
}

// =============================================================================
// TF32 tensor-core GEMM: C = op(A) @ B, row-major. 128x128 tile, BK=16,
// 128 threads (4 warps, 2x2, warp tile 64x64). Register-prefetched loads.
// A2 != null -> A operand is 0.5*(A+A2). blockIdx.z selects (B0,C0)/(B1,C1).
// =============================================================================
__global__ void __launch_bounds__(128) mm_tf32_kernel(
    const float* __restrict__ A, const float* __restrict__ A2,
    const float* __restrict__ B0, float* __restrict__ C0,
    const float* __restrict__ B1, float* __restrict__ C1,
    int N, int K)
{
    const float* B = (blockIdx.z == 0) ? B0 : B1;
    float*       C = (blockIdx.z == 0) ? C0 : C1;

    __shared__ __align__(16) unsigned As[128 * 20];  // [m][k], stride 20 (==4 mod 32)
    __shared__ __align__(16) unsigned Bs[16 * 136];  // [k][n], stride 136 (==8 mod 32)

    const int tid  = threadIdx.x;
    const int warp = tid >> 5, lane = tid & 31;
    const int gid  = lane >> 2, tig = lane & 3;
    const int wm   = (warp & 1) * 64, wn = (warp >> 1) * 64;
    const int bm   = blockIdx.y * 128, bn = blockIdx.x * 128;

    // global-load mapping
    const float* Arow  = A  + (size_t)(bm + tid) * K;
    const float* A2row = A2 ? (A2 + (size_t)(bm + tid) * K) : nullptr;
    const int rb = tid >> 3;              // B row 0..15
    const int cb = (tid & 7) * 16;        // B col start (16 floats per thread)

    float c[4][8][4];
#pragma unroll
    for (int mi = 0; mi < 4; mi++)
#pragma unroll
        for (int ni = 0; ni < 8; ni++)
#pragma unroll
            for (int v = 0; v < 4; v++) c[mi][ni][v] = 0.0f;

    float4 pa[4], pb[4];
#pragma unroll
    for (int q = 0; q < 4; q++) {
        pa[q] = *(const float4*)&Arow[q * 4];
        if (A2row) {
            float4 a2 = *(const float4*)&A2row[q * 4];
            pa[q].x = 0.5f * (pa[q].x + a2.x); pa[q].y = 0.5f * (pa[q].y + a2.y);
            pa[q].z = 0.5f * (pa[q].z + a2.z); pa[q].w = 0.5f * (pa[q].w + a2.w);
        }
        pb[q] = *(const float4*)&B[(size_t)rb * N + bn + cb + q * 4];
    }

    for (int k0 = 0; k0 < K; k0 += 16) {
        __syncthreads();
#pragma unroll
        for (int q = 0; q < 4; q++) {
            uint4 ua = make_uint4(f2tf(pa[q].x), f2tf(pa[q].y), f2tf(pa[q].z), f2tf(pa[q].w));
            *(uint4*)&As[tid * 20 + q * 4] = ua;
            uint4 ub = make_uint4(f2tf(pb[q].x), f2tf(pb[q].y), f2tf(pb[q].z), f2tf(pb[q].w));
            *(uint4*)&Bs[rb * 136 + cb + q * 4] = ub;
        }
        __syncthreads();

        if (k0 + 16 < K) {
#pragma unroll
            for (int q = 0; q < 4; q++) {
                pa[q] = *(const float4*)&Arow[k0 + 16 + q * 4];
                if (A2row) {
                    float4 a2 = *(const float4*)&A2row[k0 + 16 + q * 4];
                    pa[q].x = 0.5f * (pa[q].x + a2.x); pa[q].y = 0.5f * (pa[q].y + a2.y);
                    pa[q].z = 0.5f * (pa[q].z + a2.z); pa[q].w = 0.5f * (pa[q].w + a2.w);
                }
                pb[q] = *(const float4*)&B[(size_t)(k0 + 16 + rb) * N + bn + cb + q * 4];
            }
        }

#pragma unroll
        for (int kk = 0; kk < 16; kk += 8) {
            unsigned af[4][4];
#pragma unroll
            for (int mi = 0; mi < 4; mi++) {
                int r = wm + mi * 16 + gid;
                af[mi][0] = As[r * 20 + kk + tig];
                af[mi][1] = As[(r + 8) * 20 + kk + tig];
                af[mi][2] = As[r * 20 + kk + tig + 4];
                af[mi][3] = As[(r + 8) * 20 + kk + tig + 4];
            }
#pragma unroll
            for (int ni = 0; ni < 8; ni++) {
                unsigned b0 = Bs[(kk + tig) * 136 + wn + ni * 8 + gid];
                unsigned b1 = Bs[(kk + tig + 4) * 136 + wn + ni * 8 + gid];
#pragma unroll
                for (int mi = 0; mi < 4; mi++) mma_tf32(c[mi][ni], af[mi], b0, b1);
            }
        }
    }

#pragma unroll
    for (int mi = 0; mi < 4; mi++) {
        int r0 = bm + wm + mi * 16 + gid;
#pragma unroll
        for (int ni = 0; ni < 8; ni++) {
            int col = bn + wn + ni * 8 + tig * 2;
            *(float2*)&C[(size_t)r0 * N + col]       = make_float2(c[mi][ni][0], c[mi][ni][1]);
            *(float2*)&C[(size_t)(r0 + 8) * N + col] = make_float2(c[mi][ni][2], c[mi][ni][3]);
        }
    }
}

// =============================================================================
// prep_q: per (token, head) row of 128: softmax -> g_qs, RoPE -> g_sq
// =============================================================================
__global__ void __launch_bounds__(128) prep_q_kernel()
{
    const int t = blockIdx.x, h = blockIdx.y;
    const int j = threadIdx.x;
    const int base = t * HD + h * DH;
    const float x = g_q[base + j];

    __shared__ float row[128];
    __shared__ float red[4];
    row[j] = x;

    float m = x;
#pragma unroll
    for (int o = 16; o; o >>= 1) m = fmaxf(m, __shfl_xor_sync(0xffffffffu, m, o));
    const int w = j >> 5;
    if ((j & 31) == 0) red[w] = m;
    __syncthreads();
    m = fmaxf(fmaxf(red[0], red[1]), fmaxf(red[2], red[3]));

    float e = expf(x - m);
    float s = e;
#pragma unroll
    for (int o = 16; o; o >>= 1) s += __shfl_xor_sync(0xffffffffu, s, o);
    __syncthreads();
    if ((j & 31) == 0) red[w] = s;
    __syncthreads();
    const float denom = red[0] + red[1] + red[2] + red[3];
    g_qs[base + j] = e / denom;

    if (j < 64) {
        float inv_freq = (float)pow(10000.0, -(double)(2 * j) / 128.0);
        float fr = (float)t * inv_freq;
        double ang = (double)fr;
        float cs = (float)cos(ang);
        float sn = (float)sin(ang);
        float x1 = row[j], x2 = row[j + 64];
        g_sq[base + j]      = x1 * cs - x2 * sn;
        g_sq[base + j + 64] = x2 * cs + x1 * sn;
    }
}

// =============================================================================
// prep_k: per (token, kv-head): softmax -> g_ks, RoPE -> g_sk, logsig/16 -> g_gl
// =============================================================================
__global__ void __launch_bounds__(128) prep_k_kernel()
{
    const int t = blockIdx.x, kvh = blockIdx.y;
    const int j = threadIdx.x;
    const int base = t * KVD + kvh * DH;
    const float x = g_k[base + j];

    __shared__ float row[128];
    __shared__ float red[4];
    row[j] = x;

    float m = x;
#pragma unroll
    for (int o = 16; o; o >>= 1) m = fmaxf(m, __shfl_xor_sync(0xffffffffu, m, o));
    const int w = j >> 5;
    if ((j & 31) == 0) red[w] = m;
    __syncthreads();
    m = fmaxf(fmaxf(red[0], red[1]), fmaxf(red[2], red[3]));

    float e = expf(x - m);
    float s = e;
#pragma unroll
    for (int o = 16; o; o >>= 1) s += __shfl_xor_sync(0xffffffffu, s, o);
    __syncthreads();
    if ((j & 31) == 0) red[w] = s;
    __syncthreads();
    const float denom = red[0] + red[1] + red[2] + red[3];
    g_ks[base + j] = e / denom;

    float lsig = fminf(x, 0.0f) - log1pf(expf(-fabsf(x)));
    g_gl[base + j] = lsig * 0.0625f;

    if (j < 64) {
        float inv_freq = (float)pow(10000.0, -(double)(2 * j) / 128.0);
        float fr = (float)t * inv_freq;
        double ang = (double)fr;
        float cs = (float)cos(ang);
        float sn = (float)sin(ang);
        float x1 = row[j], x2 = row[j + 64];
        g_sk[base + j]      = x1 * cs - x2 * sn;
        g_sk[base + j + 64] = x2 * cs + x1 * sn;
    }
}

// =============================================================================
// GLA pass 1 (SIMT, unchanged): per (chunk, kv-head)
// =============================================================================
__global__ void __launch_bounds__(256) gla_pass1_kernel()
{
    extern __shared__ float sm1[];
    float* G   = sm1;              // [64][132]
    float* LAM = G   + 64 * 132;
    float* V   = LAM + 64 * 132;

    const int c = blockIdx.x, kvh = blockIdx.y;
    const int tid = threadIdx.x;

    for (int idx = tid; idx < CH * DH; idx += 256) {
        int r = idx >> 7, d = idx & 127;
        int gbase = (c * CH + r) * KVD + kvh * DH + d;
        G[r * 132 + d] = g_gl[gbase];
        V[r * 132 + d] = g_v[gbase];
    }
    __syncthreads();

    if (tid < 128) {
        float cum = 0.0f;
#pragma unroll 4
        for (int t = 0; t < CH; t++) {
            cum += G[t * 132 + tid];
            LAM[t * 132 + tid] = expf(cum);
        }
        g_ltot[(kvh * NCH + c) * DH + tid] = LAM[63 * 132 + tid];
    }
    __syncthreads();

    for (int idx = tid; idx < CH * DH; idx += 256) {
        int r = idx >> 7, d = idx & 127;
        int gbase = (c * CH + r) * KVD + kvh * DH + d;
        float lam = LAM[r * 132 + d];
        float kdl = g_ks[gbase] / lam;
        g_kdl[gbase] = kdl;
        g_lam[gbase] = lam;
        G[r * 132 + d] = kdl * LAM[63 * 132 + d];
    }
    __syncthreads();

    const int tx = tid & 15, ty = tid >> 4;
    float acc[8][8];
#pragma unroll
    for (int i = 0; i < 8; i++)
#pragma unroll
        for (int j = 0; j < 8; j++) acc[i][j] = 0.0f;

    for (int s = 0; s < CH; s++) {
        float a[8], b[8];
        *(float4*)&a[0] = *(const float4*)&G[s * 132 + ty * 8];
        *(float4*)&a[4] = *(const float4*)&G[s * 132 + ty * 8 + 4];
        *(float4*)&b[0] = *(const float4*)&V[s * 132 + tx * 8];
        *(float4*)&b[4] = *(const float4*)&V[s * 132 + tx * 8 + 4];
#pragma unroll
        for (int i = 0; i < 8; i++)
#pragma unroll
            for (int j = 0; j < 8; j++) acc[i][j] += a[i] * b[j];
    }

    float* dS = g_dS + (size_t)(kvh * NCH + c) * DH * DH;
#pragma unroll
    for (int i = 0; i < 8; i++) {
        *(float4*)&dS[(ty * 8 + i) * DH + tx * 8]     = make_float4(acc[i][0], acc[i][1], acc[i][2], acc[i][3]);
        *(float4*)&dS[(ty * 8 + i) * DH + tx * 8 + 4] = make_float4(acc[i][4], acc[i][5], acc[i][6], acc[i][7]);
    }
}

// =============================================================================
// GLA pass 2: sequential scan over chunks (unchanged)
// =============================================================================
__global__ void __launch_bounds__(128) gla_scan_kernel()
{
    const int kvh = blockIdx.x, d = blockIdx.y;
    const int dp = threadIdx.x;
    float s = 0.0f;
    for (int c = 0; c < NCH; c++) {
        size_t idx = ((size_t)(kvh * NCH + c) * DH + d) * DH + dp;
        float tmp = g_dS[idx];
        float lt = g_ltot[(kvh * NCH + c) * DH + d];
        g_dS[idx] = s;
        s = s * lt + tmp;
    }
}

// =============================================================================
// GLA pass 3 (SIMT, unchanged): per (chunk, head)
// =============================================================================
__global__ void __launch_bounds__(256) gla_pass3_kernel()
{
    extern __shared__ float sm3[];
    float* QT = sm3;               // [128][65]
    float* KT = QT + 128 * 65;
    float* Ss = KT + 128 * 65;     // [128][132]
    float* Vs = Ss + 128 * 132;    // [64][132]
    float* AT = Vs + 64 * 132;     // [64][65]

    const int c = blockIdx.x, h = blockIdx.y;
    const int kvh = h >> 2;
    const int tid = threadIdx.x;

    for (int idx = tid; idx < CH * DH; idx += 256) {
        int r = idx >> 7, d = idx & 127;
        int kb = (c * CH + r) * KVD + kvh * DH + d;
        float lam = g_lam[kb];
        QT[d * 65 + r] = g_qs[(c * CH + r) * HD + h * DH + d] * lam;
        KT[d * 65 + r] = g_kdl[kb];
        Vs[r * 132 + d] = g_v[kb];
    }
    const float* Sg = g_dS + (size_t)(kvh * NCH + c) * DH * DH;
    for (int idx = tid; idx < DH * DH; idx += 256) {
        int r = idx >> 7, d = idx & 127;
        Ss[r * 132 + d] = Sg[r * DH + d];
    }
    __syncthreads();

    const int tx = tid & 15, ty = tid >> 4;

    float O[4][8];
#pragma unroll
    for (int i = 0; i < 4; i++)
#pragma unroll
        for (int j = 0; j < 8; j++) O[i][j] = 0.0f;

    for (int dd = 0; dd < DH; dd++) {
        float a[4], b[8];
#pragma unroll
        for (int i = 0; i < 4; i++) a[i] = QT[dd * 65 + ty * 4 + i];
        *(float4*)&b[0] = *(const float4*)&Ss[dd * 132 + tx * 8];
        *(float4*)&b[4] = *(const float4*)&Ss[dd * 132 + tx * 8 + 4];
#pragma unroll
        for (int i = 0; i < 4; i++)
#pragma unroll
            for (int j = 0; j < 8; j++) O[i][j] += a[i] * b[j];
    }

    float Aacc[4][4];
#pragma unroll
    for (int i = 0; i < 4; i++)
#pragma unroll
        for (int j = 0; j < 4; j++) Aacc[i][j] = 0.0f;

    for (int dd = 0; dd < DH; dd++) {
        float a[4], b[4];
#pragma unroll
        for (int i = 0; i < 4; i++) a[i] = QT[dd * 65 + ty * 4 + i];
#pragma unroll
        for (int j = 0; j < 4; j++) b[j] = KT[dd * 65 + tx * 4 + j];
#pragma unroll
        for (int i = 0; i < 4; i++)
#pragma unroll
            for (int j = 0; j < 4; j++) Aacc[i][j] += a[i] * b[j];
    }
#pragma unroll
    for (int i = 0; i < 4; i++)
#pragma unroll
        for (int j = 0; j < 4; j++) {
            int t = ty * 4 + i, s = tx * 4 + j;
            AT[s * 65 + t] = (s <= t) ? Aacc[i][j] : 0.0f;
        }
    __syncthreads();

    for (int s = 0; s < CH; s++) {
        float a[4], b[8];
#pragma unroll
        for (int i = 0; i < 4; i++) a[i] = AT[s * 65 + ty * 4 + i];
        *(float4*)&b[0] = *(const float4*)&Vs[s * 132 + tx * 8];
        *(float4*)&b[4] = *(const float4*)&Vs[s * 132 + tx * 8 + 4];
#pragma unroll
        for (int i = 0; i < 4; i++)
#pragma unroll
            for (int j = 0; j < 8; j++) O[i][j] += a[i] * b[j];
    }

#pragma unroll
    for (int i = 0; i < 4; i++) {
        int t = c * CH + ty * 4 + i;
        *(float4*)&g_gla[t * HD + h * DH + tx * 8]     = make_float4(O[i][0], O[i][1], O[i][2], O[i][3]);
        *(float4*)&g_gla[t * HD + h * DH + tx * 8 + 4] = make_float4(O[i][4], O[i][5], O[i][6], O[i][7]);
    }
}

// =============================================================================
// Causal flash attention on tensor cores (tf32 mma, fp32 softmax).
// block = (q-tile of 128, head). 256 threads = 8 warps, warp owns 16 q-rows.
// kv tiles of 64. Online softmax in the m16n8 C-fragment layout.
// =============================================================================
__global__ void __launch_bounds__(256) attn_tc_kernel()
{
    extern __shared__ unsigned smX[];
    unsigned* Qs = smX;                    // [128][132] tf32
    unsigned* Ks = Qs + 128 * 132;         // [64][132]
    unsigned* Vs = Ks + 64 * 132;          // [64][136]
    unsigned* Pb = Vs + 64 * 136;          // [8 warps][16][68]

    const int qt = blockIdx.x, h = blockIdx.y;
    const int kvh = h >> 2;
    const int tid = threadIdx.x;
    const int warp = tid >> 5, lane = tid & 31;
    const int gid = lane >> 2, tig = lane & 3;
    unsigned* Pw = Pb + warp * 16 * 68;
    const float scale = 0.08838834764831845f;

    // load Q tile (roped q), cvt to tf32
    for (int i = tid; i < 128 * 32; i += 256) {
        int r = i >> 5, c4 = (i & 31) * 4;
        float4 v = *(const float4*)&g_sq[(size_t)(qt * 128 + r) * HD + h * DH + c4];
        *(uint4*)&Qs[r * 132 + c4] = make_uint4(f2tf(v.x), f2tf(v.y), f2tf(v.z), f2tf(v.w));
    }

    const int rbase = qt * 128 + warp * 16;   // warp's global q-row base
    float m_i[2] = {-1e30f, -1e30f};
    float l_i[2] = {0.0f, 0.0f};
    float c[16][4];
#pragma unroll
    for (int ni = 0; ni < 16; ni++)
#pragma unroll
        for (int v = 0; v < 4; v++) c[ni][v] = 0.0f;

    const int ktmax = 2 * qt + 1;
    for (int kt = 0; kt <= ktmax; kt++) {
        __syncthreads();
        for (int i = tid; i < 64 * 32; i += 256) {
            int r = i >> 5, c4 = (i & 31) * 4;
            size_t kb = (size_t)(kt * 64 + r) * KVD + kvh * DH + c4;
            float4 kv = *(const float4*)&g_sk[kb];
            float4 vv = *(const float4*)&g_v[kb];
            *(uint4*)&Ks[r * 132 + c4] = make_uint4(f2tf(kv.x), f2tf(kv.y), f2tf(kv.z), f2tf(kv.w));
            *(uint4*)&Vs[r * 136 + c4] = make_uint4(f2tf(vv.x), f2tf(vv.y), f2tf(vv.z), f2tf(vv.w));
        }
        __syncthreads();

        const int smin = kt * 64;
        if (smin > rbase + 15) continue;   // warp-uniform: fully masked

        // ---- S = Q K^T (16x64 per warp) ----
        float sacc[8][4];
#pragma unroll
        for (int ni = 0; ni < 8; ni++)
#pragma unroll
            for (int v = 0; v < 4; v++) sacc[ni][v] = 0.0f;

#pragma unroll 4
        for (int k8 = 0; k8 < 16; k8++) {
            unsigned aq[4];
            int qr = warp * 16 + gid;
            aq[0] = Qs[qr * 132 + k8 * 8 + tig];
            aq[1] = Qs[(qr + 8) * 132 + k8 * 8 + tig];
            aq[2] = Qs[qr * 132 + k8 * 8 + tig + 4];
            aq[3] = Qs[(qr + 8) * 132 + k8 * 8 + tig + 4];
#pragma unroll
            for (int ni = 0; ni < 8; ni++) {
                unsigned b0 = Ks[(ni * 8 + gid) * 132 + k8 * 8 + tig];
                unsigned b1 = Ks[(ni * 8 + gid) * 132 + k8 * 8 + tig + 4];
                mma_tf32(sacc[ni], aq, b0, b1);
            }
        }

        // ---- scale + causal mask ----
        const bool partial = (smin + 63 > rbase);
#pragma unroll
        for (int ni = 0; ni < 8; ni++)
#pragma unroll
            for (int v = 0; v < 4; v++) {
                float sv = sacc[ni][v] * scale;
                if (partial) {
                    int row = rbase + gid + (v >> 1) * 8;
                    int col = smin + ni * 8 + tig * 2 + (v & 1);
                    if (col > row) sv = -1e30f;
                }
                sacc[ni][v] = sv;
            }

        // ---- online softmax (per row-half) ----
#pragma unroll
        for (int h2 = 0; h2 < 2; h2++) {
            float rmax = -1e30f;
#pragma unroll
            for (int ni = 0; ni < 8; ni++)
                rmax = fmaxf(rmax, fmaxf(sacc[ni][2 * h2], sacc[ni][2 * h2 + 1]));
            rmax = fmaxf(rmax, __shfl_xor_sync(0xffffffffu, rmax, 1));
            rmax = fmaxf(rmax, __shfl_xor_sync(0xffffffffu, rmax, 2));
            float mnew = fmaxf(m_i[h2], rmax);
            float alpha = __expf(m_i[h2] - mnew);
            float rsum = 0.0f;
#pragma unroll
            for (int ni = 0; ni < 8; ni++) {
                float p0 = __expf(sacc[ni][2 * h2] - mnew);
                float p1 = __expf(sacc[ni][2 * h2 + 1] - mnew);
                sacc[ni][2 * h2] = p0;
                sacc[ni][2 * h2 + 1] = p1;
                rsum += p0 + p1;
            }
            rsum += __shfl_xor_sync(0xffffffffu, rsum, 1);
            rsum += __shfl_xor_sync(0xffffffffu, rsum, 2);
            l_i[h2] = l_i[h2] * alpha + rsum;
            m_i[h2] = mnew;
#pragma unroll
            for (int ni = 0; ni < 16; ni++) {
                c[ni][2 * h2]     *= alpha;
                c[ni][2 * h2 + 1] *= alpha;
            }
        }

        // ---- P -> warp-private smem (A-fragment layout) ----
#pragma unroll
        for (int ni = 0; ni < 8; ni++) {
            *(uint2*)&Pw[gid * 68 + ni * 8 + tig * 2] =
                make_uint2(f2tf(sacc[ni][0]), f2tf(sacc[ni][1]));
            *(uint2*)&Pw[(gid + 8) * 68 + ni * 8 + tig * 2] =
                make_uint2(f2tf(sacc[ni][2]), f2tf(sacc[ni][3]));
        }
        __syncwarp();

        // ---- O += P V (16x128 per warp) ----
#pragma unroll 2
        for (int k8 = 0; k8 < 8; k8++) {
            unsigned ap[4];
            ap[0] = Pw[gid * 68 + k8 * 8 + tig];
            ap[1] = Pw[(gid + 8) * 68 + k8 * 8 + tig];
            ap[2] = Pw[gid * 68 + k8 * 8 + tig + 4];
            ap[3] = Pw[(gid + 8) * 68 + k8 * 8 + tig + 4];
#pragma unroll
            for (int ni = 0; ni < 16; ni++) {
                unsigned b0 = Vs[(k8 * 8 + tig) * 136 + ni * 8 + gid];
                unsigned b1 = Vs[(k8 * 8 + tig + 4) * 136 + ni * 8 + gid];
                mma_tf32(c[ni], ap, b0, b1);
            }
        }
    }

    // ---- finalize: divide by l, store ----
    const float inv0 = 1.0f / l_i[0];
    const float inv1 = 1.0f / l_i[1];
    const int r0 = rbase + gid, r1 = r0 + 8;
#pragma unroll
    for (int ni = 0; ni < 16; ni++) {
        int col = h * DH + ni * 8 + tig * 2;
        *(float2*)&g_attn[(size_t)r0 * HD + col] = make_float2(c[ni][0] * inv0, c[ni][1] * inv0);
        *(float2*)&g_attn[(size_t)r1 * HD + col] = make_float2(c[ni][2] * inv1, c[ni][3] * inv1);
    }
}

// =============================================================================
// host launcher
// =============================================================================
extern "C" void kernel_launch(void* const* d_in, const int* in_sizes, int n_in,
                              void* d_out, int out_size)
{
    (void)in_sizes; (void)n_in; (void)out_size;
    const float* hs = (const float*)d_in[0];
    const float* Wq = (const float*)d_in[1];
    const float* Wk = (const float*)d_in[2];
    const float* Wv = (const float*)d_in[3];
    const float* Wo = (const float*)d_in[4];
    float* out = (float*)d_out;

    float *p_q, *p_k, *p_v, *p_attn, *p_gla;
    cudaGetSymbolAddress((void**)&p_q,    g_q);
    cudaGetSymbolAddress((void**)&p_k,    g_k);
    cudaGetSymbolAddress((void**)&p_v,    g_v);
    cudaGetSymbolAddress((void**)&p_attn, g_attn);
    cudaGetSymbolAddress((void**)&p_gla,  g_gla);

    const int smem1   = 3 * 64 * 132 * 4;                                    // 101376
    const int smem3   = (2 * 128 * 65 + 128 * 132 + 64 * 132 + 64 * 65) * 4; // 184576
    const int smemATC = (128 * 132 + 64 * 132 + 64 * 136 + 8 * 16 * 68) * 4; // 171008
    cudaFuncSetAttribute(gla_pass1_kernel, cudaFuncAttributeMaxDynamicSharedMemorySize, smem1);
    cudaFuncSetAttribute(gla_pass3_kernel, cudaFuncAttributeMaxDynamicSharedMemorySize, smem3);
    cudaFuncSetAttribute(attn_tc_kernel,   cudaFuncAttributeMaxDynamicSharedMemorySize, smemATC);

    // 1. q = hs @ Wq  (2048x2048x2048, tf32 mma)
    mm_tf32_kernel<<<dim3(16, 16, 1), 128>>>(hs, nullptr, Wq, p_q, Wq, p_q, HD, HIDN);
    // 2. k = hs @ Wk, v = hs @ Wv (z picks)
    mm_tf32_kernel<<<dim3(4, 16, 2), 128>>>(hs, nullptr, Wk, p_k, Wv, p_v, KVD, HIDN);
    // 3. prep: softmax / rope / gates
    prep_q_kernel<<<dim3(NTOK, NH), 128>>>();
    prep_k_kernel<<<dim3(NTOK, NKV), 128>>>();
    // 4. GLA chunked
    gla_pass1_kernel<<<dim3(NCH, NKV), 256, smem1>>>();
    gla_scan_kernel<<<dim3(NKV, DH), 128>>>();
    gla_pass3_kernel<<<dim3(NCH, NH), 256, smem3>>>();
    // 5. causal flash attention (tensor cores)
    attn_tc_kernel<<<dim3(NTOK / 128, NH), 256, smemATC>>>();
    // 6. out = (0.5*(y + o_gla)) @ Wo (tf32 mma, fused average)
    mm_tf32_kernel<<<dim3(16, 16, 1), 128>>>(p_attn, p_gla, Wo, out, Wo, out, HIDN, HD);
}

// round 5
// speedup vs baseline: 2.2166x; 1.1065x over previous
#include <cuda_runtime.h>
#include <math.h>

// Problem constants
#define NTOK 2048
#define HIDN 2048
#define NH   16
#define NKV  4
#define DH   128
#define HD   (NH*DH)     // 2048
#define KVD  (NKV*DH)    // 512
#define CH   64
#define NCH  (NTOK/CH)   // 32

// ---------------- scratch (static device globals; no allocation) -------------
__device__ float g_q   [NTOK*HD];
__device__ float g_sq  [NTOK*HD];
__device__ float g_qs  [NTOK*HD];
__device__ float g_k   [NTOK*KVD];
__device__ float g_sk  [NTOK*KVD];
__device__ float g_ks  [NTOK*KVD];
__device__ float g_gl  [NTOK*KVD];
__device__ float g_v   [NTOK*KVD];
__device__ float g_lam [NTOK*KVD];
__device__ float g_kdl [NTOK*KVD];
__device__ float g_dS  [NKV*NCH*DH*DH];
__device__ float g_ltot[NKV*NCH*DH];
__device__ float g_attn[NTOK*HD];
__device__ float g_gla [NTOK*HD];

// ---------------- tf32 mma helpers ------------------------------------------
__device__ __forceinline__ unsigned f2tf(float x) {
    unsigned r;
    asm("cvt.rna.tf32.f32 %0, %1;" : "=r"(r) : "f"(x));
    return r;
}

__device__ __forceinline__ uint4 cvt4(float4 v) {
    return make_uint4(f2tf(v.x), f2tf(v.y), f2tf(v.z), f2tf(v.w));
}

__device__ __forceinline__ void mma_tf32(float c[4], const unsigned a[4],
                                         unsigned b0, unsigned b1) {
    asm volatile(
        "mma.sync.aligned.m16n8k8.row.col.f32.tf32.tf32.f32 "
        "{%0,%1,%2,%3}, {%4,%5,%6,%7}, {%8,%9}, {%0,%1,%2,%3};"
        : "+f"(c[0]), "+f"(c[1]), "+f"(c[2]), "+f"(c[3])
        : "r"(a[0]), "r"(a[1]), "r"(a[2]), "r"(a[3]), "r"(b0), "r"(b1));
}

// =============================================================================
// TF32 GEMM body: C[128x128 tile] = op(A) @ B. 256 threads, 8 warps (2m x 4n),
// warp tile 64x32. BK=32, double-buffered smem, ONE sync per slab.
// A2 != null -> A operand is 0.5*(A+A2).
// =============================================================================
#define AS_STRIDE 36   // 36 % 32 == 4 -> conflict-free A fragment loads
#define BS_STRIDE 136  // 136 % 32 == 8 -> conflict-free B fragment loads
#define AS_BUF (128 * AS_STRIDE)
#define BS_BUF (32 * BS_STRIDE)
#define GEMM_SMEM ((2 * AS_BUF + 2 * BS_BUF) * 4)   // 71680 bytes

__device__ __forceinline__ void gemm_tf32_body(
    unsigned* __restrict__ sm,
    const float* __restrict__ A, const float* __restrict__ A2,
    const float* __restrict__ B, float* __restrict__ C,
    int N, int K, int bm, int bn)
{
    unsigned* As = sm;                  // [2][128][AS_STRIDE]
    unsigned* Bs = sm + 2 * AS_BUF;     // [2][32][BS_STRIDE]

    const int tid  = threadIdx.x;
    const int warp = tid >> 5, lane = tid & 31;
    const int gid  = lane >> 2, tig = lane & 3;
    const int wm   = (warp & 1) * 64, wn = (warp >> 1) * 32;

    const int ar = tid >> 1, ac = (tid & 1) * 16;    // A: 128 rows x 32 cols
    const int br = tid >> 3, bc = (tid & 7) * 16;    // B: 32 rows x 128 cols

    const float* Arow  = A  + (size_t)(bm + ar) * K + ac;
    const float* A2row = A2 ? (A2 + (size_t)(bm + ar) * K + ac) : nullptr;

    float4 pa[4], pb[4];

    float acc[4][4][4];
#pragma unroll
    for (int mi = 0; mi < 4; mi++)
#pragma unroll
        for (int ni = 0; ni < 4; ni++)
#pragma unroll
            for (int v = 0; v < 4; v++) acc[mi][ni][v] = 0.0f;

    // prologue: load slab 0
#pragma unroll
    for (int q = 0; q < 4; q++) {
        pa[q] = *(const float4*)&Arow[q * 4];
        if (A2row) {
            float4 a2 = *(const float4*)&A2row[q * 4];
            pa[q].x = 0.5f * (pa[q].x + a2.x); pa[q].y = 0.5f * (pa[q].y + a2.y);
            pa[q].z = 0.5f * (pa[q].z + a2.z); pa[q].w = 0.5f * (pa[q].w + a2.w);
        }
        pb[q] = *(const float4*)&B[(size_t)br * N + bn + bc + q * 4];
    }
#pragma unroll
    for (int q = 0; q < 4; q++) {
        *(uint4*)&As[ar * AS_STRIDE + ac + q * 4] = cvt4(pa[q]);
        *(uint4*)&Bs[br * BS_STRIDE + bc + q * 4] = cvt4(pb[q]);
    }
    __syncthreads();

    const int nIter = K >> 5;
    for (int it = 0; it < nIter; it++) {
        const bool more = (it + 1 < nIter);
        if (more) {
            const int k0 = (it + 1) << 5;
#pragma unroll
            for (int q = 0; q < 4; q++) {
                pa[q] = *(const float4*)&Arow[k0 + q * 4];
                if (A2row) {
                    float4 a2 = *(const float4*)&A2row[k0 + q * 4];
                    pa[q].x = 0.5f * (pa[q].x + a2.x); pa[q].y = 0.5f * (pa[q].y + a2.y);
                    pa[q].z = 0.5f * (pa[q].z + a2.z); pa[q].w = 0.5f * (pa[q].w + a2.w);
                }
                pb[q] = *(const float4*)&B[(size_t)(k0 + br) * N + bn + bc + q * 4];
            }
        }

        const unsigned* as = As + (it & 1) * AS_BUF;
        const unsigned* bs = Bs + (it & 1) * BS_BUF;
#pragma unroll
        for (int k8 = 0; k8 < 4; k8++) {
            unsigned af[4][4];
#pragma unroll
            for (int mi = 0; mi < 4; mi++) {
                int r = wm + mi * 16 + gid;
                af[mi][0] = as[r * AS_STRIDE + k8 * 8 + tig];
                af[mi][1] = as[(r + 8) * AS_STRIDE + k8 * 8 + tig];
                af[mi][2] = as[r * AS_STRIDE + k8 * 8 + tig + 4];
                af[mi][3] = as[(r + 8) * AS_STRIDE + k8 * 8 + tig + 4];
            }
#pragma unroll
            for (int ni = 0; ni < 4; ni++) {
                unsigned b0 = bs[(k8 * 8 + tig) * BS_STRIDE + wn + ni * 8 + gid];
                unsigned b1 = bs[(k8 * 8 + tig + 4) * BS_STRIDE + wn + ni * 8 + gid];
#pragma unroll
                for (int mi = 0; mi < 4; mi++) mma_tf32(acc[mi][ni], af[mi], b0, b1);
            }
        }

        if (more) {
            unsigned* asn = As + ((it + 1) & 1) * AS_BUF;
            unsigned* bsn = Bs + ((it + 1) & 1) * BS_BUF;
#pragma unroll
            for (int q = 0; q < 4; q++) {
                *(uint4*)&asn[ar * AS_STRIDE + ac + q * 4] = cvt4(pa[q]);
                *(uint4*)&bsn[br * BS_STRIDE + bc + q * 4] = cvt4(pb[q]);
            }
        }
        __syncthreads();
    }

#pragma unroll
    for (int mi = 0; mi < 4; mi++) {
        int r0 = bm + wm + mi * 16 + gid;
#pragma unroll
        for (int ni = 0; ni < 4; ni++) {
            int col = bn + wn + ni * 8 + tig * 2;
            *(float2*)&C[(size_t)r0 * N + col]       = make_float2(acc[mi][ni][0], acc[mi][ni][1]);
            *(float2*)&C[(size_t)(r0 + 8) * N + col] = make_float2(acc[mi][ni][2], acc[mi][ni][3]);
        }
    }
}

// Merged q/k/v projections in ONE launch. grid.x: [0,16)->Wq, [16,20)->Wk,
// [20,24)->Wv. All share A = hidden_states (K = 2048).
__global__ void __launch_bounds__(256) proj_kernel(
    const float* __restrict__ hs,
    const float* __restrict__ Wq, const float* __restrict__ Wk,
    const float* __restrict__ Wv,
    float* __restrict__ outq, float* __restrict__ outk, float* __restrict__ outv)
{
    extern __shared__ unsigned smg[];
    const int bx = blockIdx.x, bm = blockIdx.y * 128;
    const float* B; float* C; int N, bn;
    if (bx < 16)      { B = Wq; C = outq; N = HD;  bn = bx * 128; }
    else if (bx < 20) { B = Wk; C = outk; N = KVD; bn = (bx - 16) * 128; }
    else              { B = Wv; C = outv; N = KVD; bn = (bx - 20) * 128; }
    gemm_tf32_body(smg, hs, nullptr, B, C, N, HIDN, bm, bn);
}

// Output projection: out = (0.5*(attn + gla)) @ Wo
__global__ void __launch_bounds__(256) wo_kernel(
    const float* __restrict__ attn, const float* __restrict__ gla,
    const float* __restrict__ Wo, float* __restrict__ out)
{
    extern __shared__ unsigned smg[];
    gemm_tf32_body(smg, attn, gla, Wo, out, HIDN, HD,
                   blockIdx.y * 128, blockIdx.x * 128);
}

// =============================================================================
// prep_q: per (token, head) row of 128: softmax -> g_qs, RoPE -> g_sq
// =============================================================================
__global__ void __launch_bounds__(128) prep_q_kernel()
{
    const int t = blockIdx.x, h = blockIdx.y;
    const int j = threadIdx.x;
    const int base = t * HD + h * DH;
    const float x = g_q[base + j];

    __shared__ float row[128];
    __shared__ float red[4];
    row[j] = x;

    float m = x;
#pragma unroll
    for (int o = 16; o; o >>= 1) m = fmaxf(m, __shfl_xor_sync(0xffffffffu, m, o));
    const int w = j >> 5;
    if ((j & 31) == 0) red[w] = m;
    __syncthreads();
    m = fmaxf(fmaxf(red[0], red[1]), fmaxf(red[2], red[3]));

    float e = expf(x - m);
    float s = e;
#pragma unroll
    for (int o = 16; o; o >>= 1) s += __shfl_xor_sync(0xffffffffu, s, o);
    __syncthreads();
    if ((j & 31) == 0) red[w] = s;
    __syncthreads();
    const float denom = red[0] + red[1] + red[2] + red[3];
    g_qs[base + j] = e / denom;

    if (j < 64) {
        float inv_freq = (float)pow(10000.0, -(double)(2 * j) / 128.0);
        float fr = (float)t * inv_freq;
        double ang = (double)fr;
        float cs = (float)cos(ang);
        float sn = (float)sin(ang);
        float x1 = row[j], x2 = row[j + 64];
        g_sq[base + j]      = x1 * cs - x2 * sn;
        g_sq[base + j + 64] = x2 * cs + x1 * sn;
    }
}

// =============================================================================
// prep_k: per (token, kv-head): softmax -> g_ks, RoPE -> g_sk, logsig/16 -> g_gl
// =============================================================================
__global__ void __launch_bounds__(128) prep_k_kernel()
{
    const int t = blockIdx.x, kvh = blockIdx.y;
    const int j = threadIdx.x;
    const int base = t * KVD + kvh * DH;
    const float x = g_k[base + j];

    __shared__ float row[128];
    __shared__ float red[4];
    row[j] = x;

    float m = x;
#pragma unroll
    for (int o = 16; o; o >>= 1) m = fmaxf(m, __shfl_xor_sync(0xffffffffu, m, o));
    const int w = j >> 5;
    if ((j & 31) == 0) red[w] = m;
    __syncthreads();
    m = fmaxf(fmaxf(red[0], red[1]), fmaxf(red[2], red[3]));

    float e = expf(x - m);
    float s = e;
#pragma unroll
    for (int o = 16; o; o >>= 1) s += __shfl_xor_sync(0xffffffffu, s, o);
    __syncthreads();
    if ((j & 31) == 0) red[w] = s;
    __syncthreads();
    const float denom = red[0] + red[1] + red[2] + red[3];
    g_ks[base + j] = e / denom;

    float lsig = fminf(x, 0.0f) - log1pf(expf(-fabsf(x)));
    g_gl[base + j] = lsig * 0.0625f;

    if (j < 64) {
        float inv_freq = (float)pow(10000.0, -(double)(2 * j) / 128.0);
        float fr = (float)t * inv_freq;
        double ang = (double)fr;
        float cs = (float)cos(ang);
        float sn = (float)sin(ang);
        float x1 = row[j], x2 = row[j + 64];
        g_sk[base + j]      = x1 * cs - x2 * sn;
        g_sk[base + j + 64] = x2 * cs + x1 * sn;
    }
}

// =============================================================================
// GLA pass 1 (fp32 SIMT): per (chunk, kv-head)
// =============================================================================
__global__ void __launch_bounds__(256) gla_pass1_kernel()
{
    extern __shared__ float sm1[];
    float* G   = sm1;              // [64][132]
    float* LAM = G   + 64 * 132;
    float* V   = LAM + 64 * 132;

    const int c = blockIdx.x, kvh = blockIdx.y;
    const int tid = threadIdx.x;

    for (int idx = tid; idx < CH * DH; idx += 256) {
        int r = idx >> 7, d = idx & 127;
        int gbase = (c * CH + r) * KVD + kvh * DH + d;
        G[r * 132 + d] = g_gl[gbase];
        V[r * 132 + d] = g_v[gbase];
    }
    __syncthreads();

    if (tid < 128) {
        float cum = 0.0f;
#pragma unroll 4
        for (int t = 0; t < CH; t++) {
            cum += G[t * 132 + tid];
            LAM[t * 132 + tid] = expf(cum);
        }
        g_ltot[(kvh * NCH + c) * DH + tid] = LAM[63 * 132 + tid];
    }
    __syncthreads();

    for (int idx = tid; idx < CH * DH; idx += 256) {
        int r = idx >> 7, d = idx & 127;
        int gbase = (c * CH + r) * KVD + kvh * DH + d;
        float lam = LAM[r * 132 + d];
        float kdl = g_ks[gbase] / lam;
        g_kdl[gbase] = kdl;
        g_lam[gbase] = lam;
        G[r * 132 + d] = kdl * LAM[63 * 132 + d];
    }
    __syncthreads();

    const int tx = tid & 15, ty = tid >> 4;
    float acc[8][8];
#pragma unroll
    for (int i = 0; i < 8; i++)
#pragma unroll
        for (int j = 0; j < 8; j++) acc[i][j] = 0.0f;

    for (int s = 0; s < CH; s++) {
        float a[8], b[8];
        *(float4*)&a[0] = *(const float4*)&G[s * 132 + ty * 8];
        *(float4*)&a[4] = *(const float4*)&G[s * 132 + ty * 8 + 4];
        *(float4*)&b[0] = *(const float4*)&V[s * 132 + tx * 8];
        *(float4*)&b[4] = *(const float4*)&V[s * 132 + tx * 8 + 4];
#pragma unroll
        for (int i = 0; i < 8; i++)
#pragma unroll
            for (int j = 0; j < 8; j++) acc[i][j] += a[i] * b[j];
    }

    float* dS = g_dS + (size_t)(kvh * NCH + c) * DH * DH;
#pragma unroll
    for (int i = 0; i < 8; i++) {
        *(float4*)&dS[(ty * 8 + i) * DH + tx * 8]     = make_float4(acc[i][0], acc[i][1], acc[i][2], acc[i][3]);
        *(float4*)&dS[(ty * 8 + i) * DH + tx * 8 + 4] = make_float4(acc[i][4], acc[i][5], acc[i][6], acc[i][7]);
    }
}

// =============================================================================
// GLA pass 2: sequential scan over chunks
// =============================================================================
__global__ void __launch_bounds__(128) gla_scan_kernel()
{
    const int kvh = blockIdx.x, d = blockIdx.y;
    const int dp = threadIdx.x;
    float s = 0.0f;
    for (int c = 0; c < NCH; c++) {
        size_t idx = ((size_t)(kvh * NCH + c) * DH + d) * DH + dp;
        float tmp = g_dS[idx];
        float lt = g_ltot[(kvh * NCH + c) * DH + d];
        g_dS[idx] = s;
        s = s * lt + tmp;
    }
}

// =============================================================================
// GLA pass 3 (fp32 SIMT): per (chunk, head)
// =============================================================================
__global__ void __launch_bounds__(256) gla_pass3_kernel()
{
    extern __shared__ float sm3[];
    float* QT = sm3;               // [128][65]
    float* KT = QT + 128 * 65;
    float* Ss = KT + 128 * 65;     // [128][132]
    float* Vs = Ss + 128 * 132;    // [64][132]
    float* AT = Vs + 64 * 132;     // [64][65]

    const int c = blockIdx.x, h = blockIdx.y;
    const int kvh = h >> 2;
    const int tid = threadIdx.x;

    for (int idx = tid; idx < CH * DH; idx += 256) {
        int r = idx >> 7, d = idx & 127;
        int kb = (c * CH + r) * KVD + kvh * DH + d;
        float lam = g_lam[kb];
        QT[d * 65 + r] = g_qs[(c * CH + r) * HD + h * DH + d] * lam;
        KT[d * 65 + r] = g_kdl[kb];
        Vs[r * 132 + d] = g_v[kb];
    }
    const float* Sg = g_dS + (size_t)(kvh * NCH + c) * DH * DH;
    for (int idx = tid; idx < DH * DH; idx += 256) {
        int r = idx >> 7, d = idx & 127;
        Ss[r * 132 + d] = Sg[r * DH + d];
    }
    __syncthreads();

    const int tx = tid & 15, ty = tid >> 4;

    float O[4][8];
#pragma unroll
    for (int i = 0; i < 4; i++)
#pragma unroll
        for (int j = 0; j < 8; j++) O[i][j] = 0.0f;

    for (int dd = 0; dd < DH; dd++) {
        float a[4], b[8];
#pragma unroll
        for (int i = 0; i < 4; i++) a[i] = QT[dd * 65 + ty * 4 + i];
        *(float4*)&b[0] = *(const float4*)&Ss[dd * 132 + tx * 8];
        *(float4*)&b[4] = *(const float4*)&Ss[dd * 132 + tx * 8 + 4];
#pragma unroll
        for (int i = 0; i < 4; i++)
#pragma unroll
            for (int j = 0; j < 8; j++) O[i][j] += a[i] * b[j];
    }

    float Aacc[4][4];
#pragma unroll
    for (int i = 0; i < 4; i++)
#pragma unroll
        for (int j = 0; j < 4; j++) Aacc[i][j] = 0.0f;

    for (int dd = 0; dd < DH; dd++) {
        float a[4], b[4];
#pragma unroll
        for (int i = 0; i < 4; i++) a[i] = QT[dd * 65 + ty * 4 + i];
#pragma unroll
        for (int j = 0; j < 4; j++) b[j] = KT[dd * 65 + tx * 4 + j];
#pragma unroll
        for (int i = 0; i < 4; i++)
#pragma unroll
            for (int j = 0; j < 4; j++) Aacc[i][j] += a[i] * b[j];
    }
#pragma unroll
    for (int i = 0; i < 4; i++)
#pragma unroll
        for (int j = 0; j < 4; j++) {
            int t = ty * 4 + i, s = tx * 4 + j;
            AT[s * 65 + t] = (s <= t) ? Aacc[i][j] : 0.0f;
        }
    __syncthreads();

    for (int s = 0; s < CH; s++) {
        float a[4], b[8];
#pragma unroll
        for (int i = 0; i < 4; i++) a[i] = AT[s * 65 + ty * 4 + i];
        *(float4*)&b[0] = *(const float4*)&Vs[s * 132 + tx * 8];
        *(float4*)&b[4] = *(const float4*)&Vs[s * 132 + tx * 8 + 4];
#pragma unroll
        for (int i = 0; i < 4; i++)
#pragma unroll
            for (int j = 0; j < 8; j++) O[i][j] += a[i] * b[j];
    }

#pragma unroll
    for (int i = 0; i < 4; i++) {
        int t = c * CH + ty * 4 + i;
        *(float4*)&g_gla[t * HD + h * DH + tx * 8]     = make_float4(O[i][0], O[i][1], O[i][2], O[i][3]);
        *(float4*)&g_gla[t * HD + h * DH + tx * 8 + 4] = make_float4(O[i][4], O[i][5], O[i][6], O[i][7]);
    }
}

// =============================================================================
// Causal flash attention on tensor cores (tf32 mma, fp32 softmax).
// Heavy-first scheduling: qt = gridDim.x-1-blockIdx.x.
// =============================================================================
__global__ void __launch_bounds__(256) attn_tc_kernel()
{
    extern __shared__ unsigned smX[];
    unsigned* Qs = smX;                    // [128][132] tf32
    unsigned* Ks = Qs + 128 * 132;         // [64][132]
    unsigned* Vs = Ks + 64 * 132;          // [64][136]
    unsigned* Pb = Vs + 64 * 136;          // [8 warps][16][68]

    const int qt = gridDim.x - 1 - blockIdx.x;   // heavy tiles first
    const int h = blockIdx.y;
    const int kvh = h >> 2;
    const int tid = threadIdx.x;
    const int warp = tid >> 5, lane = tid & 31;
    const int gid = lane >> 2, tig = lane & 3;
    unsigned* Pw = Pb + warp * 16 * 68;
    const float scale = 0.08838834764831845f;

    for (int i = tid; i < 128 * 32; i += 256) {
        int r = i >> 5, c4 = (i & 31) * 4;
        float4 v = *(const float4*)&g_sq[(size_t)(qt * 128 + r) * HD + h * DH + c4];
        *(uint4*)&Qs[r * 132 + c4] = make_uint4(f2tf(v.x), f2tf(v.y), f2tf(v.z), f2tf(v.w));
    }

    const int rbase = qt * 128 + warp * 16;
    float m_i[2] = {-1e30f, -1e30f};
    float l_i[2] = {0.0f, 0.0f};
    float c[16][4];
#pragma unroll
    for (int ni = 0; ni < 16; ni++)
#pragma unroll
        for (int v = 0; v < 4; v++) c[ni][v] = 0.0f;

    const int ktmax = 2 * qt + 1;
    for (int kt = 0; kt <= ktmax; kt++) {
        __syncthreads();
        for (int i = tid; i < 64 * 32; i += 256) {
            int r = i >> 5, c4 = (i & 31) * 4;
            size_t kb = (size_t)(kt * 64 + r) * KVD + kvh * DH + c4;
            float4 kv = *(const float4*)&g_sk[kb];
            float4 vv = *(const float4*)&g_v[kb];
            *(uint4*)&Ks[r * 132 + c4] = make_uint4(f2tf(kv.x), f2tf(kv.y), f2tf(kv.z), f2tf(kv.w));
            *(uint4*)&Vs[r * 136 + c4] = make_uint4(f2tf(vv.x), f2tf(vv.y), f2tf(vv.z), f2tf(vv.w));
        }
        __syncthreads();

        const int smin = kt * 64;
        if (smin > rbase + 15) continue;

        float sacc[8][4];
#pragma unroll
        for (int ni = 0; ni < 8; ni++)
#pragma unroll
            for (int v = 0; v < 4; v++) sacc[ni][v] = 0.0f;

#pragma unroll 4
        for (int k8 = 0; k8 < 16; k8++) {
            unsigned aq[4];
            int qr = warp * 16 + gid;
            aq[0] = Qs[qr * 132 + k8 * 8 + tig];
            aq[1] = Qs[(qr + 8) * 132 + k8 * 8 + tig];
            aq[2] = Qs[qr * 132 + k8 * 8 + tig + 4];
            aq[3] = Qs[(qr + 8) * 132 + k8 * 8 + tig + 4];
#pragma unroll
            for (int ni = 0; ni < 8; ni++) {
                unsigned b0 = Ks[(ni * 8 + gid) * 132 + k8 * 8 + tig];
                unsigned b1 = Ks[(ni * 8 + gid) * 132 + k8 * 8 + tig + 4];
                mma_tf32(sacc[ni], aq, b0, b1);
            }
        }

        const bool partial = (smin + 63 > rbase);
#pragma unroll
        for (int ni = 0; ni < 8; ni++)
#pragma unroll
            for (int v = 0; v < 4; v++) {
                float sv = sacc[ni][v] * scale;
                if (partial) {
                    int row = rbase + gid + (v >> 1) * 8;
                    int col = smin + ni * 8 + tig * 2 + (v & 1);
                    if (col > row) sv = -1e30f;
                }
                sacc[ni][v] = sv;
            }

#pragma unroll
        for (int h2 = 0; h2 < 2; h2++) {
            float rmax = -1e30f;
#pragma unroll
            for (int ni = 0; ni < 8; ni++)
                rmax = fmaxf(rmax, fmaxf(sacc[ni][2 * h2], sacc[ni][2 * h2 + 1]));
            rmax = fmaxf(rmax, __shfl_xor_sync(0xffffffffu, rmax, 1));
            rmax = fmaxf(rmax, __shfl_xor_sync(0xffffffffu, rmax, 2));
            float mnew = fmaxf(m_i[h2], rmax);
            float alpha = __expf(m_i[h2] - mnew);
            float rsum = 0.0f;
#pragma unroll
            for (int ni = 0; ni < 8; ni++) {
                float p0 = __expf(sacc[ni][2 * h2] - mnew);
                float p1 = __expf(sacc[ni][2 * h2 + 1] - mnew);
                sacc[ni][2 * h2] = p0;
                sacc[ni][2 * h2 + 1] = p1;
                rsum += p0 + p1;
            }
            rsum += __shfl_xor_sync(0xffffffffu, rsum, 1);
            rsum += __shfl_xor_sync(0xffffffffu, rsum, 2);
            l_i[h2] = l_i[h2] * alpha + rsum;
            m_i[h2] = mnew;
#pragma unroll
            for (int ni = 0; ni < 16; ni++) {
                c[ni][2 * h2]     *= alpha;
                c[ni][2 * h2 + 1] *= alpha;
            }
        }

#pragma unroll
        for (int ni = 0; ni < 8; ni++) {
            *(uint2*)&Pw[gid * 68 + ni * 8 + tig * 2] =
                make_uint2(f2tf(sacc[ni][0]), f2tf(sacc[ni][1]));
            *(uint2*)&Pw[(gid + 8) * 68 + ni * 8 + tig * 2] =
                make_uint2(f2tf(sacc[ni][2]), f2tf(sacc[ni][3]));
        }
        __syncwarp();

#pragma unroll 2
        for (int k8 = 0; k8 < 8; k8++) {
            unsigned ap[4];
            ap[0] = Pw[gid * 68 + k8 * 8 + tig];
            ap[1] = Pw[(gid + 8) * 68 + k8 * 8 + tig];
            ap[2] = Pw[gid * 68 + k8 * 8 + tig + 4];
            ap[3] = Pw[(gid + 8) * 68 + k8 * 8 + tig + 4];
#pragma unroll
            for (int ni = 0; ni < 16; ni++) {
                unsigned b0 = Vs[(k8 * 8 + tig) * 136 + ni * 8 + gid];
                unsigned b1 = Vs[(k8 * 8 + tig + 4) * 136 + ni * 8 + gid];
                mma_tf32(c[ni], ap, b0, b1);
            }
        }
    }

    const float inv0 = 1.0f / l_i[0];
    const float inv1 = 1.0f / l_i[1];
    const int r0 = rbase + gid, r1 = r0 + 8;
#pragma unroll
    for (int ni = 0; ni < 16; ni++) {
        int col = h * DH + ni * 8 + tig * 2;
        *(float2*)&g_attn[(size_t)r0 * HD + col] = make_float2(c[ni][0] * inv0, c[ni][1] * inv0);
        *(float2*)&g_attn[(size_t)r1 * HD + col] = make_float2(c[ni][2] * inv1, c[ni][3] * inv1);
    }
}

// =============================================================================
// host launcher
// =============================================================================
extern "C" void kernel_launch(void* const* d_in, const int* in_sizes, int n_in,
                              void* d_out, int out_size)
{
    (void)in_sizes; (void)n_in; (void)out_size;
    const float* hs = (const float*)d_in[0];
    const float* Wq = (const float*)d_in[1];
    const float* Wk = (const float*)d_in[2];
    const float* Wv = (const float*)d_in[3];
    const float* Wo = (const float*)d_in[4];
    float* out = (float*)d_out;

    float *p_q, *p_k, *p_v, *p_attn, *p_gla;
    cudaGetSymbolAddress((void**)&p_q,    g_q);
    cudaGetSymbolAddress((void**)&p_k,    g_k);
    cudaGetSymbolAddress((void**)&p_v,    g_v);
    cudaGetSymbolAddress((void**)&p_attn, g_attn);
    cudaGetSymbolAddress((void**)&p_gla,  g_gla);

    const int smem1   = 3 * 64 * 132 * 4;                                    // 101376
    const int smem3   = (2 * 128 * 65 + 128 * 132 + 64 * 132 + 64 * 65) * 4; // 184576
    const int smemATC = (128 * 132 + 64 * 132 + 64 * 136 + 8 * 16 * 68) * 4; // 171008
    cudaFuncSetAttribute(proj_kernel,      cudaFuncAttributeMaxDynamicSharedMemorySize, GEMM_SMEM);
    cudaFuncSetAttribute(wo_kernel,        cudaFuncAttributeMaxDynamicSharedMemorySize, GEMM_SMEM);
    cudaFuncSetAttribute(gla_pass1_kernel, cudaFuncAttributeMaxDynamicSharedMemorySize, smem1);
    cudaFuncSetAttribute(gla_pass3_kernel, cudaFuncAttributeMaxDynamicSharedMemorySize, smem3);
    cudaFuncSetAttribute(attn_tc_kernel,   cudaFuncAttributeMaxDynamicSharedMemorySize, smemATC);

    // 1. q/k/v projections in one launch (tf32 mma, double-buffered)
    proj_kernel<<<dim3(24, 16), 256, GEMM_SMEM>>>(hs, Wq, Wk, Wv, p_q, p_k, p_v);
    // 2. prep: softmax / rope / gates
    prep_q_kernel<<<dim3(NTOK, NH), 128>>>();
    prep_k_kernel<<<dim3(NTOK, NKV), 128>>>();
    // 3. GLA chunked
    gla_pass1_kernel<<<dim3(NCH, NKV), 256, smem1>>>();
    gla_scan_kernel<<<dim3(NKV, DH), 128>>>();
    gla_pass3_kernel<<<dim3(NCH, NH), 256, smem3>>>();
    // 4. causal flash attention (tensor cores, heavy-first)
    attn_tc_kernel<<<dim3(NTOK / 128, NH), 256, smemATC>>>();
    // 5. out = (0.5*(y + o_gla)) @ Wo (fused average)
    wo_kernel<<<dim3(16, 16), 256, GEMM_SMEM>>>(p_attn, p_gla, Wo, out);
}

// round 6
// speedup vs baseline: 2.3388x; 1.0551x over previous
#include <cuda_runtime.h>
#include <math.h>

// Problem constants
#define NTOK 2048
#define HIDN 2048
#define NH   16
#define NKV  4
#define DH   128
#define HD   (NH*DH)     // 2048
#define KVD  (NKV*DH)    // 512
#define CH   64
#define NCH  (NTOK/CH)   // 32

// ---------------- scratch (static device globals; no allocation) -------------
__device__ float  g_sq  [NTOK*HD];
__device__ float  g_qs  [NTOK*HD];
__device__ float  g_sk  [NTOK*KVD];
__device__ float  g_ks  [NTOK*KVD];
__device__ float  g_gl  [NTOK*KVD];
__device__ float  g_v   [NTOK*KVD];
__device__ float  g_lam [NTOK*KVD];
__device__ float  g_kdl [NTOK*KVD];
__device__ float  g_dS  [NKV*NCH*DH*DH];
__device__ float  g_ltot[NKV*NCH*DH];
__device__ float  g_attn[NTOK*HD];
__device__ float  g_gla [NTOK*HD];
__device__ float2 g_rope[NTOK*64];     // (cos, sin) per (token, freq)

// ---------------- tf32 mma helpers ------------------------------------------
__device__ __forceinline__ unsigned f2tf(float x) {
    unsigned r;
    asm("cvt.rna.tf32.f32 %0, %1;" : "=r"(r) : "f"(x));
    return r;
}

__device__ __forceinline__ uint4 cvt4(float4 v) {
    return make_uint4(f2tf(v.x), f2tf(v.y), f2tf(v.z), f2tf(v.w));
}

__device__ __forceinline__ void mma_tf32(float c[4], const unsigned a[4],
                                         unsigned b0, unsigned b1) {
    asm volatile(
        "mma.sync.aligned.m16n8k8.row.col.f32.tf32.tf32.f32 "
        "{%0,%1,%2,%3}, {%4,%5,%6,%7}, {%8,%9}, {%0,%1,%2,%3};"
        : "+f"(c[0]), "+f"(c[1]), "+f"(c[2]), "+f"(c[3])
        : "r"(a[0]), "r"(a[1]), "r"(a[2]), "r"(a[3]), "r"(b0), "r"(b1));
}

// =============================================================================
// RoPE cos/sin table (same math as before, computed once per launch)
// =============================================================================
__global__ void __launch_bounds__(64) rope_table_kernel()
{
    const int t = blockIdx.x, j = threadIdx.x;
    float inv_freq = (float)pow(10000.0, -(double)(2 * j) / 128.0);
    float fr = (float)t * inv_freq;
    double ang = (double)fr;
    g_rope[t * 64 + j] = make_float2((float)cos(ang), (float)sin(ang));
}

// =============================================================================
// TF32 GEMM core: acc[4][4][4] = op(A) @ B over a 128x128 tile. 256 threads,
// 8 warps (2m x 4n), warp tile 64x32. BK=32, double-buffered smem, one sync
// per slab. A2 != null -> A operand is 0.5*(A+A2).
// =============================================================================
#define AS_STRIDE 36
#define BS_STRIDE 136
#define AS_BUF (128 * AS_STRIDE)
#define BS_BUF (32 * BS_STRIDE)
#define GEMM_SMEM ((2 * AS_BUF + 2 * BS_BUF) * 4)   // 71680 bytes

__device__ __forceinline__ void gemm_tf32_acc(
    unsigned* __restrict__ sm,
    const float* __restrict__ A, const float* __restrict__ A2,
    const float* __restrict__ B,
    int N, int K, int bm, int bn, float acc[4][4][4])
{
    unsigned* As = sm;
    unsigned* Bs = sm + 2 * AS_BUF;

    const int tid  = threadIdx.x;
    const int warp = tid >> 5, lane = tid & 31;
    const int gid  = lane >> 2, tig = lane & 3;
    const int wm   = (warp & 1) * 64, wn = (warp >> 1) * 32;

    const int ar = tid >> 1, ac = (tid & 1) * 16;
    const int br = tid >> 3, bc = (tid & 7) * 16;

    const float* Arow  = A  + (size_t)(bm + ar) * K + ac;
    const float* A2row = A2 ? (A2 + (size_t)(bm + ar) * K + ac) : nullptr;

    float4 pa[4], pb[4];

#pragma unroll
    for (int mi = 0; mi < 4; mi++)
#pragma unroll
        for (int ni = 0; ni < 4; ni++)
#pragma unroll
            for (int v = 0; v < 4; v++) acc[mi][ni][v] = 0.0f;

#pragma unroll
    for (int q = 0; q < 4; q++) {
        pa[q] = *(const float4*)&Arow[q * 4];
        if (A2row) {
            float4 a2 = *(const float4*)&A2row[q * 4];
            pa[q].x = 0.5f * (pa[q].x + a2.x); pa[q].y = 0.5f * (pa[q].y + a2.y);
            pa[q].z = 0.5f * (pa[q].z + a2.z); pa[q].w = 0.5f * (pa[q].w + a2.w);
        }
        pb[q] = *(const float4*)&B[(size_t)br * N + bn + bc + q * 4];
    }
#pragma unroll
    for (int q = 0; q < 4; q++) {
        *(uint4*)&As[ar * AS_STRIDE + ac + q * 4] = cvt4(pa[q]);
        *(uint4*)&Bs[br * BS_STRIDE + bc + q * 4] = cvt4(pb[q]);
    }
    __syncthreads();

    const int nIter = K >> 5;
    for (int it = 0; it < nIter; it++) {
        const bool more = (it + 1 < nIter);
        if (more) {
            const int k0 = (it + 1) << 5;
#pragma unroll
            for (int q = 0; q < 4; q++) {
                pa[q] = *(const float4*)&Arow[k0 + q * 4];
                if (A2row) {
                    float4 a2 = *(const float4*)&A2row[k0 + q * 4];
                    pa[q].x = 0.5f * (pa[q].x + a2.x); pa[q].y = 0.5f * (pa[q].y + a2.y);
                    pa[q].z = 0.5f * (pa[q].z + a2.z); pa[q].w = 0.5f * (pa[q].w + a2.w);
                }
                pb[q] = *(const float4*)&B[(size_t)(k0 + br) * N + bn + bc + q * 4];
            }
        }

        const unsigned* as = As + (it & 1) * AS_BUF;
        const unsigned* bs = Bs + (it & 1) * BS_BUF;
#pragma unroll
        for (int k8 = 0; k8 < 4; k8++) {
            unsigned af[4][4];
#pragma unroll
            for (int mi = 0; mi < 4; mi++) {
                int r = wm + mi * 16 + gid;
                af[mi][0] = as[r * AS_STRIDE + k8 * 8 + tig];
                af[mi][1] = as[(r + 8) * AS_STRIDE + k8 * 8 + tig];
                af[mi][2] = as[r * AS_STRIDE + k8 * 8 + tig + 4];
                af[mi][3] = as[(r + 8) * AS_STRIDE + k8 * 8 + tig + 4];
            }
#pragma unroll
            for (int ni = 0; ni < 4; ni++) {
                unsigned b0 = bs[(k8 * 8 + tig) * BS_STRIDE + wn + ni * 8 + gid];
                unsigned b1 = bs[(k8 * 8 + tig + 4) * BS_STRIDE + wn + ni * 8 + gid];
#pragma unroll
                for (int mi = 0; mi < 4; mi++) mma_tf32(acc[mi][ni], af[mi], b0, b1);
            }
        }

        if (more) {
            unsigned* asn = As + ((it + 1) & 1) * AS_BUF;
            unsigned* bsn = Bs + ((it + 1) & 1) * BS_BUF;
#pragma unroll
            for (int q = 0; q < 4; q++) {
                *(uint4*)&asn[ar * AS_STRIDE + ac + q * 4] = cvt4(pa[q]);
                *(uint4*)&bsn[br * BS_STRIDE + bc + q * 4] = cvt4(pb[q]);
            }
        }
        __syncthreads();
    }
}

// Plain global store of the 128x128 acc tile.
__device__ __forceinline__ void gemm_store(
    float acc[4][4][4], float* __restrict__ C, int N, int bm, int bn)
{
    const int tid  = threadIdx.x;
    const int warp = tid >> 5, lane = tid & 31;
    const int gid  = lane >> 2, tig = lane & 3;
    const int wm   = (warp & 1) * 64, wn = (warp >> 1) * 32;
#pragma unroll
    for (int mi = 0; mi < 4; mi++) {
        int r0 = bm + wm + mi * 16 + gid;
#pragma unroll
        for (int ni = 0; ni < 4; ni++) {
            int col = bn + wn + ni * 8 + tig * 2;
            *(float2*)&C[(size_t)r0 * N + col]       = make_float2(acc[mi][ni][0], acc[mi][ni][1]);
            *(float2*)&C[(size_t)(r0 + 8) * N + col] = make_float2(acc[mi][ni][2], acc[mi][ni][3]);
        }
    }
}

// Fused prep epilogue: stage acc tile into smem, then per row (= one token of
// one head): softmax -> outs, RoPE (via table) -> outr, optional logsigmoid/16
// -> outg. Identical arithmetic to the old prep kernels.
__device__ __forceinline__ void prep_epilogue(
    float acc[4][4][4], unsigned* sm, int bm, int rowstride, int headoff,
    float* __restrict__ outs, float* __restrict__ outr, float* __restrict__ outg)
{
    float* St = (float*)sm;   // [128][132] — reuses GEMM buffers (>= 67584 B)
    const int tid  = threadIdx.x;
    const int warp = tid >> 5, lane = tid & 31;
    const int gid  = lane >> 2, tig = lane & 3;
    const int wm   = (warp & 1) * 64, wn = (warp >> 1) * 32;

#pragma unroll
    for (int mi = 0; mi < 4; mi++) {
        int r0 = wm + mi * 16 + gid;
#pragma unroll
        for (int ni = 0; ni < 4; ni++) {
            int col = wn + ni * 8 + tig * 2;
            *(float2*)&St[r0 * 132 + col]       = make_float2(acc[mi][ni][0], acc[mi][ni][1]);
            *(float2*)&St[(r0 + 8) * 132 + col] = make_float2(acc[mi][ni][2], acc[mi][ni][3]);
        }
    }
    __syncthreads();

    for (int r = warp; r < 128; r += 8) {
        const float* Sr = St + r * 132;
        float x0 = Sr[lane], x1 = Sr[lane + 32], x2 = Sr[lane + 64], x3 = Sr[lane + 96];

        float m = fmaxf(fmaxf(x0, x1), fmaxf(x2, x3));
#pragma unroll
        for (int o = 16; o; o >>= 1) m = fmaxf(m, __shfl_xor_sync(0xffffffffu, m, o));

        float e0 = expf(x0 - m), e1 = expf(x1 - m), e2 = expf(x2 - m), e3 = expf(x3 - m);
        float s = e0 + e1 + e2 + e3;
#pragma unroll
        for (int o = 16; o; o >>= 1) s += __shfl_xor_sync(0xffffffffu, s, o);

        const int t = bm + r;
        const size_t ob = (size_t)t * rowstride + headoff;
        outs[ob + lane]      = e0 / s;
        outs[ob + lane + 32] = e1 / s;
        outs[ob + lane + 64] = e2 / s;
        outs[ob + lane + 96] = e3 / s;

        float2 cs0 = g_rope[t * 64 + lane];
        float2 cs1 = g_rope[t * 64 + lane + 32];
        outr[ob + lane]      = x0 * cs0.x - x2 * cs0.y;
        outr[ob + lane + 64] = x2 * cs0.x + x0 * cs0.y;
        outr[ob + lane + 32] = x1 * cs1.x - x3 * cs1.y;
        outr[ob + lane + 96] = x3 * cs1.x + x1 * cs1.y;

        if (outg) {
            outg[ob + lane]      = (fminf(x0, 0.0f) - log1pf(expf(-fabsf(x0)))) * 0.0625f;
            outg[ob + lane + 32] = (fminf(x1, 0.0f) - log1pf(expf(-fabsf(x1)))) * 0.0625f;
            outg[ob + lane + 64] = (fminf(x2, 0.0f) - log1pf(expf(-fabsf(x2)))) * 0.0625f;
            outg[ob + lane + 96] = (fminf(x3, 0.0f) - log1pf(expf(-fabsf(x3)))) * 0.0625f;
        }
    }
}

// Merged q/k/v projections + fused prep. grid.x: [0,16)->q (+softmax/rope),
// [16,20)->k (+softmax/rope/gate), [20,24)->v (plain store).
__global__ void __launch_bounds__(256) proj_kernel(
    const float* __restrict__ hs,
    const float* __restrict__ Wq, const float* __restrict__ Wk,
    const float* __restrict__ Wv)
{
    extern __shared__ unsigned smg[];
    const int bx = blockIdx.x, bm = blockIdx.y * 128;
    float acc[4][4][4];

    if (bx < 16) {
        gemm_tf32_acc(smg, hs, nullptr, Wq, HD, HIDN, bm, bx * 128, acc);
        prep_epilogue(acc, smg, bm, HD, bx * DH, g_qs, g_sq, nullptr);
    } else if (bx < 20) {
        const int kvh = bx - 16;
        gemm_tf32_acc(smg, hs, nullptr, Wk, KVD, HIDN, bm, kvh * 128, acc);
        prep_epilogue(acc, smg, bm, KVD, kvh * DH, g_ks, g_sk, g_gl);
    } else {
        gemm_tf32_acc(smg, hs, nullptr, Wv, KVD, HIDN, bm, (bx - 20) * 128, acc);
        gemm_store(acc, g_v, KVD, bm, (bx - 20) * 128);
    }
}

// Output projection: out = (0.5*(attn + gla)) @ Wo
__global__ void __launch_bounds__(256) wo_kernel(
    const float* __restrict__ attn, const float* __restrict__ gla,
    const float* __restrict__ Wo, float* __restrict__ out)
{
    extern __shared__ unsigned smg[];
    float acc[4][4][4];
    gemm_tf32_acc(smg, attn, gla, Wo, HIDN, HD, blockIdx.y * 128, blockIdx.x * 128, acc);
    gemm_store(acc, out, HIDN, blockIdx.y * 128, blockIdx.x * 128);
}

// =============================================================================
// GLA pass 1: grid (NCH, NKV, 2) — z selects a 64-wide d-half for occupancy.
// Gate prefix -> lam/kdl/ltot (its half), then dS[d-half][d'] = kw^T @ V.
// =============================================================================
#define P1_SMEM ((64 * 68 * 2 + 64 * 132 + 64) * 4)

__global__ void __launch_bounds__(256) gla_pass1_kernel()
{
    extern __shared__ float sm1[];
    float* GL   = sm1;                 // [64][68] gl, then lam (in place)
    float* KW   = GL + 64 * 68;        // [64][68]
    float* Vt   = KW + 64 * 68;        // [64][132]
    float* LEND = Vt + 64 * 132;       // [64]

    const int c = blockIdx.x, kvh = blockIdx.y, z = blockIdx.z;
    const int dbase = z * 64;
    const int tid = threadIdx.x;

    for (int i = tid; i < 64 * 64; i += 256) {
        int r = i >> 6, d = i & 63;
        GL[r * 68 + d] = g_gl[(c * CH + r) * KVD + kvh * DH + dbase + d];
    }
    for (int i = tid; i < 64 * 128; i += 256) {
        int r = i >> 7, d = i & 127;
        Vt[r * 132 + d] = g_v[(c * CH + r) * KVD + kvh * DH + d];
    }
    __syncthreads();

    if (tid < 64) {
        float cum = 0.0f;
#pragma unroll 4
        for (int t = 0; t < CH; t++) {
            cum += GL[t * 68 + tid];
            GL[t * 68 + tid] = expf(cum);
        }
        float le = GL[63 * 68 + tid];
        LEND[tid] = le;
        g_ltot[(kvh * NCH + c) * DH + dbase + tid] = le;
    }
    __syncthreads();

    for (int i = tid; i < 64 * 64; i += 256) {
        int r = i >> 6, d = i & 63;
        int gi = (c * CH + r) * KVD + kvh * DH + dbase + d;
        float lam = GL[r * 68 + d];
        float kdl = g_ks[gi] / lam;
        g_kdl[gi] = kdl;
        g_lam[gi] = lam;
        KW[r * 68 + d] = kdl * LEND[d];
    }
    __syncthreads();

    // dS[dbase+dl][d'] = sum_t KW[t][dl] * Vt[t][d'] : 64x128, inner 64
    const int tx = tid & 15, ty = tid >> 4;
    float acc[4][8];
#pragma unroll
    for (int i = 0; i < 4; i++)
#pragma unroll
        for (int j = 0; j < 8; j++) acc[i][j] = 0.0f;

    for (int t = 0; t < CH; t++) {
        float a[4], b[8];
        *(float4*)&a[0] = *(const float4*)&KW[t * 68 + ty * 4];
        *(float4*)&b[0] = *(const float4*)&Vt[t * 132 + tx * 8];
        *(float4*)&b[4] = *(const float4*)&Vt[t * 132 + tx * 8 + 4];
#pragma unroll
        for (int i = 0; i < 4; i++)
#pragma unroll
            for (int j = 0; j < 8; j++) acc[i][j] += a[i] * b[j];
    }

    float* dS = g_dS + (size_t)(kvh * NCH + c) * DH * DH + (size_t)dbase * DH;
#pragma unroll
    for (int i = 0; i < 4; i++) {
        *(float4*)&dS[(ty * 4 + i) * DH + tx * 8]     = make_float4(acc[i][0], acc[i][1], acc[i][2], acc[i][3]);
        *(float4*)&dS[(ty * 4 + i) * DH + tx * 8 + 4] = make_float4(acc[i][4], acc[i][5], acc[i][6], acc[i][7]);
    }
}

// =============================================================================
// GLA pass 2: sequential scan over chunks
// =============================================================================
__global__ void __launch_bounds__(128) gla_scan_kernel()
{
    const int kvh = blockIdx.x, d = blockIdx.y;
    const int dp = threadIdx.x;
    float s = 0.0f;
    for (int c = 0; c < NCH; c++) {
        size_t idx = ((size_t)(kvh * NCH + c) * DH + d) * DH + dp;
        float tmp = g_dS[idx];
        float lt = g_ltot[(kvh * NCH + c) * DH + d];
        g_dS[idx] = s;
        s = s * lt + tmp;
    }
}

// =============================================================================
// GLA pass 3 (fp32 SIMT): per (chunk, head)
// =============================================================================
__global__ void __launch_bounds__(256) gla_pass3_kernel()
{
    extern __shared__ float sm3[];
    float* QT = sm3;               // [128][65]
    float* KT = QT + 128 * 65;
    float* Ss = KT + 128 * 65;     // [128][132]
    float* Vs = Ss + 128 * 132;    // [64][132]
    float* AT = Vs + 64 * 132;     // [64][65]

    const int c = blockIdx.x, h = blockIdx.y;
    const int kvh = h >> 2;
    const int tid = threadIdx.x;

    for (int idx = tid; idx < CH * DH; idx += 256) {
        int r = idx >> 7, d = idx & 127;
        int kb = (c * CH + r) * KVD + kvh * DH + d;
        float lam = g_lam[kb];
        QT[d * 65 + r] = g_qs[(c * CH + r) * HD + h * DH + d] * lam;
        KT[d * 65 + r] = g_kdl[kb];
        Vs[r * 132 + d] = g_v[kb];
    }
    const float* Sg = g_dS + (size_t)(kvh * NCH + c) * DH * DH;
    for (int idx = tid; idx < DH * DH; idx += 256) {
        int r = idx >> 7, d = idx & 127;
        Ss[r * 132 + d] = Sg[r * DH + d];
    }
    __syncthreads();

    const int tx = tid & 15, ty = tid >> 4;

    float O[4][8];
#pragma unroll
    for (int i = 0; i < 4; i++)
#pragma unroll
        for (int j = 0; j < 8; j++) O[i][j] = 0.0f;

    for (int dd = 0; dd < DH; dd++) {
        float a[4], b[8];
#pragma unroll
        for (int i = 0; i < 4; i++) a[i] = QT[dd * 65 + ty * 4 + i];
        *(float4*)&b[0] = *(const float4*)&Ss[dd * 132 + tx * 8];
        *(float4*)&b[4] = *(const float4*)&Ss[dd * 132 + tx * 8 + 4];
#pragma unroll
        for (int i = 0; i < 4; i++)
#pragma unroll
            for (int j = 0; j < 8; j++) O[i][j] += a[i] * b[j];
    }

    float Aacc[4][4];
#pragma unroll
    for (int i = 0; i < 4; i++)
#pragma unroll
        for (int j = 0; j < 4; j++) Aacc[i][j] = 0.0f;

    for (int dd = 0; dd < DH; dd++) {
        float a[4], b[4];
#pragma unroll
        for (int i = 0; i < 4; i++) a[i] = QT[dd * 65 + ty * 4 + i];
#pragma unroll
        for (int j = 0; j < 4; j++) b[j] = KT[dd * 65 + tx * 4 + j];
#pragma unroll
        for (int i = 0; i < 4; i++)
#pragma unroll
            for (int j = 0; j < 4; j++) Aacc[i][j] += a[i] * b[j];
    }
#pragma unroll
    for (int i = 0; i < 4; i++)
#pragma unroll
        for (int j = 0; j < 4; j++) {
            int t = ty * 4 + i, s = tx * 4 + j;
            AT[s * 65 + t] = (s <= t) ? Aacc[i][j] : 0.0f;
        }
    __syncthreads();

    for (int s = 0; s < CH; s++) {
        float a[4], b[8];
#pragma unroll
        for (int i = 0; i < 4; i++) a[i] = AT[s * 65 + ty * 4 + i];
        *(float4*)&b[0] = *(const float4*)&Vs[s * 132 + tx * 8];
        *(float4*)&b[4] = *(const float4*)&Vs[s * 132 + tx * 8 + 4];
#pragma unroll
        for (int i = 0; i < 4; i++)
#pragma unroll
            for (int j = 0; j < 8; j++) O[i][j] += a[i] * b[j];
    }

#pragma unroll
    for (int i = 0; i < 4; i++) {
        int t = c * CH + ty * 4 + i;
        *(float4*)&g_gla[t * HD + h * DH + tx * 8]     = make_float4(O[i][0], O[i][1], O[i][2], O[i][3]);
        *(float4*)&g_gla[t * HD + h * DH + tx * 8 + 4] = make_float4(O[i][4], O[i][5], O[i][6], O[i][7]);
    }
}

// =============================================================================
// Causal flash attention, tf32 mma, cp.async-pipelined K (double) / V (single).
// K/V stored fp32 in smem; tf32 conversion at fragment consume (bit-identical).
// =============================================================================
#define ATTN_SMEM ((128*132 + 2*64*132 + 64*136 + 8*16*68) * 4)   // 204800 B

__device__ __forceinline__ void cp16(void* dst, const void* src) {
    unsigned d = (unsigned)__cvta_generic_to_shared(dst);
    asm volatile("cp.async.cg.shared.global [%0], [%1], 16;" :: "r"(d), "l"(src));
}

__global__ void __launch_bounds__(256) attn_tc_kernel()
{
    extern __shared__ char smraw[];
    unsigned* Qs = (unsigned*)smraw;                              // [128][132] tf32
    float*    Ks = (float*)(smraw + 128 * 132 * 4);               // [2][64][132] fp32
    float*    Vs = (float*)(smraw + (128 * 132 + 2 * 64 * 132) * 4); // [64][136] fp32
    unsigned* Pb = (unsigned*)(smraw + (128 * 132 + 2 * 64 * 132 + 64 * 136) * 4);

    const int qt = gridDim.x - 1 - blockIdx.x;   // heavy tiles first
    const int h = blockIdx.y;
    const int kvh = h >> 2;
    const int tid = threadIdx.x;
    const int warp = tid >> 5, lane = tid & 31;
    const int gid = lane >> 2, tig = lane & 3;
    unsigned* Pw = Pb + warp * 16 * 68;
    const float scale = 0.08838834764831845f;
    const int ktmax = 2 * qt + 1;

    // issue K_0 before the Q load so it overlaps
    {
#pragma unroll
        for (int i = 0; i < 8; i++) {
            int idx = tid + i * 256;
            int r = idx >> 5, c4 = (idx & 31) * 4;
            cp16(&Ks[r * 132 + c4], &g_sk[(size_t)r * KVD + kvh * DH + c4]);
        }
        asm volatile("cp.async.commit_group;");
    }

    for (int i = tid; i < 128 * 32; i += 256) {
        int r = i >> 5, c4 = (i & 31) * 4;
        float4 v = *(const float4*)&g_sq[(size_t)(qt * 128 + r) * HD + h * DH + c4];
        *(uint4*)&Qs[r * 132 + c4] = make_uint4(f2tf(v.x), f2tf(v.y), f2tf(v.z), f2tf(v.w));
    }

    const int rbase = qt * 128 + warp * 16;
    float m_i[2] = {-1e30f, -1e30f};
    float l_i[2] = {0.0f, 0.0f};
    float c[16][4];
#pragma unroll
    for (int ni = 0; ni < 16; ni++)
#pragma unroll
        for (int v = 0; v < 4; v++) c[ni][v] = 0.0f;

    for (int kt = 0; kt <= ktmax; kt++) {
        __syncthreads();   // prev PV / QK done; Q visible on kt==0

        // issue V_kt
#pragma unroll
        for (int i = 0; i < 8; i++) {
            int idx = tid + i * 256;
            int r = idx >> 5, c4 = (idx & 31) * 4;
            cp16(&Vs[r * 136 + c4], &g_v[(size_t)(kt * 64 + r) * KVD + kvh * DH + c4]);
        }
        asm volatile("cp.async.commit_group;");

        // issue K_{kt+1} (dup of kt on last iter to keep group count uniform)
        {
            const int ktn = (kt < ktmax) ? kt + 1 : kt;
            float* KB = Ks + ((kt + 1) & 1) * 64 * 132;
#pragma unroll
            for (int i = 0; i < 8; i++) {
                int idx = tid + i * 256;
                int r = idx >> 5, c4 = (idx & 31) * 4;
                cp16(&KB[r * 132 + c4], &g_sk[(size_t)(ktn * 64 + r) * KVD + kvh * DH + c4]);
            }
            asm volatile("cp.async.commit_group;");
        }

        asm volatile("cp.async.wait_group 2;");   // K_kt complete
        __syncthreads();

        const float* KB = Ks + (kt & 1) * 64 * 132;
        const int smin = kt * 64;
        const bool active = (smin <= rbase + 15);

        if (active) {
            float sacc[8][4];
#pragma unroll
            for (int ni = 0; ni < 8; ni++)
#pragma unroll
                for (int v = 0; v < 4; v++) sacc[ni][v] = 0.0f;

#pragma unroll 4
            for (int k8 = 0; k8 < 16; k8++) {
                unsigned aq[4];
                int qr = warp * 16 + gid;
                aq[0] = Qs[qr * 132 + k8 * 8 + tig];
                aq[1] = Qs[(qr + 8) * 132 + k8 * 8 + tig];
                aq[2] = Qs[qr * 132 + k8 * 8 + tig + 4];
                aq[3] = Qs[(qr + 8) * 132 + k8 * 8 + tig + 4];
#pragma unroll
                for (int ni = 0; ni < 8; ni++) {
                    unsigned b0 = f2tf(KB[(ni * 8 + gid) * 132 + k8 * 8 + tig]);
                    unsigned b1 = f2tf(KB[(ni * 8 + gid) * 132 + k8 * 8 + tig + 4]);
                    mma_tf32(sacc[ni], aq, b0, b1);
                }
            }

            const bool partial = (smin + 63 > rbase);
#pragma unroll
            for (int ni = 0; ni < 8; ni++)
#pragma unroll
                for (int v = 0; v < 4; v++) {
                    float sv = sacc[ni][v] * scale;
                    if (partial) {
                        int row = rbase + gid + (v >> 1) * 8;
                        int col = smin + ni * 8 + tig * 2 + (v & 1);
                        if (col > row) sv = -1e30f;
                    }
                    sacc[ni][v] = sv;
                }

#pragma unroll
            for (int h2 = 0; h2 < 2; h2++) {
                float rmax = -1e30f;
#pragma unroll
                for (int ni = 0; ni < 8; ni++)
                    rmax = fmaxf(rmax, fmaxf(sacc[ni][2 * h2], sacc[ni][2 * h2 + 1]));
                rmax = fmaxf(rmax, __shfl_xor_sync(0xffffffffu, rmax, 1));
                rmax = fmaxf(rmax, __shfl_xor_sync(0xffffffffu, rmax, 2));
                float mnew = fmaxf(m_i[h2], rmax);
                float alpha = __expf(m_i[h2] - mnew);
                float rsum = 0.0f;
#pragma unroll
                for (int ni = 0; ni < 8; ni++) {
                    float p0 = __expf(sacc[ni][2 * h2] - mnew);
                    float p1 = __expf(sacc[ni][2 * h2 + 1] - mnew);
                    sacc[ni][2 * h2] = p0;
                    sacc[ni][2 * h2 + 1] = p1;
                    rsum += p0 + p1;
                }
                rsum += __shfl_xor_sync(0xffffffffu, rsum, 1);
                rsum += __shfl_xor_sync(0xffffffffu, rsum, 2);
                l_i[h2] = l_i[h2] * alpha + rsum;
                m_i[h2] = mnew;
#pragma unroll
                for (int ni = 0; ni < 16; ni++) {
                    c[ni][2 * h2]     *= alpha;
                    c[ni][2 * h2 + 1] *= alpha;
                }
            }

#pragma unroll
            for (int ni = 0; ni < 8; ni++) {
                *(uint2*)&Pw[gid * 68 + ni * 8 + tig * 2] =
                    make_uint2(f2tf(sacc[ni][0]), f2tf(sacc[ni][1]));
                *(uint2*)&Pw[(gid + 8) * 68 + ni * 8 + tig * 2] =
                    make_uint2(f2tf(sacc[ni][2]), f2tf(sacc[ni][3]));
            }
        }

        asm volatile("cp.async.wait_group 1;");   // V_kt complete
        __syncthreads();

        if (active) {
#pragma unroll 2
            for (int k8 = 0; k8 < 8; k8++) {
                unsigned ap[4];
                ap[0] = Pw[gid * 68 + k8 * 8 + tig];
                ap[1] = Pw[(gid + 8) * 68 + k8 * 8 + tig];
                ap[2] = Pw[gid * 68 + k8 * 8 + tig + 4];
                ap[3] = Pw[(gid + 8) * 68 + k8 * 8 + tig + 4];
#pragma unroll
                for (int ni = 0; ni < 16; ni++) {
                    unsigned b0 = f2tf(Vs[(k8 * 8 + tig) * 136 + ni * 8 + gid]);
                    unsigned b1 = f2tf(Vs[(k8 * 8 + tig + 4) * 136 + ni * 8 + gid]);
                    mma_tf32(c[ni], ap, b0, b1);
                }
            }
        }
    }

    const float inv0 = 1.0f / l_i[0];
    const float inv1 = 1.0f / l_i[1];
    const int r0 = rbase + gid, r1 = r0 + 8;
#pragma unroll
    for (int ni = 0; ni < 16; ni++) {
        int col = h * DH + ni * 8 + tig * 2;
        *(float2*)&g_attn[(size_t)r0 * HD + col] = make_float2(c[ni][0] * inv0, c[ni][1] * inv0);
        *(float2*)&g_attn[(size_t)r1 * HD + col] = make_float2(c[ni][2] * inv1, c[ni][3] * inv1);
    }
}

// =============================================================================
// host launcher
// =============================================================================
extern "C" void kernel_launch(void* const* d_in, const int* in_sizes, int n_in,
                              void* d_out, int out_size)
{
    (void)in_sizes; (void)n_in; (void)out_size;
    const float* hs = (const float*)d_in[0];
    const float* Wq = (const float*)d_in[1];
    const float* Wk = (const float*)d_in[2];
    const float* Wv = (const float*)d_in[3];
    const float* Wo = (const float*)d_in[4];
    float* out = (float*)d_out;

    float *p_attn, *p_gla;
    cudaGetSymbolAddress((void**)&p_attn, g_attn);
    cudaGetSymbolAddress((void**)&p_gla,  g_gla);

    const int smem3 = (2 * 128 * 65 + 128 * 132 + 64 * 132 + 64 * 65) * 4;
    cudaFuncSetAttribute(proj_kernel,      cudaFuncAttributeMaxDynamicSharedMemorySize, GEMM_SMEM);
    cudaFuncSetAttribute(wo_kernel,        cudaFuncAttributeMaxDynamicSharedMemorySize, GEMM_SMEM);
    cudaFuncSetAttribute(gla_pass1_kernel, cudaFuncAttributeMaxDynamicSharedMemorySize, P1_SMEM);
    cudaFuncSetAttribute(gla_pass3_kernel, cudaFuncAttributeMaxDynamicSharedMemorySize, smem3);
    cudaFuncSetAttribute(attn_tc_kernel,   cudaFuncAttributeMaxDynamicSharedMemorySize, ATTN_SMEM);

    // 0. RoPE table
    rope_table_kernel<<<NTOK, 64>>>();
    // 1. q/k/v projections + fused softmax/rope/gate prep
    proj_kernel<<<dim3(24, 16), 256, GEMM_SMEM>>>(hs, Wq, Wk, Wv);
    // 2. GLA chunked
    gla_pass1_kernel<<<dim3(NCH, NKV, 2), 256, P1_SMEM>>>();
    gla_scan_kernel<<<dim3(NKV, DH), 128>>>();
    gla_pass3_kernel<<<dim3(NCH, NH), 256, smem3>>>();
    // 3. causal flash attention (tensor cores, cp.async pipelined, heavy-first)
    attn_tc_kernel<<<dim3(NTOK / 128, NH), 256, ATTN_SMEM>>>();
    // 4. out = (0.5*(y + o_gla)) @ Wo (fused average)
    wo_kernel<<<dim3(16, 16), 256, GEMM_SMEM>>>(p_attn, p_gla, Wo, out);
}

// round 8
// speedup vs baseline: 2.4544x; 1.0494x over previous
#include <cuda_runtime.h>
#include <math.h>

// Problem constants
#define NTOK 2048
#define HIDN 2048
#define NH   16
#define NKV  4
#define DH   128
#define HD   (NH*DH)     // 2048
#define KVD  (NKV*DH)    // 512
#define CH   64
#define NCH  (NTOK/CH)   // 32

// ---------------- scratch (static device globals; no allocation) -------------
__device__ float  g_sq  [NTOK*HD];
__device__ float  g_qs  [NTOK*HD];
__device__ float  g_sk  [NTOK*KVD];
__device__ float  g_ks  [NTOK*KVD];
__device__ float  g_gl  [NTOK*KVD];
__device__ float  g_v   [NTOK*KVD];
__device__ float  g_lam [NTOK*KVD];
__device__ float  g_kdl [NTOK*KVD];
__device__ float  g_dS  [NKV*NCH*DH*DH];   // pass1 output (per-chunk delta state)
__device__ float  g_S   [NKV*NCH*DH*DH];   // scan output (chunk-start state)
__device__ float  g_ltot[NKV*NCH*DH];
__device__ float  g_attn[NTOK*HD];         // 0.5*gla (pass3), then += 0.5*y (attn)
__device__ float2 g_rope[NTOK*64];

// ---------------- tf32 mma helpers ------------------------------------------
__device__ __forceinline__ unsigned f2tf(float x) {
    unsigned r;
    asm("cvt.rna.tf32.f32 %0, %1;" : "=r"(r) : "f"(x));
    return r;
}

__device__ __forceinline__ void mma_tf32(float c[4], const unsigned a[4],
                                         unsigned b0, unsigned b1) {
    asm volatile(
        "mma.sync.aligned.m16n8k8.row.col.f32.tf32.tf32.f32 "
        "{%0,%1,%2,%3}, {%4,%5,%6,%7}, {%8,%9}, {%0,%1,%2,%3};"
        : "+f"(c[0]), "+f"(c[1]), "+f"(c[2]), "+f"(c[3])
        : "r"(a[0]), "r"(a[1]), "r"(a[2]), "r"(a[3]), "r"(b0), "r"(b1));
}

__device__ __forceinline__ void cp16(void* dst, const void* src) {
    unsigned d = (unsigned)__cvta_generic_to_shared(dst);
    asm volatile("cp.async.cg.shared.global [%0], [%1], 16;" :: "r"(d), "l"(src));
}

// =============================================================================
// RoPE cos/sin table
// =============================================================================
__global__ void __launch_bounds__(64) rope_table_kernel()
{
    const int t = blockIdx.x, j = threadIdx.x;
    float inv_freq = (float)pow(10000.0, -(double)(2 * j) / 128.0);
    float fr = (float)t * inv_freq;
    double ang = (double)fr;
    g_rope[t * 64 + j] = make_float2((float)cos(ang), (float)sin(ang));
}

// =============================================================================
// TF32 GEMM v3: 128x128 tile, 128 threads (4 warps, 2x2, 64x64 warp tiles),
// BK=32, cp.async double-buffered (raw fp32 in smem, tf32 cvt at consume).
// =============================================================================
#define AS_STRIDE 36
#define BS_STRIDE 136
#define AS_BUF (128 * AS_STRIDE)
#define BS_BUF (32 * BS_STRIDE)
#define GEMM_SMEM ((2 * AS_BUF + 2 * BS_BUF) * 4)   // 71680 bytes

__device__ __forceinline__ void gemm_issue_slab(
    float* As, float* Bs,
    const float* __restrict__ A, const float* __restrict__ B,
    int N, int K, int bm, int bn, int k0)
{
    const int tid = threadIdx.x;
    // A: 128 rows x 32 cols; thread t -> row t, 8x cp16
    {
        const float* src = A + (size_t)(bm + tid) * K + k0;
        float* dst = As + tid * AS_STRIDE;
#pragma unroll
        for (int q = 0; q < 8; q++) cp16(dst + q * 4, src + q * 4);
    }
    // B: 32 rows x 128 cols; thread t -> row t>>2, col part (t&3)*4 + q*16
    {
        const int r = tid >> 2, cpart = (tid & 3) * 4;
        const float* src = B + (size_t)(k0 + r) * N + bn + cpart;
        float* dst = Bs + r * BS_STRIDE + cpart;
#pragma unroll
        for (int q = 0; q < 8; q++) cp16(dst + q * 16, src + q * 16);
    }
}

__device__ __forceinline__ void gemm_tf32_acc(
    float* __restrict__ sm,
    const float* __restrict__ A, const float* __restrict__ B,
    int N, int K, int bm, int bn, float acc[4][8][4])
{
    float* As = sm;
    float* Bs = sm + 2 * AS_BUF;

    const int tid  = threadIdx.x;
    const int warp = tid >> 5, lane = tid & 31;
    const int gid  = lane >> 2, tig = lane & 3;
    const int wm   = (warp & 1) * 64, wn = (warp >> 1) * 64;

#pragma unroll
    for (int mi = 0; mi < 4; mi++)
#pragma unroll
        for (int ni = 0; ni < 8; ni++)
#pragma unroll
            for (int v = 0; v < 4; v++) acc[mi][ni][v] = 0.0f;

    const int nIter = K >> 5;
    gemm_issue_slab(As, Bs, A, B, N, K, bm, bn, 0);
    asm volatile("cp.async.commit_group;");
    if (nIter > 1) {
        gemm_issue_slab(As + AS_BUF, Bs + BS_BUF, A, B, N, K, bm, bn, 32);
    }
    asm volatile("cp.async.commit_group;");

    for (int it = 0; it < nIter; it++) {
        if (it + 1 < nIter)
            asm volatile("cp.async.wait_group 1;");
        else
            asm volatile("cp.async.wait_group 0;");
        __syncthreads();

        const float* as = As + (it & 1) * AS_BUF;
        const float* bs = Bs + (it & 1) * BS_BUF;
#pragma unroll
        for (int k8 = 0; k8 < 4; k8++) {
            unsigned af[4][4];
#pragma unroll
            for (int mi = 0; mi < 4; mi++) {
                int r = wm + mi * 16 + gid;
                af[mi][0] = f2tf(as[r * AS_STRIDE + k8 * 8 + tig]);
                af[mi][1] = f2tf(as[(r + 8) * AS_STRIDE + k8 * 8 + tig]);
                af[mi][2] = f2tf(as[r * AS_STRIDE + k8 * 8 + tig + 4]);
                af[mi][3] = f2tf(as[(r + 8) * AS_STRIDE + k8 * 8 + tig + 4]);
            }
#pragma unroll
            for (int ni = 0; ni < 8; ni++) {
                unsigned b0 = f2tf(bs[(k8 * 8 + tig) * BS_STRIDE + wn + ni * 8 + gid]);
                unsigned b1 = f2tf(bs[(k8 * 8 + tig + 4) * BS_STRIDE + wn + ni * 8 + gid]);
#pragma unroll
                for (int mi = 0; mi < 4; mi++) mma_tf32(acc[mi][ni], af[mi], b0, b1);
            }
        }
        __syncthreads();

        if (it + 2 < nIter) {
            // slab (it+2) belongs in buffer ((it+2) & 1) == (it & 1) — the one
            // just consumed. (R7 bug: this parity was inverted.)
            gemm_issue_slab(As + (it & 1) * AS_BUF, Bs + (it & 1) * BS_BUF,
                            A, B, N, K, bm, bn, (it + 2) << 5);
        }
        asm volatile("cp.async.commit_group;");
    }
}

__device__ __forceinline__ void gemm_store(
    float acc[4][8][4], float* __restrict__ C, int N, int bm, int bn)
{
    const int tid  = threadIdx.x;
    const int warp = tid >> 5, lane = tid & 31;
    const int gid  = lane >> 2, tig = lane & 3;
    const int wm   = (warp & 1) * 64, wn = (warp >> 1) * 64;
#pragma unroll
    for (int mi = 0; mi < 4; mi++) {
        int r0 = bm + wm + mi * 16 + gid;
#pragma unroll
        for (int ni = 0; ni < 8; ni++) {
            int col = bn + wn + ni * 8 + tig * 2;
            *(float2*)&C[(size_t)r0 * N + col]       = make_float2(acc[mi][ni][0], acc[mi][ni][1]);
            *(float2*)&C[(size_t)(r0 + 8) * N + col] = make_float2(acc[mi][ni][2], acc[mi][ni][3]);
        }
    }
}

// Fused prep epilogue (4-warp version): softmax -> outs, RoPE -> outr,
// optional logsigmoid/16 -> outg. Identical arithmetic to the prep kernels.
__device__ __forceinline__ void prep_epilogue(
    float acc[4][8][4], float* sm, int bm, int rowstride, int headoff,
    float* __restrict__ outs, float* __restrict__ outr, float* __restrict__ outg)
{
    float* St = sm;   // [128][132] staging (fits in 71680B)
    const int tid  = threadIdx.x;
    const int warp = tid >> 5, lane = tid & 31;
    const int gid  = lane >> 2, tig = lane & 3;
    const int wm   = (warp & 1) * 64, wn = (warp >> 1) * 64;

#pragma unroll
    for (int mi = 0; mi < 4; mi++) {
        int r0 = wm + mi * 16 + gid;
#pragma unroll
        for (int ni = 0; ni < 8; ni++) {
            int col = wn + ni * 8 + tig * 2;
            *(float2*)&St[r0 * 132 + col]       = make_float2(acc[mi][ni][0], acc[mi][ni][1]);
            *(float2*)&St[(r0 + 8) * 132 + col] = make_float2(acc[mi][ni][2], acc[mi][ni][3]);
        }
    }
    __syncthreads();

    for (int r = warp; r < 128; r += 4) {
        const float* Sr = St + r * 132;
        float x0 = Sr[lane], x1 = Sr[lane + 32], x2 = Sr[lane + 64], x3 = Sr[lane + 96];

        float m = fmaxf(fmaxf(x0, x1), fmaxf(x2, x3));
#pragma unroll
        for (int o = 16; o; o >>= 1) m = fmaxf(m, __shfl_xor_sync(0xffffffffu, m, o));

        float e0 = expf(x0 - m), e1 = expf(x1 - m), e2 = expf(x2 - m), e3 = expf(x3 - m);
        float s = e0 + e1 + e2 + e3;
#pragma unroll
        for (int o = 16; o; o >>= 1) s += __shfl_xor_sync(0xffffffffu, s, o);

        const int t = bm + r;
        const size_t ob = (size_t)t * rowstride + headoff;
        outs[ob + lane]      = e0 / s;
        outs[ob + lane + 32] = e1 / s;
        outs[ob + lane + 64] = e2 / s;
        outs[ob + lane + 96] = e3 / s;

        float2 cs0 = g_rope[t * 64 + lane];
        float2 cs1 = g_rope[t * 64 + lane + 32];
        outr[ob + lane]      = x0 * cs0.x - x2 * cs0.y;
        outr[ob + lane + 64] = x2 * cs0.x + x0 * cs0.y;
        outr[ob + lane + 32] = x1 * cs1.x - x3 * cs1.y;
        outr[ob + lane + 96] = x3 * cs1.x + x1 * cs1.y;

        if (outg) {
            outg[ob + lane]      = (fminf(x0, 0.0f) - log1pf(expf(-fabsf(x0)))) * 0.0625f;
            outg[ob + lane + 32] = (fminf(x1, 0.0f) - log1pf(expf(-fabsf(x1)))) * 0.0625f;
            outg[ob + lane + 64] = (fminf(x2, 0.0f) - log1pf(expf(-fabsf(x2)))) * 0.0625f;
            outg[ob + lane + 96] = (fminf(x3, 0.0f) - log1pf(expf(-fabsf(x3)))) * 0.0625f;
        }
    }
}

// Merged q/k/v projections + fused prep.
__global__ void __launch_bounds__(128) proj_kernel(
    const float* __restrict__ hs,
    const float* __restrict__ Wq, const float* __restrict__ Wk,
    const float* __restrict__ Wv)
{
    extern __shared__ float smg[];
    const int bx = blockIdx.x, bm = blockIdx.y * 128;
    float acc[4][8][4];

    if (bx < 16) {
        gemm_tf32_acc(smg, hs, Wq, HD, HIDN, bm, bx * 128, acc);
        prep_epilogue(acc, smg, bm, HD, bx * DH, g_qs, g_sq, nullptr);
    } else if (bx < 20) {
        const int kvh = bx - 16;
        gemm_tf32_acc(smg, hs, Wk, KVD, HIDN, bm, kvh * 128, acc);
        prep_epilogue(acc, smg, bm, KVD, kvh * DH, g_ks, g_sk, g_gl);
    } else {
        gemm_tf32_acc(smg, hs, Wv, KVD, HIDN, bm, (bx - 20) * 128, acc);
        gemm_store(acc, g_v, KVD, bm, (bx - 20) * 128);
    }
}

// Output projection: out = g_attn @ Wo (g_attn already holds 0.5*y + 0.5*gla)
__global__ void __launch_bounds__(128) wo_kernel(
    const float* __restrict__ comb, const float* __restrict__ Wo,
    float* __restrict__ out)
{
    extern __shared__ float smg[];
    float acc[4][8][4];
    gemm_tf32_acc(smg, comb, Wo, HIDN, HD, blockIdx.y * 128, blockIdx.x * 128, acc);
    gemm_store(acc, out, HIDN, blockIdx.y * 128, blockIdx.x * 128);
}

// =============================================================================
// GLA pass 1: grid (NCH, NKV, 2) — z selects a 64-wide d-half.
// =============================================================================
#define P1_SMEM ((64 * 68 * 2 + 64 * 132 + 64) * 4)

__global__ void __launch_bounds__(256) gla_pass1_kernel()
{
    extern __shared__ float sm1[];
    float* GL   = sm1;                 // [64][68]
    float* KW   = GL + 64 * 68;        // [64][68]
    float* Vt   = KW + 64 * 68;        // [64][132]
    float* LEND = Vt + 64 * 132;       // [64]

    const int c = blockIdx.x, kvh = blockIdx.y, z = blockIdx.z;
    const int dbase = z * 64;
    const int tid = threadIdx.x;

    for (int i = tid; i < 64 * 64; i += 256) {
        int r = i >> 6, d = i & 63;
        GL[r * 68 + d] = g_gl[(c * CH + r) * KVD + kvh * DH + dbase + d];
    }
    for (int i = tid; i < 64 * 128; i += 256) {
        int r = i >> 7, d = i & 127;
        Vt[r * 132 + d] = g_v[(c * CH + r) * KVD + kvh * DH + d];
    }
    __syncthreads();

    if (tid < 64) {
        float cum = 0.0f;
#pragma unroll 4
        for (int t = 0; t < CH; t++) {
            cum += GL[t * 68 + tid];
            GL[t * 68 + tid] = expf(cum);
        }
        float le = GL[63 * 68 + tid];
        LEND[tid] = le;
        g_ltot[(kvh * NCH + c) * DH + dbase + tid] = le;
    }
    __syncthreads();

    for (int i = tid; i < 64 * 64; i += 256) {
        int r = i >> 6, d = i & 63;
        int gi = (c * CH + r) * KVD + kvh * DH + dbase + d;
        float lam = GL[r * 68 + d];
        float kdl = g_ks[gi] / lam;
        g_kdl[gi] = kdl;
        g_lam[gi] = lam;
        KW[r * 68 + d] = kdl * LEND[d];
    }
    __syncthreads();

    const int tx = tid & 15, ty = tid >> 4;
    float acc[4][8];
#pragma unroll
    for (int i = 0; i < 4; i++)
#pragma unroll
        for (int j = 0; j < 8; j++) acc[i][j] = 0.0f;

    for (int t = 0; t < CH; t++) {
        float a[4], b[8];
        *(float4*)&a[0] = *(const float4*)&KW[t * 68 + ty * 4];
        *(float4*)&b[0] = *(const float4*)&Vt[t * 132 + tx * 8];
        *(float4*)&b[4] = *(const float4*)&Vt[t * 132 + tx * 8 + 4];
#pragma unroll
        for (int i = 0; i < 4; i++)
#pragma unroll
            for (int j = 0; j < 8; j++) acc[i][j] += a[i] * b[j];
    }

    float* dS = g_dS + (size_t)(kvh * NCH + c) * DH * DH + (size_t)dbase * DH;
#pragma unroll
    for (int i = 0; i < 4; i++) {
        *(float4*)&dS[(ty * 4 + i) * DH + tx * 8]     = make_float4(acc[i][0], acc[i][1], acc[i][2], acc[i][3]);
        *(float4*)&dS[(ty * 4 + i) * DH + tx * 8 + 4] = make_float4(acc[i][4], acc[i][5], acc[i][6], acc[i][7]);
    }
}

// =============================================================================
// GLA pass 2: scan over chunks. Reads g_dS, writes g_S (separate arrays ->
// loads hoistable above stores), 4-deep register prefetch.
// =============================================================================
__global__ void __launch_bounds__(128) gla_scan_kernel()
{
    const int kvh = blockIdx.x, d = blockIdx.y;
    const int dp = threadIdx.x;

    __shared__ float lt[NCH];
    if (dp < NCH) lt[dp] = g_ltot[(kvh * NCH + dp) * DH + d];
    __syncthreads();

    const size_t base = (size_t)(kvh * NCH) * DH * DH + (size_t)d * DH + dp;
    const float* __restrict__ src = g_dS + base;
    float* __restrict__ dst = g_S + base;
    const size_t step = (size_t)DH * DH;

    float s = 0.0f;
    float pre[4];
#pragma unroll
    for (int c = 0; c < 4; c++) pre[c] = src[c * step];
#pragma unroll
    for (int c = 0; c < NCH; c++) {
        float v = pre[c & 3];
        if (c + 4 < NCH) pre[c & 3] = src[(c + 4) * step];
        dst[c * step] = s;
        s = s * lt[c] + v;
    }
}

// =============================================================================
// GLA pass 3 (fp32 SIMT, 512 threads): per (chunk, head). Writes 0.5*o_gla
// into g_attn (attn kernel later adds 0.5*y).
// =============================================================================
__global__ void __launch_bounds__(512) gla_pass3_kernel()
{
    extern __shared__ float sm3[];
    float* QT = sm3;               // [128][65]
    float* KT = QT + 128 * 65;
    float* Ss = KT + 128 * 65;     // [128][132]
    float* Vs = Ss + 128 * 132;    // [64][132]
    float* AT = Vs + 64 * 132;     // [64][65]

    const int c = blockIdx.x, h = blockIdx.y;
    const int kvh = h >> 2;
    const int tid = threadIdx.x;

    for (int idx = tid; idx < CH * DH; idx += 512) {
        int r = idx >> 7, d = idx & 127;
        int kb = (c * CH + r) * KVD + kvh * DH + d;
        float lam = g_lam[kb];
        QT[d * 65 + r] = g_qs[(c * CH + r) * HD + h * DH + d] * lam;
        KT[d * 65 + r] = g_kdl[kb];
        Vs[r * 132 + d] = g_v[kb];
    }
    const float* Sg = g_S + (size_t)(kvh * NCH + c) * DH * DH;
    for (int idx = tid; idx < DH * DH; idx += 512) {
        int r = idx >> 7, d = idx & 127;
        Ss[r * 132 + d] = Sg[r * DH + d];
    }
    __syncthreads();

    const int tx = tid & 15, ty = tid >> 4;   // ty 0..31

    float O[2][8];
#pragma unroll
    for (int i = 0; i < 2; i++)
#pragma unroll
        for (int j = 0; j < 8; j++) O[i][j] = 0.0f;

    for (int dd = 0; dd < DH; dd++) {
        float a[2], b[8];
#pragma unroll
        for (int i = 0; i < 2; i++) a[i] = QT[dd * 65 + ty * 2 + i];
        *(float4*)&b[0] = *(const float4*)&Ss[dd * 132 + tx * 8];
        *(float4*)&b[4] = *(const float4*)&Ss[dd * 132 + tx * 8 + 4];
#pragma unroll
        for (int i = 0; i < 2; i++)
#pragma unroll
            for (int j = 0; j < 8; j++) O[i][j] += a[i] * b[j];
    }

    float Aacc[2][4];
#pragma unroll
    for (int i = 0; i < 2; i++)
#pragma unroll
        for (int j = 0; j < 4; j++) Aacc[i][j] = 0.0f;

    for (int dd = 0; dd < DH; dd++) {
        float a[2], b[4];
#pragma unroll
        for (int i = 0; i < 2; i++) a[i] = QT[dd * 65 + ty * 2 + i];
#pragma unroll
        for (int j = 0; j < 4; j++) b[j] = KT[dd * 65 + tx * 4 + j];
#pragma unroll
        for (int i = 0; i < 2; i++)
#pragma unroll
            for (int j = 0; j < 4; j++) Aacc[i][j] += a[i] * b[j];
    }
#pragma unroll
    for (int i = 0; i < 2; i++)
#pragma unroll
        for (int j = 0; j < 4; j++) {
            int t = ty * 2 + i, s = tx * 4 + j;
            AT[s * 65 + t] = (s <= t) ? Aacc[i][j] : 0.0f;
        }
    __syncthreads();

    for (int s = 0; s < CH; s++) {
        float a[2], b[8];
#pragma unroll
        for (int i = 0; i < 2; i++) a[i] = AT[s * 65 + ty * 2 + i];
        *(float4*)&b[0] = *(const float4*)&Vs[s * 132 + tx * 8];
        *(float4*)&b[4] = *(const float4*)&Vs[s * 132 + tx * 8 + 4];
#pragma unroll
        for (int i = 0; i < 2; i++)
#pragma unroll
            for (int j = 0; j < 8; j++) O[i][j] += a[i] * b[j];
    }

#pragma unroll
    for (int i = 0; i < 2; i++) {
        int t = c * CH + ty * 2 + i;
        float4 o0 = make_float4(0.5f*O[i][0], 0.5f*O[i][1], 0.5f*O[i][2], 0.5f*O[i][3]);
        float4 o1 = make_float4(0.5f*O[i][4], 0.5f*O[i][5], 0.5f*O[i][6], 0.5f*O[i][7]);
        *(float4*)&g_attn[t * HD + h * DH + tx * 8]     = o0;
        *(float4*)&g_attn[t * HD + h * DH + tx * 8 + 4] = o1;
    }
}

// =============================================================================
// Causal flash attention, tf32 mma, cp.async-pipelined. Final store does
// g_attn += 0.5*y (pass3 already wrote 0.5*gla).
// =============================================================================
#define ATTN_SMEM ((128*132 + 2*64*132 + 64*136 + 8*16*68) * 4)   // 204800 B

__global__ void __launch_bounds__(256) attn_tc_kernel()
{
    extern __shared__ char smraw[];
    unsigned* Qs = (unsigned*)smraw;                                 // [128][132] tf32
    float*    Ks = (float*)(smraw + 128 * 132 * 4);                  // [2][64][132]
    float*    Vs = (float*)(smraw + (128 * 132 + 2 * 64 * 132) * 4); // [64][136]
    unsigned* Pb = (unsigned*)(smraw + (128 * 132 + 2 * 64 * 132 + 64 * 136) * 4);

    const int qt = gridDim.x - 1 - blockIdx.x;
    const int h = blockIdx.y;
    const int kvh = h >> 2;
    const int tid = threadIdx.x;
    const int warp = tid >> 5, lane = tid & 31;
    const int gid = lane >> 2, tig = lane & 3;
    unsigned* Pw = Pb + warp * 16 * 68;
    const float scale = 0.08838834764831845f;
    const int ktmax = 2 * qt + 1;

    {
#pragma unroll
        for (int i = 0; i < 8; i++) {
            int idx = tid + i * 256;
            int r = idx >> 5, c4 = (idx & 31) * 4;
            cp16(&Ks[r * 132 + c4], &g_sk[(size_t)r * KVD + kvh * DH + c4]);
        }
        asm volatile("cp.async.commit_group;");
    }

    for (int i = tid; i < 128 * 32; i += 256) {
        int r = i >> 5, c4 = (i & 31) * 4;
        float4 v = *(const float4*)&g_sq[(size_t)(qt * 128 + r) * HD + h * DH + c4];
        *(uint4*)&Qs[r * 132 + c4] = make_uint4(f2tf(v.x), f2tf(v.y), f2tf(v.z), f2tf(v.w));
    }

    const int rbase = qt * 128 + warp * 16;
    float m_i[2] = {-1e30f, -1e30f};
    float l_i[2] = {0.0f, 0.0f};
    float c[16][4];
#pragma unroll
    for (int ni = 0; ni < 16; ni++)
#pragma unroll
        for (int v = 0; v < 4; v++) c[ni][v] = 0.0f;

    for (int kt = 0; kt <= ktmax; kt++) {
        __syncthreads();

#pragma unroll
        for (int i = 0; i < 8; i++) {
            int idx = tid + i * 256;
            int r = idx >> 5, c4 = (idx & 31) * 4;
            cp16(&Vs[r * 136 + c4], &g_v[(size_t)(kt * 64 + r) * KVD + kvh * DH + c4]);
        }
        asm volatile("cp.async.commit_group;");

        {
            const int ktn = (kt < ktmax) ? kt + 1 : kt;
            float* KB = Ks + ((kt + 1) & 1) * 64 * 132;
#pragma unroll
            for (int i = 0; i < 8; i++) {
                int idx = tid + i * 256;
                int r = idx >> 5, c4 = (idx & 31) * 4;
                cp16(&KB[r * 132 + c4], &g_sk[(size_t)(ktn * 64 + r) * KVD + kvh * DH + c4]);
            }
            asm volatile("cp.async.commit_group;");
        }

        asm volatile("cp.async.wait_group 2;");
        __syncthreads();

        const float* KB = Ks + (kt & 1) * 64 * 132;
        const int smin = kt * 64;
        const bool active = (smin <= rbase + 15);

        if (active) {
            float sacc[8][4];
#pragma unroll
            for (int ni = 0; ni < 8; ni++)
#pragma unroll
                for (int v = 0; v < 4; v++) sacc[ni][v] = 0.0f;

#pragma unroll 4
            for (int k8 = 0; k8 < 16; k8++) {
                unsigned aq[4];
                int qr = warp * 16 + gid;
                aq[0] = Qs[qr * 132 + k8 * 8 + tig];
                aq[1] = Qs[(qr + 8) * 132 + k8 * 8 + tig];
                aq[2] = Qs[qr * 132 + k8 * 8 + tig + 4];
                aq[3] = Qs[(qr + 8) * 132 + k8 * 8 + tig + 4];
#pragma unroll
                for (int ni = 0; ni < 8; ni++) {
                    unsigned b0 = f2tf(KB[(ni * 8 + gid) * 132 + k8 * 8 + tig]);
                    unsigned b1 = f2tf(KB[(ni * 8 + gid) * 132 + k8 * 8 + tig + 4]);
                    mma_tf32(sacc[ni], aq, b0, b1);
                }
            }

            const bool partial = (smin + 63 > rbase);
#pragma unroll
            for (int ni = 0; ni < 8; ni++)
#pragma unroll
                for (int v = 0; v < 4; v++) {
                    float sv = sacc[ni][v] * scale;
                    if (partial) {
                        int row = rbase + gid + (v >> 1) * 8;
                        int col = smin + ni * 8 + tig * 2 + (v & 1);
                        if (col > row) sv = -1e30f;
                    }
                    sacc[ni][v] = sv;
                }

#pragma unroll
            for (int h2 = 0; h2 < 2; h2++) {
                float rmax = -1e30f;
#pragma unroll
                for (int ni = 0; ni < 8; ni++)
                    rmax = fmaxf(rmax, fmaxf(sacc[ni][2 * h2], sacc[ni][2 * h2 + 1]));
                rmax = fmaxf(rmax, __shfl_xor_sync(0xffffffffu, rmax, 1));
                rmax = fmaxf(rmax, __shfl_xor_sync(0xffffffffu, rmax, 2));
                float mnew = fmaxf(m_i[h2], rmax);
                float alpha = __expf(m_i[h2] - mnew);
                float rsum = 0.0f;
#pragma unroll
                for (int ni = 0; ni < 8; ni++) {
                    float p0 = __expf(sacc[ni][2 * h2] - mnew);
                    float p1 = __expf(sacc[ni][2 * h2 + 1] - mnew);
                    sacc[ni][2 * h2] = p0;
                    sacc[ni][2 * h2 + 1] = p1;
                    rsum += p0 + p1;
                }
                rsum += __shfl_xor_sync(0xffffffffu, rsum, 1);
                rsum += __shfl_xor_sync(0xffffffffu, rsum, 2);
                l_i[h2] = l_i[h2] * alpha + rsum;
                m_i[h2] = mnew;
#pragma unroll
                for (int ni = 0; ni < 16; ni++) {
                    c[ni][2 * h2]     *= alpha;
                    c[ni][2 * h2 + 1] *= alpha;
                }
            }

#pragma unroll
            for (int ni = 0; ni < 8; ni++) {
                *(uint2*)&Pw[gid * 68 + ni * 8 + tig * 2] =
                    make_uint2(f2tf(sacc[ni][0]), f2tf(sacc[ni][1]));
                *(uint2*)&Pw[(gid + 8) * 68 + ni * 8 + tig * 2] =
                    make_uint2(f2tf(sacc[ni][2]), f2tf(sacc[ni][3]));
            }
        }

        asm volatile("cp.async.wait_group 1;");
        __syncthreads();

        if (active) {
#pragma unroll 2
            for (int k8 = 0; k8 < 8; k8++) {
                unsigned ap[4];
                ap[0] = Pw[gid * 68 + k8 * 8 + tig];
                ap[1] = Pw[(gid + 8) * 68 + k8 * 8 + tig];
                ap[2] = Pw[gid * 68 + k8 * 8 + tig + 4];
                ap[3] = Pw[(gid + 8) * 68 + k8 * 8 + tig + 4];
#pragma unroll
                for (int ni = 0; ni < 16; ni++) {
                    unsigned b0 = f2tf(Vs[(k8 * 8 + tig) * 136 + ni * 8 + gid]);
                    unsigned b1 = f2tf(Vs[(k8 * 8 + tig + 4) * 136 + ni * 8 + gid]);
                    mma_tf32(c[ni], ap, b0, b1);
                }
            }
        }
    }

    const float h0 = 0.5f / l_i[0];
    const float h1 = 0.5f / l_i[1];
    const int r0 = rbase + gid, r1 = r0 + 8;
#pragma unroll
    for (int ni = 0; ni < 16; ni++) {
        int col = h * DH + ni * 8 + tig * 2;
        float2 p0 = *(float2*)&g_attn[(size_t)r0 * HD + col];
        float2 p1 = *(float2*)&g_attn[(size_t)r1 * HD + col];
        *(float2*)&g_attn[(size_t)r0 * HD + col] =
            make_float2(c[ni][0] * h0 + p0.x, c[ni][1] * h0 + p0.y);
        *(float2*)&g_attn[(size_t)r1 * HD + col] =
            make_float2(c[ni][2] * h1 + p1.x, c[ni][3] * h1 + p1.y);
    }
}

// =============================================================================
// host launcher
// =============================================================================
extern "C" void kernel_launch(void* const* d_in, const int* in_sizes, int n_in,
                              void* d_out, int out_size)
{
    (void)in_sizes; (void)n_in; (void)out_size;
    const float* hs = (const float*)d_in[0];
    const float* Wq = (const float*)d_in[1];
    const float* Wk = (const float*)d_in[2];
    const float* Wv = (const float*)d_in[3];
    const float* Wo = (const float*)d_in[4];
    float* out = (float*)d_out;

    float* p_attn;
    cudaGetSymbolAddress((void**)&p_attn, g_attn);

    const int smem3 = (2 * 128 * 65 + 128 * 132 + 64 * 132 + 64 * 65) * 4;
    cudaFuncSetAttribute(proj_kernel,      cudaFuncAttributeMaxDynamicSharedMemorySize, GEMM_SMEM);
    cudaFuncSetAttribute(wo_kernel,        cudaFuncAttributeMaxDynamicSharedMemorySize, GEMM_SMEM);
    cudaFuncSetAttribute(gla_pass1_kernel, cudaFuncAttributeMaxDynamicSharedMemorySize, P1_SMEM);
    cudaFuncSetAttribute(gla_pass3_kernel, cudaFuncAttributeMaxDynamicSharedMemorySize, smem3);
    cudaFuncSetAttribute(attn_tc_kernel,   cudaFuncAttributeMaxDynamicSharedMemorySize, ATTN_SMEM);

    // 0. RoPE table
    rope_table_kernel<<<NTOK, 64>>>();
    // 1. q/k/v projections + fused softmax/rope/gate prep (cp.async GEMM)
    proj_kernel<<<dim3(24, 16), 128, GEMM_SMEM>>>(hs, Wq, Wk, Wv);
    // 2. GLA chunked
    gla_pass1_kernel<<<dim3(NCH, NKV, 2), 256, P1_SMEM>>>();
    gla_scan_kernel<<<dim3(NKV, DH), 128>>>();
    gla_pass3_kernel<<<dim3(NCH, NH), 512, smem3>>>();       // writes 0.5*gla
    // 3. causal flash attention (adds 0.5*y into g_attn)
    attn_tc_kernel<<<dim3(NTOK / 128, NH), 256, ATTN_SMEM>>>();
    // 4. out = g_attn @ Wo
    wo_kernel<<<dim3(16, 16), 128, GEMM_SMEM>>>(p_attn, Wo, out);
}

// round 9
// speedup vs baseline: 2.8092x; 1.1446x over previous
#include <cuda_runtime.h>
#include <math.h>

// Problem constants
#define NTOK 2048
#define HIDN 2048
#define NH   16
#define NKV  4
#define DH   128
#define HD   (NH*DH)     // 2048
#define KVD  (NKV*DH)    // 512
#define CH   64
#define NCH  (NTOK/CH)   // 32

// ---------------- scratch (static device globals; no allocation) -------------
__device__ float    g_sq  [NTOK*HD];
__device__ float    g_qs  [NTOK*HD];
__device__ float    g_sk  [NTOK*KVD];
__device__ float    g_ks  [NTOK*KVD];
__device__ float    g_gl  [NTOK*KVD];
__device__ float    g_v   [NTOK*KVD];
__device__ float    g_lam [NTOK*KVD];
__device__ float    g_kdl [NTOK*KVD];
__device__ float    g_dS  [NKV*NCH*DH*DH];
__device__ float    g_S   [NKV*NCH*DH*DH];
__device__ float    g_ltot[NKV*NCH*DH];
__device__ float    g_y   [NTOK*HD];      // 0.5 * attention branch
__device__ float    g_gla [NTOK*HD];      // 0.5 * GLA branch
__device__ unsigned g_cmb [NTOK*HD];      // tf32(y + gla) for the Wo GEMM
__device__ float2   g_rope[NTOK*64];
// pre-rounded tf32 operands
__device__ unsigned g_hsT [NTOK*HIDN];
__device__ unsigned g_WqT [HIDN*HD];
__device__ unsigned g_WkT [HIDN*KVD];
__device__ unsigned g_WvT [HIDN*KVD];
__device__ unsigned g_WoT [HD*HIDN];

// ---------------- tf32 mma helpers ------------------------------------------
__device__ __forceinline__ unsigned f2tf(float x) {
    unsigned r;
    asm("cvt.rna.tf32.f32 %0, %1;" : "=r"(r) : "f"(x));
    return r;
}

__device__ __forceinline__ uint4 cvt4(float4 v) {
    return make_uint4(f2tf(v.x), f2tf(v.y), f2tf(v.z), f2tf(v.w));
}

__device__ __forceinline__ void mma_tf32(float c[4], const unsigned a[4],
                                         unsigned b0, unsigned b1) {
    asm volatile(
        "mma.sync.aligned.m16n8k8.row.col.f32.tf32.tf32.f32 "
        "{%0,%1,%2,%3}, {%4,%5,%6,%7}, {%8,%9}, {%0,%1,%2,%3};"
        : "+f"(c[0]), "+f"(c[1]), "+f"(c[2]), "+f"(c[3])
        : "r"(a[0]), "r"(a[1]), "r"(a[2]), "r"(a[3]), "r"(b0), "r"(b1));
}

__device__ __forceinline__ void cp16(void* dst, const void* src) {
    unsigned d = (unsigned)__cvta_generic_to_shared(dst);
    asm volatile("cp.async.cg.shared.global [%0], [%1], 16;" :: "r"(d), "l"(src));
}

// =============================================================================
// fp32 -> tf32 pre-rounding (vectorized)
// =============================================================================
__global__ void __launch_bounds__(256) cvt_kernel(
    const float4* __restrict__ src, uint4* __restrict__ dst, int n4)
{
    int i = blockIdx.x * blockDim.x + threadIdx.x;
    if (i < n4) dst[i] = cvt4(src[i]);
}

// combine: cmb = tf32(y + gla)
__global__ void __launch_bounds__(256) combine_kernel()
{
    int i = blockIdx.x * blockDim.x + threadIdx.x;   // over NTOK*HD/4
    float4 a = ((const float4*)g_y)[i];
    float4 b = ((const float4*)g_gla)[i];
    ((uint4*)g_cmb)[i] = cvt4(make_float4(a.x + b.x, a.y + b.y, a.z + b.z, a.w + b.w));
}

// =============================================================================
// RoPE cos/sin table
// =============================================================================
__global__ void __launch_bounds__(64) rope_table_kernel()
{
    const int t = blockIdx.x, j = threadIdx.x;
    float inv_freq = (float)pow(10000.0, -(double)(2 * j) / 128.0);
    float fr = (float)t * inv_freq;
    double ang = (double)fr;
    g_rope[t * 64 + j] = make_float2((float)cos(ang), (float)sin(ang));
}

// =============================================================================
// TF32 GEMM v4: operands pre-rounded to tf32 (u32) -> NO cvt in the hot loop.
// 128x128 tile, 128 threads (4 warps, 2x2, 64x64 warp tiles), BK=32,
// cp.async double-buffered.
// =============================================================================
#define AS_STRIDE 36
#define BS_STRIDE 136
#define AS_BUF (128 * AS_STRIDE)
#define BS_BUF (32 * BS_STRIDE)
#define GEMM_SMEM ((2 * AS_BUF + 2 * BS_BUF) * 4)   // 71680 bytes

__device__ __forceinline__ void gemm_issue_slab(
    unsigned* As, unsigned* Bs,
    const unsigned* __restrict__ A, const unsigned* __restrict__ B,
    int N, int K, int bm, int bn, int k0)
{
    const int tid = threadIdx.x;
    {
        const unsigned* src = A + (size_t)(bm + tid) * K + k0;
        unsigned* dst = As + tid * AS_STRIDE;
#pragma unroll
        for (int q = 0; q < 8; q++) cp16(dst + q * 4, src + q * 4);
    }
    {
        const int r = tid >> 2, cpart = (tid & 3) * 4;
        const unsigned* src = B + (size_t)(k0 + r) * N + bn + cpart;
        unsigned* dst = Bs + r * BS_STRIDE + cpart;
#pragma unroll
        for (int q = 0; q < 8; q++) cp16(dst + q * 16, src + q * 16);
    }
}

__device__ __forceinline__ void gemm_tf32_acc(
    unsigned* __restrict__ sm,
    const unsigned* __restrict__ A, const unsigned* __restrict__ B,
    int N, int K, int bm, int bn, float acc[4][8][4])
{
    unsigned* As = sm;
    unsigned* Bs = sm + 2 * AS_BUF;

    const int tid  = threadIdx.x;
    const int warp = tid >> 5, lane = tid & 31;
    const int gid  = lane >> 2, tig = lane & 3;
    const int wm   = (warp & 1) * 64, wn = (warp >> 1) * 64;

#pragma unroll
    for (int mi = 0; mi < 4; mi++)
#pragma unroll
        for (int ni = 0; ni < 8; ni++)
#pragma unroll
            for (int v = 0; v < 4; v++) acc[mi][ni][v] = 0.0f;

    const int nIter = K >> 5;
    gemm_issue_slab(As, Bs, A, B, N, K, bm, bn, 0);
    asm volatile("cp.async.commit_group;");
    if (nIter > 1) {
        gemm_issue_slab(As + AS_BUF, Bs + BS_BUF, A, B, N, K, bm, bn, 32);
    }
    asm volatile("cp.async.commit_group;");

    for (int it = 0; it < nIter; it++) {
        if (it + 1 < nIter)
            asm volatile("cp.async.wait_group 1;");
        else
            asm volatile("cp.async.wait_group 0;");
        __syncthreads();

        const unsigned* as = As + (it & 1) * AS_BUF;
        const unsigned* bs = Bs + (it & 1) * BS_BUF;
#pragma unroll
        for (int k8 = 0; k8 < 4; k8++) {
            unsigned af[4][4];
#pragma unroll
            for (int mi = 0; mi < 4; mi++) {
                int r = wm + mi * 16 + gid;
                af[mi][0] = as[r * AS_STRIDE + k8 * 8 + tig];
                af[mi][1] = as[(r + 8) * AS_STRIDE + k8 * 8 + tig];
                af[mi][2] = as[r * AS_STRIDE + k8 * 8 + tig + 4];
                af[mi][3] = as[(r + 8) * AS_STRIDE + k8 * 8 + tig + 4];
            }
#pragma unroll
            for (int ni = 0; ni < 8; ni++) {
                unsigned b0 = bs[(k8 * 8 + tig) * BS_STRIDE + wn + ni * 8 + gid];
                unsigned b1 = bs[(k8 * 8 + tig + 4) * BS_STRIDE + wn + ni * 8 + gid];
#pragma unroll
                for (int mi = 0; mi < 4; mi++) mma_tf32(acc[mi][ni], af[mi], b0, b1);
            }
        }
        __syncthreads();

        if (it + 2 < nIter) {
            // slab (it+2) -> buffer ((it+2)&1) == (it&1), the one just consumed
            gemm_issue_slab(As + (it & 1) * AS_BUF, Bs + (it & 1) * BS_BUF,
                            A, B, N, K, bm, bn, (it + 2) << 5);
        }
        asm volatile("cp.async.commit_group;");
    }
}

__device__ __forceinline__ void gemm_store(
    float acc[4][8][4], float* __restrict__ C, int N, int bm, int bn)
{
    const int tid  = threadIdx.x;
    const int warp = tid >> 5, lane = tid & 31;
    const int gid  = lane >> 2, tig = lane & 3;
    const int wm   = (warp & 1) * 64, wn = (warp >> 1) * 64;
#pragma unroll
    for (int mi = 0; mi < 4; mi++) {
        int r0 = bm + wm + mi * 16 + gid;
#pragma unroll
        for (int ni = 0; ni < 8; ni++) {
            int col = bn + wn + ni * 8 + tig * 2;
            *(float2*)&C[(size_t)r0 * N + col]       = make_float2(acc[mi][ni][0], acc[mi][ni][1]);
            *(float2*)&C[(size_t)(r0 + 8) * N + col] = make_float2(acc[mi][ni][2], acc[mi][ni][3]);
        }
    }
}

// Fused prep epilogue: softmax -> outs, RoPE -> outr, optional logsigmoid/16.
__device__ __forceinline__ void prep_epilogue(
    float acc[4][8][4], unsigned* sm, int bm, int rowstride, int headoff,
    float* __restrict__ outs, float* __restrict__ outr, float* __restrict__ outg)
{
    float* St = (float*)sm;   // [128][132] staging
    const int tid  = threadIdx.x;
    const int warp = tid >> 5, lane = tid & 31;
    const int gid  = lane >> 2, tig = lane & 3;
    const int wm   = (warp & 1) * 64, wn = (warp >> 1) * 64;

#pragma unroll
    for (int mi = 0; mi < 4; mi++) {
        int r0 = wm + mi * 16 + gid;
#pragma unroll
        for (int ni = 0; ni < 8; ni++) {
            int col = wn + ni * 8 + tig * 2;
            *(float2*)&St[r0 * 132 + col]       = make_float2(acc[mi][ni][0], acc[mi][ni][1]);
            *(float2*)&St[(r0 + 8) * 132 + col] = make_float2(acc[mi][ni][2], acc[mi][ni][3]);
        }
    }
    __syncthreads();

    for (int r = warp; r < 128; r += 4) {
        const float* Sr = St + r * 132;
        float x0 = Sr[lane], x1 = Sr[lane + 32], x2 = Sr[lane + 64], x3 = Sr[lane + 96];

        float m = fmaxf(fmaxf(x0, x1), fmaxf(x2, x3));
#pragma unroll
        for (int o = 16; o; o >>= 1) m = fmaxf(m, __shfl_xor_sync(0xffffffffu, m, o));

        float e0 = expf(x0 - m), e1 = expf(x1 - m), e2 = expf(x2 - m), e3 = expf(x3 - m);
        float s = e0 + e1 + e2 + e3;
#pragma unroll
        for (int o = 16; o; o >>= 1) s += __shfl_xor_sync(0xffffffffu, s, o);

        const int t = bm + r;
        const size_t ob = (size_t)t * rowstride + headoff;
        outs[ob + lane]      = e0 / s;
        outs[ob + lane + 32] = e1 / s;
        outs[ob + lane + 64] = e2 / s;
        outs[ob + lane + 96] = e3 / s;

        float2 cs0 = g_rope[t * 64 + lane];
        float2 cs1 = g_rope[t * 64 + lane + 32];
        outr[ob + lane]      = x0 * cs0.x - x2 * cs0.y;
        outr[ob + lane + 64] = x2 * cs0.x + x0 * cs0.y;
        outr[ob + lane + 32] = x1 * cs1.x - x3 * cs1.y;
        outr[ob + lane + 96] = x3 * cs1.x + x1 * cs1.y;

        if (outg) {
            outg[ob + lane]      = (fminf(x0, 0.0f) - log1pf(expf(-fabsf(x0)))) * 0.0625f;
            outg[ob + lane + 32] = (fminf(x1, 0.0f) - log1pf(expf(-fabsf(x1)))) * 0.0625f;
            outg[ob + lane + 64] = (fminf(x2, 0.0f) - log1pf(expf(-fabsf(x2)))) * 0.0625f;
            outg[ob + lane + 96] = (fminf(x3, 0.0f) - log1pf(expf(-fabsf(x3)))) * 0.0625f;
        }
    }
}

// Merged q/k/v projections + fused prep (operands pre-rounded tf32).
__global__ void __launch_bounds__(128) proj_kernel()
{
    extern __shared__ unsigned smg[];
    const int bx = blockIdx.x, bm = blockIdx.y * 128;
    float acc[4][8][4];

    if (bx < 16) {
        gemm_tf32_acc(smg, g_hsT, g_WqT, HD, HIDN, bm, bx * 128, acc);
        prep_epilogue(acc, smg, bm, HD, bx * DH, g_qs, g_sq, nullptr);
    } else if (bx < 20) {
        const int kvh = bx - 16;
        gemm_tf32_acc(smg, g_hsT, g_WkT, KVD, HIDN, bm, kvh * 128, acc);
        prep_epilogue(acc, smg, bm, KVD, kvh * DH, g_ks, g_sk, g_gl);
    } else {
        gemm_tf32_acc(smg, g_hsT, g_WvT, KVD, HIDN, bm, (bx - 20) * 128, acc);
        gemm_store(acc, g_v, KVD, bm, (bx - 20) * 128);
    }
}

// Output projection: out = cmb @ Wo (both pre-rounded tf32)
__global__ void __launch_bounds__(128) wo_kernel(float* __restrict__ out)
{
    extern __shared__ unsigned smg[];
    float acc[4][8][4];
    gemm_tf32_acc(smg, g_cmb, g_WoT, HIDN, HD, blockIdx.y * 128, blockIdx.x * 128, acc);
    gemm_store(acc, out, HIDN, blockIdx.y * 128, blockIdx.x * 128);
}

// =============================================================================
// GLA pass 1: grid (NCH, NKV, 2) — z selects a 64-wide d-half.
// =============================================================================
#define P1_SMEM ((64 * 68 * 2 + 64 * 132 + 64) * 4)

__global__ void __launch_bounds__(256) gla_pass1_kernel()
{
    extern __shared__ float sm1[];
    float* GL   = sm1;                 // [64][68]
    float* KW   = GL + 64 * 68;        // [64][68]
    float* Vt   = KW + 64 * 68;        // [64][132]
    float* LEND = Vt + 64 * 132;       // [64]

    const int c = blockIdx.x, kvh = blockIdx.y, z = blockIdx.z;
    const int dbase = z * 64;
    const int tid = threadIdx.x;

    for (int i = tid; i < 64 * 64; i += 256) {
        int r = i >> 6, d = i & 63;
        GL[r * 68 + d] = g_gl[(c * CH + r) * KVD + kvh * DH + dbase + d];
    }
    for (int i = tid; i < 64 * 128; i += 256) {
        int r = i >> 7, d = i & 127;
        Vt[r * 132 + d] = g_v[(c * CH + r) * KVD + kvh * DH + d];
    }
    __syncthreads();

    if (tid < 64) {
        float cum = 0.0f;
#pragma unroll 4
        for (int t = 0; t < CH; t++) {
            cum += GL[t * 68 + tid];
            GL[t * 68 + tid] = expf(cum);
        }
        float le = GL[63 * 68 + tid];
        LEND[tid] = le;
        g_ltot[(kvh * NCH + c) * DH + dbase + tid] = le;
    }
    __syncthreads();

    for (int i = tid; i < 64 * 64; i += 256) {
        int r = i >> 6, d = i & 63;
        int gi = (c * CH + r) * KVD + kvh * DH + dbase + d;
        float lam = GL[r * 68 + d];
        float kdl = g_ks[gi] / lam;
        g_kdl[gi] = kdl;
        g_lam[gi] = lam;
        KW[r * 68 + d] = kdl * LEND[d];
    }
    __syncthreads();

    const int tx = tid & 15, ty = tid >> 4;
    float acc[4][8];
#pragma unroll
    for (int i = 0; i < 4; i++)
#pragma unroll
        for (int j = 0; j < 8; j++) acc[i][j] = 0.0f;

    for (int t = 0; t < CH; t++) {
        float a[4], b[8];
        *(float4*)&a[0] = *(const float4*)&KW[t * 68 + ty * 4];
        *(float4*)&b[0] = *(const float4*)&Vt[t * 132 + tx * 8];
        *(float4*)&b[4] = *(const float4*)&Vt[t * 132 + tx * 8 + 4];
#pragma unroll
        for (int i = 0; i < 4; i++)
#pragma unroll
            for (int j = 0; j < 8; j++) acc[i][j] += a[i] * b[j];
    }

    float* dS = g_dS + (size_t)(kvh * NCH + c) * DH * DH + (size_t)dbase * DH;
#pragma unroll
    for (int i = 0; i < 4; i++) {
        *(float4*)&dS[(ty * 4 + i) * DH + tx * 8]     = make_float4(acc[i][0], acc[i][1], acc[i][2], acc[i][3]);
        *(float4*)&dS[(ty * 4 + i) * DH + tx * 8 + 4] = make_float4(acc[i][4], acc[i][5], acc[i][6], acc[i][7]);
    }
}

// =============================================================================
// GLA pass 2: scan over chunks (separate src/dst, register prefetch).
// =============================================================================
__global__ void __launch_bounds__(128) gla_scan_kernel()
{
    const int kvh = blockIdx.x, d = blockIdx.y;
    const int dp = threadIdx.x;

    __shared__ float lt[NCH];
    if (dp < NCH) lt[dp] = g_ltot[(kvh * NCH + dp) * DH + d];
    __syncthreads();

    const size_t base = (size_t)(kvh * NCH) * DH * DH + (size_t)d * DH + dp;
    const float* __restrict__ src = g_dS + base;
    float* __restrict__ dst = g_S + base;
    const size_t step = (size_t)DH * DH;

    float s = 0.0f;
    float pre[4];
#pragma unroll
    for (int c = 0; c < 4; c++) pre[c] = src[c * step];
#pragma unroll
    for (int c = 0; c < NCH; c++) {
        float v = pre[c & 3];
        if (c + 4 < NCH) pre[c & 3] = src[(c + 4) * step];
        dst[c * step] = s;
        s = s * lt[c] + v;
    }
}

// =============================================================================
// GLA pass 3 (fp32 SIMT, 512 threads): writes 0.5*o_gla into g_gla.
// =============================================================================
__global__ void __launch_bounds__(512) gla_pass3_kernel()
{
    extern __shared__ float sm3[];
    float* QT = sm3;               // [128][65]
    float* KT = QT + 128 * 65;
    float* Ss = KT + 128 * 65;     // [128][132]
    float* Vs = Ss + 128 * 132;    // [64][132]
    float* AT = Vs + 64 * 132;     // [64][65]

    const int c = blockIdx.x, h = blockIdx.y;
    const int kvh = h >> 2;
    const int tid = threadIdx.x;

    for (int idx = tid; idx < CH * DH; idx += 512) {
        int r = idx >> 7, d = idx & 127;
        int kb = (c * CH + r) * KVD + kvh * DH + d;
        float lam = g_lam[kb];
        QT[d * 65 + r] = g_qs[(c * CH + r) * HD + h * DH + d] * lam;
        KT[d * 65 + r] = g_kdl[kb];
        Vs[r * 132 + d] = g_v[kb];
    }
    const float* Sg = g_S + (size_t)(kvh * NCH + c) * DH * DH;
    for (int idx = tid; idx < DH * DH; idx += 512) {
        int r = idx >> 7, d = idx & 127;
        Ss[r * 132 + d] = Sg[r * DH + d];
    }
    __syncthreads();

    const int tx = tid & 15, ty = tid >> 4;   // ty 0..31

    float O[2][8];
#pragma unroll
    for (int i = 0; i < 2; i++)
#pragma unroll
        for (int j = 0; j < 8; j++) O[i][j] = 0.0f;

    for (int dd = 0; dd < DH; dd++) {
        float a[2], b[8];
#pragma unroll
        for (int i = 0; i < 2; i++) a[i] = QT[dd * 65 + ty * 2 + i];
        *(float4*)&b[0] = *(const float4*)&Ss[dd * 132 + tx * 8];
        *(float4*)&b[4] = *(const float4*)&Ss[dd * 132 + tx * 8 + 4];
#pragma unroll
        for (int i = 0; i < 2; i++)
#pragma unroll
            for (int j = 0; j < 8; j++) O[i][j] += a[i] * b[j];
    }

    float Aacc[2][4];
#pragma unroll
    for (int i = 0; i < 2; i++)
#pragma unroll
        for (int j = 0; j < 4; j++) Aacc[i][j] = 0.0f;

    for (int dd = 0; dd < DH; dd++) {
        float a[2], b[4];
#pragma unroll
        for (int i = 0; i < 2; i++) a[i] = QT[dd * 65 + ty * 2 + i];
#pragma unroll
        for (int j = 0; j < 4; j++) b[j] = KT[dd * 65 + tx * 4 + j];
#pragma unroll
        for (int i = 0; i < 2; i++)
#pragma unroll
            for (int j = 0; j < 4; j++) Aacc[i][j] += a[i] * b[j];
    }
#pragma unroll
    for (int i = 0; i < 2; i++)
#pragma unroll
        for (int j = 0; j < 4; j++) {
            int t = ty * 2 + i, s = tx * 4 + j;
            AT[s * 65 + t] = (s <= t) ? Aacc[i][j] : 0.0f;
        }
    __syncthreads();

    for (int s = 0; s < CH; s++) {
        float a[2], b[8];
#pragma unroll
        for (int i = 0; i < 2; i++) a[i] = AT[s * 65 + ty * 2 + i];
        *(float4*)&b[0] = *(const float4*)&Vs[s * 132 + tx * 8];
        *(float4*)&b[4] = *(const float4*)&Vs[s * 132 + tx * 8 + 4];
#pragma unroll
        for (int i = 0; i < 2; i++)
#pragma unroll
            for (int j = 0; j < 8; j++) O[i][j] += a[i] * b[j];
    }

#pragma unroll
    for (int i = 0; i < 2; i++) {
        int t = c * CH + ty * 2 + i;
        float4 o0 = make_float4(0.5f*O[i][0], 0.5f*O[i][1], 0.5f*O[i][2], 0.5f*O[i][3]);
        float4 o1 = make_float4(0.5f*O[i][4], 0.5f*O[i][5], 0.5f*O[i][6], 0.5f*O[i][7]);
        *(float4*)&g_gla[t * HD + h * DH + tx * 8]     = o0;
        *(float4*)&g_gla[t * HD + h * DH + tx * 8 + 4] = o1;
    }
}

// =============================================================================
// Causal flash attention: writes 0.5*y into g_y (plain store — no RMW, so it
// can run concurrently with the GLA chain).
// =============================================================================
#define ATTN_SMEM ((128*132 + 2*64*132 + 64*136 + 8*16*68) * 4)   // 204800 B

__global__ void __launch_bounds__(256) attn_tc_kernel()
{
    extern __shared__ char smraw[];
    unsigned* Qs = (unsigned*)smraw;                                 // [128][132] tf32
    float*    Ks = (float*)(smraw + 128 * 132 * 4);                  // [2][64][132]
    float*    Vs = (float*)(smraw + (128 * 132 + 2 * 64 * 132) * 4); // [64][136]
    unsigned* Pb = (unsigned*)(smraw + (128 * 132 + 2 * 64 * 132 + 64 * 136) * 4);

    const int qt = gridDim.x - 1 - blockIdx.x;
    const int h = blockIdx.y;
    const int kvh = h >> 2;
    const int tid = threadIdx.x;
    const int warp = tid >> 5, lane = tid & 31;
    const int gid = lane >> 2, tig = lane & 3;
    unsigned* Pw = Pb + warp * 16 * 68;
    const float scale = 0.08838834764831845f;
    const int ktmax = 2 * qt + 1;

    {
#pragma unroll
        for (int i = 0; i < 8; i++) {
            int idx = tid + i * 256;
            int r = idx >> 5, c4 = (idx & 31) * 4;
            cp16(&Ks[r * 132 + c4], &g_sk[(size_t)r * KVD + kvh * DH + c4]);
        }
        asm volatile("cp.async.commit_group;");
    }

    for (int i = tid; i < 128 * 32; i += 256) {
        int r = i >> 5, c4 = (i & 31) * 4;
        float4 v = *(const float4*)&g_sq[(size_t)(qt * 128 + r) * HD + h * DH + c4];
        *(uint4*)&Qs[r * 132 + c4] = make_uint4(f2tf(v.x), f2tf(v.y), f2tf(v.z), f2tf(v.w));
    }

    const int rbase = qt * 128 + warp * 16;
    float m_i[2] = {-1e30f, -1e30f};
    float l_i[2] = {0.0f, 0.0f};
    float c[16][4];
#pragma unroll
    for (int ni = 0; ni < 16; ni++)
#pragma unroll
        for (int v = 0; v < 4; v++) c[ni][v] = 0.0f;

    for (int kt = 0; kt <= ktmax; kt++) {
        __syncthreads();

#pragma unroll
        for (int i = 0; i < 8; i++) {
            int idx = tid + i * 256;
            int r = idx >> 5, c4 = (idx & 31) * 4;
            cp16(&Vs[r * 136 + c4], &g_v[(size_t)(kt * 64 + r) * KVD + kvh * DH + c4]);
        }
        asm volatile("cp.async.commit_group;");

        {
            const int ktn = (kt < ktmax) ? kt + 1 : kt;
            float* KB = Ks + ((kt + 1) & 1) * 64 * 132;
#pragma unroll
            for (int i = 0; i < 8; i++) {
                int idx = tid + i * 256;
                int r = idx >> 5, c4 = (idx & 31) * 4;
                cp16(&KB[r * 132 + c4], &g_sk[(size_t)(ktn * 64 + r) * KVD + kvh * DH + c4]);
            }
            asm volatile("cp.async.commit_group;");
        }

        asm volatile("cp.async.wait_group 2;");
        __syncthreads();

        const float* KB = Ks + (kt & 1) * 64 * 132;
        const int smin = kt * 64;
        const bool active = (smin <= rbase + 15);

        if (active) {
            float sacc[8][4];
#pragma unroll
            for (int ni = 0; ni < 8; ni++)
#pragma unroll
                for (int v = 0; v < 4; v++) sacc[ni][v] = 0.0f;

#pragma unroll 4
            for (int k8 = 0; k8 < 16; k8++) {
                unsigned aq[4];
                int qr = warp * 16 + gid;
                aq[0] = Qs[qr * 132 + k8 * 8 + tig];
                aq[1] = Qs[(qr + 8) * 132 + k8 * 8 + tig];
                aq[2] = Qs[qr * 132 + k8 * 8 + tig + 4];
                aq[3] = Qs[(qr + 8) * 132 + k8 * 8 + tig + 4];
#pragma unroll
                for (int ni = 0; ni < 8; ni++) {
                    unsigned b0 = f2tf(KB[(ni * 8 + gid) * 132 + k8 * 8 + tig]);
                    unsigned b1 = f2tf(KB[(ni * 8 + gid) * 132 + k8 * 8 + tig + 4]);
                    mma_tf32(sacc[ni], aq, b0, b1);
                }
            }

            const bool partial = (smin + 63 > rbase);
#pragma unroll
            for (int ni = 0; ni < 8; ni++)
#pragma unroll
                for (int v = 0; v < 4; v++) {
                    float sv = sacc[ni][v] * scale;
                    if (partial) {
                        int row = rbase + gid + (v >> 1) * 8;
                        int col = smin + ni * 8 + tig * 2 + (v & 1);
                        if (col > row) sv = -1e30f;
                    }
                    sacc[ni][v] = sv;
                }

#pragma unroll
            for (int h2 = 0; h2 < 2; h2++) {
                float rmax = -1e30f;
#pragma unroll
                for (int ni = 0; ni < 8; ni++)
                    rmax = fmaxf(rmax, fmaxf(sacc[ni][2 * h2], sacc[ni][2 * h2 + 1]));
                rmax = fmaxf(rmax, __shfl_xor_sync(0xffffffffu, rmax, 1));
                rmax = fmaxf(rmax, __shfl_xor_sync(0xffffffffu, rmax, 2));
                float mnew = fmaxf(m_i[h2], rmax);
                float alpha = __expf(m_i[h2] - mnew);
                float rsum = 0.0f;
#pragma unroll
                for (int ni = 0; ni < 8; ni++) {
                    float p0 = __expf(sacc[ni][2 * h2] - mnew);
                    float p1 = __expf(sacc[ni][2 * h2 + 1] - mnew);
                    sacc[ni][2 * h2] = p0;
                    sacc[ni][2 * h2 + 1] = p1;
                    rsum += p0 + p1;
                }
                rsum += __shfl_xor_sync(0xffffffffu, rsum, 1);
                rsum += __shfl_xor_sync(0xffffffffu, rsum, 2);
                l_i[h2] = l_i[h2] * alpha + rsum;
                m_i[h2] = mnew;
#pragma unroll
                for (int ni = 0; ni < 16; ni++) {
                    c[ni][2 * h2]     *= alpha;
                    c[ni][2 * h2 + 1] *= alpha;
                }
            }

#pragma unroll
            for (int ni = 0; ni < 8; ni++) {
                *(uint2*)&Pw[gid * 68 + ni * 8 + tig * 2] =
                    make_uint2(f2tf(sacc[ni][0]), f2tf(sacc[ni][1]));
                *(uint2*)&Pw[(gid + 8) * 68 + ni * 8 + tig * 2] =
                    make_uint2(f2tf(sacc[ni][2]), f2tf(sacc[ni][3]));
            }
        }

        asm volatile("cp.async.wait_group 1;");
        __syncthreads();

        if (active) {
#pragma unroll 2
            for (int k8 = 0; k8 < 8; k8++) {
                unsigned ap[4];
                ap[0] = Pw[gid * 68 + k8 * 8 + tig];
                ap[1] = Pw[(gid + 8) * 68 + k8 * 8 + tig];
                ap[2] = Pw[gid * 68 + k8 * 8 + tig + 4];
                ap[3] = Pw[(gid + 8) * 68 + k8 * 8 + tig + 4];
#pragma unroll
                for (int ni = 0; ni < 16; ni++) {
                    unsigned b0 = f2tf(Vs[(k8 * 8 + tig) * 136 + ni * 8 + gid]);
                    unsigned b1 = f2tf(Vs[(k8 * 8 + tig + 4) * 136 + ni * 8 + gid]);
                    mma_tf32(c[ni], ap, b0, b1);
                }
            }
        }
    }

    const float h0 = 0.5f / l_i[0];
    const float h1 = 0.5f / l_i[1];
    const int r0 = rbase + gid, r1 = r0 + 8;
#pragma unroll
    for (int ni = 0; ni < 16; ni++) {
        int col = h * DH + ni * 8 + tig * 2;
        *(float2*)&g_y[(size_t)r0 * HD + col] = make_float2(c[ni][0] * h0, c[ni][1] * h0);
        *(float2*)&g_y[(size_t)r1 * HD + col] = make_float2(c[ni][2] * h1, c[ni][3] * h1);
    }
}

// =============================================================================
// host launcher — fork/join: GLA chain (stream A) || attention (stream B)
// =============================================================================
extern "C" void kernel_launch(void* const* d_in, const int* in_sizes, int n_in,
                              void* d_out, int out_size)
{
    (void)in_sizes; (void)n_in; (void)out_size;
    const float* hs = (const float*)d_in[0];
    const float* Wq = (const float*)d_in[1];
    const float* Wk = (const float*)d_in[2];
    const float* Wv = (const float*)d_in[3];
    const float* Wo = (const float*)d_in[4];
    float* out = (float*)d_out;

    unsigned *p_hsT, *p_WqT, *p_WkT, *p_WvT, *p_WoT;
    cudaGetSymbolAddress((void**)&p_hsT, g_hsT);
    cudaGetSymbolAddress((void**)&p_WqT, g_WqT);
    cudaGetSymbolAddress((void**)&p_WkT, g_WkT);
    cudaGetSymbolAddress((void**)&p_WvT, g_WvT);
    cudaGetSymbolAddress((void**)&p_WoT, g_WoT);

    // one-time stream/event creation (first call is the uncaptured correctness
    // run; during capture these handles are only USED, never created)
    static cudaStream_t sA = nullptr, sB = nullptr;
    static cudaEvent_t ev0, evP, evA, evB;
    if (sA == nullptr) {
        cudaStreamCreateWithFlags(&sA, cudaStreamNonBlocking);
        cudaStreamCreateWithFlags(&sB, cudaStreamNonBlocking);
        cudaEventCreateWithFlags(&ev0, cudaEventDisableTiming);
        cudaEventCreateWithFlags(&evP, cudaEventDisableTiming);
        cudaEventCreateWithFlags(&evA, cudaEventDisableTiming);
        cudaEventCreateWithFlags(&evB, cudaEventDisableTiming);
    }

    const int smem3 = (2 * 128 * 65 + 128 * 132 + 64 * 132 + 64 * 65) * 4;
    cudaFuncSetAttribute(proj_kernel,      cudaFuncAttributeMaxDynamicSharedMemorySize, GEMM_SMEM);
    cudaFuncSetAttribute(wo_kernel,        cudaFuncAttributeMaxDynamicSharedMemorySize, GEMM_SMEM);
    cudaFuncSetAttribute(gla_pass1_kernel, cudaFuncAttributeMaxDynamicSharedMemorySize, P1_SMEM);
    cudaFuncSetAttribute(gla_pass3_kernel, cudaFuncAttributeMaxDynamicSharedMemorySize, smem3);
    cudaFuncSetAttribute(attn_tc_kernel,   cudaFuncAttributeMaxDynamicSharedMemorySize, ATTN_SMEM);

    // --- fork Wo conversion onto stream A early (only wo needs it) ---
    cudaEventRecord(ev0, 0);
    cudaStreamWaitEvent(sA, ev0, 0);
    cvt_kernel<<<4096, 256, 0, sA>>>((const float4*)Wo, (uint4*)p_WoT, HD * HIDN / 4);

    // --- main stream: rope table + operand pre-rounding + projections ---
    rope_table_kernel<<<NTOK, 64>>>();
    cvt_kernel<<<4096, 256>>>((const float4*)hs, (uint4*)p_hsT, NTOK * HIDN / 4);
    cvt_kernel<<<4096, 256>>>((const float4*)Wq, (uint4*)p_WqT, HIDN * HD / 4);
    cvt_kernel<<<1024, 256>>>((const float4*)Wk, (uint4*)p_WkT, HIDN * KVD / 4);
    cvt_kernel<<<1024, 256>>>((const float4*)Wv, (uint4*)p_WvT, HIDN * KVD / 4);
    proj_kernel<<<dim3(24, 16), 128, GEMM_SMEM>>>();
    cudaEventRecord(evP, 0);

    // --- stream A: GLA chain ---
    cudaStreamWaitEvent(sA, evP, 0);
    gla_pass1_kernel<<<dim3(NCH, NKV, 2), 256, P1_SMEM, sA>>>();
    gla_scan_kernel<<<dim3(NKV, DH), 128, 0, sA>>>();
    gla_pass3_kernel<<<dim3(NCH, NH), 512, smem3, sA>>>();
    cudaEventRecord(evA, sA);

    // --- stream B: causal flash attention (concurrent with GLA chain) ---
    cudaStreamWaitEvent(sB, evP, 0);
    attn_tc_kernel<<<dim3(NTOK / 128, NH), 256, ATTN_SMEM, sB>>>();
    cudaEventRecord(evB, sB);

    // --- join, combine, output projection ---
    cudaStreamWaitEvent(0, evA, 0);
    cudaStreamWaitEvent(0, evB, 0);
    combine_kernel<<<NTOK * HD / 4 / 256, 256>>>();
    wo_kernel<<<dim3(16, 16), 128, GEMM_SMEM>>>(out);
}

// round 10
// speedup vs baseline: 2.8669x; 1.0206x over previous
#include <cuda_runtime.h>
#include <math.h>

// Problem constants
#define NTOK 2048
#define HIDN 2048
#define NH   16
#define NKV  4
#define DH   128
#define HD   (NH*DH)     // 2048
#define KVD  (NKV*DH)    // 512
#define CH   64
#define NCH  (NTOK/CH)   // 32

// ---------------- scratch (static device globals; no allocation) -------------
__device__ unsigned g_sqT [NTOK*HD];      // roped q, tf32 (attn only)
__device__ float    g_qs  [NTOK*HD];      // softmax q (GLA)
__device__ unsigned g_skT [NTOK*KVD];     // roped k, tf32 (attn only)
__device__ float    g_ks  [NTOK*KVD];     // softmax k (GLA)
__device__ float    g_gl  [NTOK*KVD];
__device__ float    g_v   [NTOK*KVD];     // fp32 v (GLA)
__device__ unsigned g_vT  [NTOK*KVD];     // tf32 v (attn)
__device__ float    g_lam [NTOK*KVD];
__device__ float    g_kdl [NTOK*KVD];
__device__ float    g_dS  [NKV*NCH*DH*DH];
__device__ float    g_S   [NKV*NCH*DH*DH];
__device__ float    g_ltot[NKV*NCH*DH];
__device__ float    g_y   [NTOK*HD];      // 0.5 * attention branch
__device__ float    g_gla [NTOK*HD];      // 0.5 * GLA branch
__device__ unsigned g_cmb [NTOK*HD];      // tf32(y + gla) for the Wo GEMM
__device__ float2   g_rope[NTOK*64];
// pre-rounded tf32 GEMM operands
__device__ unsigned g_hsT [NTOK*HIDN];
__device__ unsigned g_WqT [HIDN*HD];
__device__ unsigned g_WkT [HIDN*KVD];
__device__ unsigned g_WvT [HIDN*KVD];
__device__ unsigned g_WoT [HD*HIDN];

// ---------------- tf32 mma helpers ------------------------------------------
__device__ __forceinline__ unsigned f2tf(float x) {
    unsigned r;
    asm("cvt.rna.tf32.f32 %0, %1;" : "=r"(r) : "f"(x));
    return r;
}

__device__ __forceinline__ uint4 cvt4(float4 v) {
    return make_uint4(f2tf(v.x), f2tf(v.y), f2tf(v.z), f2tf(v.w));
}

__device__ __forceinline__ void mma_tf32(float c[4], const unsigned a[4],
                                         unsigned b0, unsigned b1) {
    asm volatile(
        "mma.sync.aligned.m16n8k8.row.col.f32.tf32.tf32.f32 "
        "{%0,%1,%2,%3}, {%4,%5,%6,%7}, {%8,%9}, {%0,%1,%2,%3};"
        : "+f"(c[0]), "+f"(c[1]), "+f"(c[2]), "+f"(c[3])
        : "r"(a[0]), "r"(a[1]), "r"(a[2]), "r"(a[3]), "r"(b0), "r"(b1));
}

__device__ __forceinline__ void cp16(void* dst, const void* src) {
    unsigned d = (unsigned)__cvta_generic_to_shared(dst);
    asm volatile("cp.async.cg.shared.global [%0], [%1], 16;" :: "r"(d), "l"(src));
}

// =============================================================================
// fp32 -> tf32 pre-rounding. cvt_all handles hs+Wq+Wk+Wv in ONE launch.
// =============================================================================
#define N4_HS (NTOK*HIDN/4)       // 1M
#define N4_WQ (HIDN*HD/4)         // 1M
#define N4_WK (HIDN*KVD/4)        // 256K

__global__ void __launch_bounds__(256) cvt_all_kernel(
    const float4* __restrict__ hs, const float4* __restrict__ Wq,
    const float4* __restrict__ Wk, const float4* __restrict__ Wv)
{
    int i = blockIdx.x * blockDim.x + threadIdx.x;
    if (i < N4_HS) {
        ((uint4*)g_hsT)[i] = cvt4(hs[i]);
    } else if (i < N4_HS + N4_WQ) {
        int j = i - N4_HS;
        ((uint4*)g_WqT)[j] = cvt4(Wq[j]);
    } else if (i < N4_HS + N4_WQ + N4_WK) {
        int j = i - N4_HS - N4_WQ;
        ((uint4*)g_WkT)[j] = cvt4(Wk[j]);
    } else {
        int j = i - N4_HS - N4_WQ - N4_WK;
        ((uint4*)g_WvT)[j] = cvt4(Wv[j]);
    }
}

__global__ void __launch_bounds__(256) cvt_kernel(
    const float4* __restrict__ src, uint4* __restrict__ dst, int n4)
{
    int i = blockIdx.x * blockDim.x + threadIdx.x;
    if (i < n4) dst[i] = cvt4(src[i]);
}

// combine: cmb = tf32(y + gla)
__global__ void __launch_bounds__(256) combine_kernel()
{
    int i = blockIdx.x * blockDim.x + threadIdx.x;   // over NTOK*HD/4
    float4 a = ((const float4*)g_y)[i];
    float4 b = ((const float4*)g_gla)[i];
    ((uint4*)g_cmb)[i] = cvt4(make_float4(a.x + b.x, a.y + b.y, a.z + b.z, a.w + b.w));
}

// =============================================================================
// RoPE cos/sin table
// =============================================================================
__global__ void __launch_bounds__(64) rope_table_kernel()
{
    const int t = blockIdx.x, j = threadIdx.x;
    float inv_freq = (float)pow(10000.0, -(double)(2 * j) / 128.0);
    float fr = (float)t * inv_freq;
    double ang = (double)fr;
    g_rope[t * 64 + j] = make_float2((float)cos(ang), (float)sin(ang));
}

// =============================================================================
// TF32 GEMM v4: operands pre-rounded tf32, cp.async double-buffered.
// 128x128 tile, 128 threads (4 warps, 2x2, 64x64 warp tiles), BK=32.
// =============================================================================
#define AS_STRIDE 36
#define BS_STRIDE 136
#define AS_BUF (128 * AS_STRIDE)
#define BS_BUF (32 * BS_STRIDE)
#define GEMM_SMEM ((2 * AS_BUF + 2 * BS_BUF) * 4)   // 71680 bytes

__device__ __forceinline__ void gemm_issue_slab(
    unsigned* As, unsigned* Bs,
    const unsigned* __restrict__ A, const unsigned* __restrict__ B,
    int N, int K, int bm, int bn, int k0)
{
    const int tid = threadIdx.x;
    {
        const unsigned* src = A + (size_t)(bm + tid) * K + k0;
        unsigned* dst = As + tid * AS_STRIDE;
#pragma unroll
        for (int q = 0; q < 8; q++) cp16(dst + q * 4, src + q * 4);
    }
    {
        const int r = tid >> 2, cpart = (tid & 3) * 4;
        const unsigned* src = B + (size_t)(k0 + r) * N + bn + cpart;
        unsigned* dst = Bs + r * BS_STRIDE + cpart;
#pragma unroll
        for (int q = 0; q < 8; q++) cp16(dst + q * 16, src + q * 16);
    }
}

__device__ __forceinline__ void gemm_tf32_acc(
    unsigned* __restrict__ sm,
    const unsigned* __restrict__ A, const unsigned* __restrict__ B,
    int N, int K, int bm, int bn, float acc[4][8][4])
{
    unsigned* As = sm;
    unsigned* Bs = sm + 2 * AS_BUF;

    const int tid  = threadIdx.x;
    const int warp = tid >> 5, lane = tid & 31;
    const int gid  = lane >> 2, tig = lane & 3;
    const int wm   = (warp & 1) * 64, wn = (warp >> 1) * 64;

#pragma unroll
    for (int mi = 0; mi < 4; mi++)
#pragma unroll
        for (int ni = 0; ni < 8; ni++)
#pragma unroll
            for (int v = 0; v < 4; v++) acc[mi][ni][v] = 0.0f;

    const int nIter = K >> 5;
    gemm_issue_slab(As, Bs, A, B, N, K, bm, bn, 0);
    asm volatile("cp.async.commit_group;");
    if (nIter > 1) {
        gemm_issue_slab(As + AS_BUF, Bs + BS_BUF, A, B, N, K, bm, bn, 32);
    }
    asm volatile("cp.async.commit_group;");

    for (int it = 0; it < nIter; it++) {
        if (it + 1 < nIter)
            asm volatile("cp.async.wait_group 1;");
        else
            asm volatile("cp.async.wait_group 0;");
        __syncthreads();

        const unsigned* as = As + (it & 1) * AS_BUF;
        const unsigned* bs = Bs + (it & 1) * BS_BUF;
#pragma unroll
        for (int k8 = 0; k8 < 4; k8++) {
            unsigned af[4][4];
#pragma unroll
            for (int mi = 0; mi < 4; mi++) {
                int r = wm + mi * 16 + gid;
                af[mi][0] = as[r * AS_STRIDE + k8 * 8 + tig];
                af[mi][1] = as[(r + 8) * AS_STRIDE + k8 * 8 + tig];
                af[mi][2] = as[r * AS_STRIDE + k8 * 8 + tig + 4];
                af[mi][3] = as[(r + 8) * AS_STRIDE + k8 * 8 + tig + 4];
            }
#pragma unroll
            for (int ni = 0; ni < 8; ni++) {
                unsigned b0 = bs[(k8 * 8 + tig) * BS_STRIDE + wn + ni * 8 + gid];
                unsigned b1 = bs[(k8 * 8 + tig + 4) * BS_STRIDE + wn + ni * 8 + gid];
#pragma unroll
                for (int mi = 0; mi < 4; mi++) mma_tf32(acc[mi][ni], af[mi], b0, b1);
            }
        }
        __syncthreads();

        if (it + 2 < nIter) {
            gemm_issue_slab(As + (it & 1) * AS_BUF, Bs + (it & 1) * BS_BUF,
                            A, B, N, K, bm, bn, (it + 2) << 5);
        }
        asm volatile("cp.async.commit_group;");
    }
}

__device__ __forceinline__ void gemm_store(
    float acc[4][8][4], float* __restrict__ C, int N, int bm, int bn)
{
    const int tid  = threadIdx.x;
    const int warp = tid >> 5, lane = tid & 31;
    const int gid  = lane >> 2, tig = lane & 3;
    const int wm   = (warp & 1) * 64, wn = (warp >> 1) * 64;
#pragma unroll
    for (int mi = 0; mi < 4; mi++) {
        int r0 = bm + wm + mi * 16 + gid;
#pragma unroll
        for (int ni = 0; ni < 8; ni++) {
            int col = bn + wn + ni * 8 + tig * 2;
            *(float2*)&C[(size_t)r0 * N + col]       = make_float2(acc[mi][ni][0], acc[mi][ni][1]);
            *(float2*)&C[(size_t)(r0 + 8) * N + col] = make_float2(acc[mi][ni][2], acc[mi][ni][3]);
        }
    }
}

// V store: fp32 for GLA + tf32 shadow for attention.
__device__ __forceinline__ void gemm_store_v(
    float acc[4][8][4], int bm, int bn)
{
    const int tid  = threadIdx.x;
    const int warp = tid >> 5, lane = tid & 31;
    const int gid  = lane >> 2, tig = lane & 3;
    const int wm   = (warp & 1) * 64, wn = (warp >> 1) * 64;
#pragma unroll
    for (int mi = 0; mi < 4; mi++) {
        int r0 = bm + wm + mi * 16 + gid;
#pragma unroll
        for (int ni = 0; ni < 8; ni++) {
            int col = bn + wn + ni * 8 + tig * 2;
            float2 v0 = make_float2(acc[mi][ni][0], acc[mi][ni][1]);
            float2 v1 = make_float2(acc[mi][ni][2], acc[mi][ni][3]);
            *(float2*)&g_v[(size_t)r0 * KVD + col]       = v0;
            *(float2*)&g_v[(size_t)(r0 + 8) * KVD + col] = v1;
            *(uint2*)&g_vT[(size_t)r0 * KVD + col]       = make_uint2(f2tf(v0.x), f2tf(v0.y));
            *(uint2*)&g_vT[(size_t)(r0 + 8) * KVD + col] = make_uint2(f2tf(v1.x), f2tf(v1.y));
        }
    }
}

// Fused prep epilogue: softmax -> outs (fp32), RoPE -> outr (TF32 bits —
// identical values attention previously produced by cvt'ing the fp32 store),
// optional logsigmoid/16 -> outg.
__device__ __forceinline__ void prep_epilogue(
    float acc[4][8][4], unsigned* sm, int bm, int rowstride, int headoff,
    float* __restrict__ outs, unsigned* __restrict__ outr, float* __restrict__ outg)
{
    float* St = (float*)sm;   // [128][132] staging
    const int tid  = threadIdx.x;
    const int warp = tid >> 5, lane = tid & 31;
    const int gid  = lane >> 2, tig = lane & 3;
    const int wm   = (warp & 1) * 64, wn = (warp >> 1) * 64;

#pragma unroll
    for (int mi = 0; mi < 4; mi++) {
        int r0 = wm + mi * 16 + gid;
#pragma unroll
        for (int ni = 0; ni < 8; ni++) {
            int col = wn + ni * 8 + tig * 2;
            *(float2*)&St[r0 * 132 + col]       = make_float2(acc[mi][ni][0], acc[mi][ni][1]);
            *(float2*)&St[(r0 + 8) * 132 + col] = make_float2(acc[mi][ni][2], acc[mi][ni][3]);
        }
    }
    __syncthreads();

    for (int r = warp; r < 128; r += 4) {
        const float* Sr = St + r * 132;
        float x0 = Sr[lane], x1 = Sr[lane + 32], x2 = Sr[lane + 64], x3 = Sr[lane + 96];

        float m = fmaxf(fmaxf(x0, x1), fmaxf(x2, x3));
#pragma unroll
        for (int o = 16; o; o >>= 1) m = fmaxf(m, __shfl_xor_sync(0xffffffffu, m, o));

        float e0 = expf(x0 - m), e1 = expf(x1 - m), e2 = expf(x2 - m), e3 = expf(x3 - m);
        float s = e0 + e1 + e2 + e3;
#pragma unroll
        for (int o = 16; o; o >>= 1) s += __shfl_xor_sync(0xffffffffu, s, o);

        const int t = bm + r;
        const size_t ob = (size_t)t * rowstride + headoff;
        outs[ob + lane]      = e0 / s;
        outs[ob + lane + 32] = e1 / s;
        outs[ob + lane + 64] = e2 / s;
        outs[ob + lane + 96] = e3 / s;

        float2 cs0 = g_rope[t * 64 + lane];
        float2 cs1 = g_rope[t * 64 + lane + 32];
        outr[ob + lane]      = f2tf(x0 * cs0.x - x2 * cs0.y);
        outr[ob + lane + 64] = f2tf(x2 * cs0.x + x0 * cs0.y);
        outr[ob + lane + 32] = f2tf(x1 * cs1.x - x3 * cs1.y);
        outr[ob + lane + 96] = f2tf(x3 * cs1.x + x1 * cs1.y);

        if (outg) {
            outg[ob + lane]      = (fminf(x0, 0.0f) - log1pf(expf(-fabsf(x0)))) * 0.0625f;
            outg[ob + lane + 32] = (fminf(x1, 0.0f) - log1pf(expf(-fabsf(x1)))) * 0.0625f;
            outg[ob + lane + 64] = (fminf(x2, 0.0f) - log1pf(expf(-fabsf(x2)))) * 0.0625f;
            outg[ob + lane + 96] = (fminf(x3, 0.0f) - log1pf(expf(-fabsf(x3)))) * 0.0625f;
        }
    }
}

// Merged q/k/v projections + fused prep.
__global__ void __launch_bounds__(128) proj_kernel()
{
    extern __shared__ unsigned smg[];
    const int bx = blockIdx.x, bm = blockIdx.y * 128;
    float acc[4][8][4];

    if (bx < 16) {
        gemm_tf32_acc(smg, g_hsT, g_WqT, HD, HIDN, bm, bx * 128, acc);
        prep_epilogue(acc, smg, bm, HD, bx * DH, g_qs, g_sqT, nullptr);
    } else if (bx < 20) {
        const int kvh = bx - 16;
        gemm_tf32_acc(smg, g_hsT, g_WkT, KVD, HIDN, bm, kvh * 128, acc);
        prep_epilogue(acc, smg, bm, KVD, kvh * DH, g_ks, g_skT, g_gl);
    } else {
        gemm_tf32_acc(smg, g_hsT, g_WvT, KVD, HIDN, bm, (bx - 20) * 128, acc);
        gemm_store_v(acc, bm, (bx - 20) * 128);
    }
}

// Output projection: out = cmb @ Wo (both pre-rounded tf32)
__global__ void __launch_bounds__(128) wo_kernel(float* __restrict__ out)
{
    extern __shared__ unsigned smg[];
    float acc[4][8][4];
    gemm_tf32_acc(smg, g_cmb, g_WoT, HIDN, HD, blockIdx.y * 128, blockIdx.x * 128, acc);
    gemm_store(acc, out, HIDN, blockIdx.y * 128, blockIdx.x * 128);
}

// =============================================================================
// GLA pass 1: grid (NCH, NKV, 2) — z selects a 64-wide d-half.
// =============================================================================
#define P1_SMEM ((64 * 68 * 2 + 64 * 132 + 64) * 4)

__global__ void __launch_bounds__(256) gla_pass1_kernel()
{
    extern __shared__ float sm1[];
    float* GL   = sm1;                 // [64][68]
    float* KW   = GL + 64 * 68;        // [64][68]
    float* Vt   = KW + 64 * 68;        // [64][132]
    float* LEND = Vt + 64 * 132;       // [64]

    const int c = blockIdx.x, kvh = blockIdx.y, z = blockIdx.z;
    const int dbase = z * 64;
    const int tid = threadIdx.x;

    for (int i = tid; i < 64 * 64; i += 256) {
        int r = i >> 6, d = i & 63;
        GL[r * 68 + d] = g_gl[(c * CH + r) * KVD + kvh * DH + dbase + d];
    }
    for (int i = tid; i < 64 * 128; i += 256) {
        int r = i >> 7, d = i & 127;
        Vt[r * 132 + d] = g_v[(c * CH + r) * KVD + kvh * DH + d];
    }
    __syncthreads();

    if (tid < 64) {
        float cum = 0.0f;
#pragma unroll 4
        for (int t = 0; t < CH; t++) {
            cum += GL[t * 68 + tid];
            GL[t * 68 + tid] = expf(cum);
        }
        float le = GL[63 * 68 + tid];
        LEND[tid] = le;
        g_ltot[(kvh * NCH + c) * DH + dbase + tid] = le;
    }
    __syncthreads();

    for (int i = tid; i < 64 * 64; i += 256) {
        int r = i >> 6, d = i & 63;
        int gi = (c * CH + r) * KVD + kvh * DH + dbase + d;
        float lam = GL[r * 68 + d];
        float kdl = g_ks[gi] / lam;
        g_kdl[gi] = kdl;
        g_lam[gi] = lam;
        KW[r * 68 + d] = kdl * LEND[d];
    }
    __syncthreads();

    const int tx = tid & 15, ty = tid >> 4;
    float acc[4][8];
#pragma unroll
    for (int i = 0; i < 4; i++)
#pragma unroll
        for (int j = 0; j < 8; j++) acc[i][j] = 0.0f;

    for (int t = 0; t < CH; t++) {
        float a[4], b[8];
        *(float4*)&a[0] = *(const float4*)&KW[t * 68 + ty * 4];
        *(float4*)&b[0] = *(const float4*)&Vt[t * 132 + tx * 8];
        *(float4*)&b[4] = *(const float4*)&Vt[t * 132 + tx * 8 + 4];
#pragma unroll
        for (int i = 0; i < 4; i++)
#pragma unroll
            for (int j = 0; j < 8; j++) acc[i][j] += a[i] * b[j];
    }

    float* dS = g_dS + (size_t)(kvh * NCH + c) * DH * DH + (size_t)dbase * DH;
#pragma unroll
    for (int i = 0; i < 4; i++) {
        *(float4*)&dS[(ty * 4 + i) * DH + tx * 8]     = make_float4(acc[i][0], acc[i][1], acc[i][2], acc[i][3]);
        *(float4*)&dS[(ty * 4 + i) * DH + tx * 8 + 4] = make_float4(acc[i][4], acc[i][5], acc[i][6], acc[i][7]);
    }
}

// =============================================================================
// GLA pass 2: scan over chunks (separate src/dst, register prefetch).
// =============================================================================
__global__ void __launch_bounds__(128) gla_scan_kernel()
{
    const int kvh = blockIdx.x, d = blockIdx.y;
    const int dp = threadIdx.x;

    __shared__ float lt[NCH];
    if (dp < NCH) lt[dp] = g_ltot[(kvh * NCH + dp) * DH + d];
    __syncthreads();

    const size_t base = (size_t)(kvh * NCH) * DH * DH + (size_t)d * DH + dp;
    const float* __restrict__ src = g_dS + base;
    float* __restrict__ dst = g_S + base;
    const size_t step = (size_t)DH * DH;

    float s = 0.0f;
    float pre[4];
#pragma unroll
    for (int c = 0; c < 4; c++) pre[c] = src[c * step];
#pragma unroll
    for (int c = 0; c < NCH; c++) {
        float v = pre[c & 3];
        if (c + 4 < NCH) pre[c & 3] = src[(c + 4) * step];
        dst[c * step] = s;
        s = s * lt[c] + v;
    }
}

// =============================================================================
// GLA pass 3 (fp32 SIMT, 512 threads): writes 0.5*o_gla into g_gla.
// =============================================================================
__global__ void __launch_bounds__(512) gla_pass3_kernel()
{
    extern __shared__ float sm3[];
    float* QT = sm3;               // [128][65]
    float* KT = QT + 128 * 65;
    float* Ss = KT + 128 * 65;     // [128][132]
    float* Vs = Ss + 128 * 132;    // [64][132]
    float* AT = Vs + 64 * 132;     // [64][65]

    const int c = blockIdx.x, h = blockIdx.y;
    const int kvh = h >> 2;
    const int tid = threadIdx.x;

    for (int idx = tid; idx < CH * DH; idx += 512) {
        int r = idx >> 7, d = idx & 127;
        int kb = (c * CH + r) * KVD + kvh * DH + d;
        float lam = g_lam[kb];
        QT[d * 65 + r] = g_qs[(c * CH + r) * HD + h * DH + d] * lam;
        KT[d * 65 + r] = g_kdl[kb];
        Vs[r * 132 + d] = g_v[kb];
    }
    const float* Sg = g_S + (size_t)(kvh * NCH + c) * DH * DH;
    for (int idx = tid; idx < DH * DH; idx += 512) {
        int r = idx >> 7, d = idx & 127;
        Ss[r * 132 + d] = Sg[r * DH + d];
    }
    __syncthreads();

    const int tx = tid & 15, ty = tid >> 4;   // ty 0..31

    float O[2][8];
#pragma unroll
    for (int i = 0; i < 2; i++)
#pragma unroll
        for (int j = 0; j < 8; j++) O[i][j] = 0.0f;

    for (int dd = 0; dd < DH; dd++) {
        float a[2], b[8];
#pragma unroll
        for (int i = 0; i < 2; i++) a[i] = QT[dd * 65 + ty * 2 + i];
        *(float4*)&b[0] = *(const float4*)&Ss[dd * 132 + tx * 8];
        *(float4*)&b[4] = *(const float4*)&Ss[dd * 132 + tx * 8 + 4];
#pragma unroll
        for (int i = 0; i < 2; i++)
#pragma unroll
            for (int j = 0; j < 8; j++) O[i][j] += a[i] * b[j];
    }

    float Aacc[2][4];
#pragma unroll
    for (int i = 0; i < 2; i++)
#pragma unroll
        for (int j = 0; j < 4; j++) Aacc[i][j] = 0.0f;

    for (int dd = 0; dd < DH; dd++) {
        float a[2], b[4];
#pragma unroll
        for (int i = 0; i < 2; i++) a[i] = QT[dd * 65 + ty * 2 + i];
#pragma unroll
        for (int j = 0; j < 4; j++) b[j] = KT[dd * 65 + tx * 4 + j];
#pragma unroll
        for (int i = 0; i < 2; i++)
#pragma unroll
            for (int j = 0; j < 4; j++) Aacc[i][j] += a[i] * b[j];
    }
#pragma unroll
    for (int i = 0; i < 2; i++)
#pragma unroll
        for (int j = 0; j < 4; j++) {
            int t = ty * 2 + i, s = tx * 4 + j;
            AT[s * 65 + t] = (s <= t) ? Aacc[i][j] : 0.0f;
        }
    __syncthreads();

    for (int s = 0; s < CH; s++) {
        float a[2], b[8];
#pragma unroll
        for (int i = 0; i < 2; i++) a[i] = AT[s * 65 + ty * 2 + i];
        *(float4*)&b[0] = *(const float4*)&Vs[s * 132 + tx * 8];
        *(float4*)&b[4] = *(const float4*)&Vs[s * 132 + tx * 8 + 4];
#pragma unroll
        for (int i = 0; i < 2; i++)
#pragma unroll
            for (int j = 0; j < 8; j++) O[i][j] += a[i] * b[j];
    }

#pragma unroll
    for (int i = 0; i < 2; i++) {
        int t = c * CH + ty * 2 + i;
        float4 o0 = make_float4(0.5f*O[i][0], 0.5f*O[i][1], 0.5f*O[i][2], 0.5f*O[i][3]);
        float4 o1 = make_float4(0.5f*O[i][4], 0.5f*O[i][5], 0.5f*O[i][6], 0.5f*O[i][7]);
        *(float4*)&g_gla[t * HD + h * DH + tx * 8]     = o0;
        *(float4*)&g_gla[t * HD + h * DH + tx * 8 + 4] = o1;
    }
}

// =============================================================================
// Causal flash attention: all operands pre-rounded tf32 — zero cvt in the
// hot loops. Writes 0.5*y into g_y (concurrent with the GLA chain).
// =============================================================================
#define ATTN_SMEM ((128*132 + 2*64*132 + 64*136 + 8*16*68) * 4)   // 204800 B

__global__ void __launch_bounds__(256) attn_tc_kernel()
{
    extern __shared__ char smraw[];
    unsigned* Qs = (unsigned*)smraw;                                    // [128][132]
    unsigned* Ks = (unsigned*)(smraw + 128 * 132 * 4);                  // [2][64][132]
    unsigned* Vs = (unsigned*)(smraw + (128 * 132 + 2 * 64 * 132) * 4); // [64][136]
    unsigned* Pb = (unsigned*)(smraw + (128 * 132 + 2 * 64 * 132 + 64 * 136) * 4);

    const int qt = gridDim.x - 1 - blockIdx.x;
    const int h = blockIdx.y;
    const int kvh = h >> 2;
    const int tid = threadIdx.x;
    const int warp = tid >> 5, lane = tid & 31;
    const int gid = lane >> 2, tig = lane & 3;
    unsigned* Pw = Pb + warp * 16 * 68;
    const float scale = 0.08838834764831845f;
    const int ktmax = 2 * qt + 1;

    {
#pragma unroll
        for (int i = 0; i < 8; i++) {
            int idx = tid + i * 256;
            int r = idx >> 5, c4 = (idx & 31) * 4;
            cp16(&Ks[r * 132 + c4], &g_skT[(size_t)r * KVD + kvh * DH + c4]);
        }
        asm volatile("cp.async.commit_group;");
    }

    for (int i = tid; i < 128 * 32; i += 256) {
        int r = i >> 5, c4 = (i & 31) * 4;
        *(uint4*)&Qs[r * 132 + c4] =
            *(const uint4*)&g_sqT[(size_t)(qt * 128 + r) * HD + h * DH + c4];
    }

    const int rbase = qt * 128 + warp * 16;
    float m_i[2] = {-1e30f, -1e30f};
    float l_i[2] = {0.0f, 0.0f};
    float c[16][4];
#pragma unroll
    for (int ni = 0; ni < 16; ni++)
#pragma unroll
        for (int v = 0; v < 4; v++) c[ni][v] = 0.0f;

    for (int kt = 0; kt <= ktmax; kt++) {
        __syncthreads();

#pragma unroll
        for (int i = 0; i < 8; i++) {
            int idx = tid + i * 256;
            int r = idx >> 5, c4 = (idx & 31) * 4;
            cp16(&Vs[r * 136 + c4], &g_vT[(size_t)(kt * 64 + r) * KVD + kvh * DH + c4]);
        }
        asm volatile("cp.async.commit_group;");

        {
            const int ktn = (kt < ktmax) ? kt + 1 : kt;
            unsigned* KB = Ks + ((kt + 1) & 1) * 64 * 132;
#pragma unroll
            for (int i = 0; i < 8; i++) {
                int idx = tid + i * 256;
                int r = idx >> 5, c4 = (idx & 31) * 4;
                cp16(&KB[r * 132 + c4], &g_skT[(size_t)(ktn * 64 + r) * KVD + kvh * DH + c4]);
            }
            asm volatile("cp.async.commit_group;");
        }

        asm volatile("cp.async.wait_group 2;");
        __syncthreads();

        const unsigned* KB = Ks + (kt & 1) * 64 * 132;
        const int smin = kt * 64;
        const bool active = (smin <= rbase + 15);

        if (active) {
            float sacc[8][4];
#pragma unroll
            for (int ni = 0; ni < 8; ni++)
#pragma unroll
                for (int v = 0; v < 4; v++) sacc[ni][v] = 0.0f;

#pragma unroll 4
            for (int k8 = 0; k8 < 16; k8++) {
                unsigned aq[4];
                int qr = warp * 16 + gid;
                aq[0] = Qs[qr * 132 + k8 * 8 + tig];
                aq[1] = Qs[(qr + 8) * 132 + k8 * 8 + tig];
                aq[2] = Qs[qr * 132 + k8 * 8 + tig + 4];
                aq[3] = Qs[(qr + 8) * 132 + k8 * 8 + tig + 4];
#pragma unroll
                for (int ni = 0; ni < 8; ni++) {
                    unsigned b0 = KB[(ni * 8 + gid) * 132 + k8 * 8 + tig];
                    unsigned b1 = KB[(ni * 8 + gid) * 132 + k8 * 8 + tig + 4];
                    mma_tf32(sacc[ni], aq, b0, b1);
                }
            }

            const bool partial = (smin + 63 > rbase);
#pragma unroll
            for (int ni = 0; ni < 8; ni++)
#pragma unroll
                for (int v = 0; v < 4; v++) {
                    float sv = sacc[ni][v] * scale;
                    if (partial) {
                        int row = rbase + gid + (v >> 1) * 8;
                        int col = smin + ni * 8 + tig * 2 + (v & 1);
                        if (col > row) sv = -1e30f;
                    }
                    sacc[ni][v] = sv;
                }

#pragma unroll
            for (int h2 = 0; h2 < 2; h2++) {
                float rmax = -1e30f;
#pragma unroll
                for (int ni = 0; ni < 8; ni++)
                    rmax = fmaxf(rmax, fmaxf(sacc[ni][2 * h2], sacc[ni][2 * h2 + 1]));
                rmax = fmaxf(rmax, __shfl_xor_sync(0xffffffffu, rmax, 1));
                rmax = fmaxf(rmax, __shfl_xor_sync(0xffffffffu, rmax, 2));
                float mnew = fmaxf(m_i[h2], rmax);
                float alpha = __expf(m_i[h2] - mnew);
                float rsum = 0.0f;
#pragma unroll
                for (int ni = 0; ni < 8; ni++) {
                    float p0 = __expf(sacc[ni][2 * h2] - mnew);
                    float p1 = __expf(sacc[ni][2 * h2 + 1] - mnew);
                    sacc[ni][2 * h2] = p0;
                    sacc[ni][2 * h2 + 1] = p1;
                    rsum += p0 + p1;
                }
                rsum += __shfl_xor_sync(0xffffffffu, rsum, 1);
                rsum += __shfl_xor_sync(0xffffffffu, rsum, 2);
                l_i[h2] = l_i[h2] * alpha + rsum;
                m_i[h2] = mnew;
#pragma unroll
                for (int ni = 0; ni < 16; ni++) {
                    c[ni][2 * h2]     *= alpha;
                    c[ni][2 * h2 + 1] *= alpha;
                }
            }

#pragma unroll
            for (int ni = 0; ni < 8; ni++) {
                *(uint2*)&Pw[gid * 68 + ni * 8 + tig * 2] =
                    make_uint2(f2tf(sacc[ni][0]), f2tf(sacc[ni][1]));
                *(uint2*)&Pw[(gid + 8) * 68 + ni * 8 + tig * 2] =
                    make_uint2(f2tf(sacc[ni][2]), f2tf(sacc[ni][3]));
            }
        }

        asm volatile("cp.async.wait_group 1;");
        __syncthreads();

        if (active) {
#pragma unroll 2
            for (int k8 = 0; k8 < 8; k8++) {
                unsigned ap[4];
                ap[0] = Pw[gid * 68 + k8 * 8 + tig];
                ap[1] = Pw[(gid + 8) * 68 + k8 * 8 + tig];
                ap[2] = Pw[gid * 68 + k8 * 8 + tig + 4];
                ap[3] = Pw[(gid + 8) * 68 + k8 * 8 + tig + 4];
#pragma unroll
                for (int ni = 0; ni < 16; ni++) {
                    unsigned b0 = Vs[(k8 * 8 + tig) * 136 + ni * 8 + gid];
                    unsigned b1 = Vs[(k8 * 8 + tig + 4) * 136 + ni * 8 + gid];
                    mma_tf32(c[ni], ap, b0, b1);
                }
            }
        }
    }

    const float h0 = 0.5f / l_i[0];
    const float h1 = 0.5f / l_i[1];
    const int r0 = rbase + gid, r1 = r0 + 8;
#pragma unroll
    for (int ni = 0; ni < 16; ni++) {
        int col = h * DH + ni * 8 + tig * 2;
        *(float2*)&g_y[(size_t)r0 * HD + col] = make_float2(c[ni][0] * h0, c[ni][1] * h0);
        *(float2*)&g_y[(size_t)r1 * HD + col] = make_float2(c[ni][2] * h1, c[ni][3] * h1);
    }
}

// =============================================================================
// host launcher — fork/join: GLA chain (stream A) || attention (stream B)
// =============================================================================
extern "C" void kernel_launch(void* const* d_in, const int* in_sizes, int n_in,
                              void* d_out, int out_size)
{
    (void)in_sizes; (void)n_in; (void)out_size;
    const float* hs = (const float*)d_in[0];
    const float* Wq = (const float*)d_in[1];
    const float* Wk = (const float*)d_in[2];
    const float* Wv = (const float*)d_in[3];
    const float* Wo = (const float*)d_in[4];
    float* out = (float*)d_out;

    unsigned* p_WoT;
    cudaGetSymbolAddress((void**)&p_WoT, g_WoT);

    static cudaStream_t sA = nullptr, sB = nullptr;
    static cudaEvent_t ev0, evP, evA, evB;
    if (sA == nullptr) {
        cudaStreamCreateWithFlags(&sA, cudaStreamNonBlocking);
        cudaStreamCreateWithFlags(&sB, cudaStreamNonBlocking);
        cudaEventCreateWithFlags(&ev0, cudaEventDisableTiming);
        cudaEventCreateWithFlags(&evP, cudaEventDisableTiming);
        cudaEventCreateWithFlags(&evA, cudaEventDisableTiming);
        cudaEventCreateWithFlags(&evB, cudaEventDisableTiming);
    }

    const int smem3 = (2 * 128 * 65 + 128 * 132 + 64 * 132 + 64 * 65) * 4;
    cudaFuncSetAttribute(proj_kernel,      cudaFuncAttributeMaxDynamicSharedMemorySize, GEMM_SMEM);
    cudaFuncSetAttribute(wo_kernel,        cudaFuncAttributeMaxDynamicSharedMemorySize, GEMM_SMEM);
    cudaFuncSetAttribute(gla_pass1_kernel, cudaFuncAttributeMaxDynamicSharedMemorySize, P1_SMEM);
    cudaFuncSetAttribute(gla_pass3_kernel, cudaFuncAttributeMaxDynamicSharedMemorySize, smem3);
    cudaFuncSetAttribute(attn_tc_kernel,   cudaFuncAttributeMaxDynamicSharedMemorySize, ATTN_SMEM);

    // --- fork Wo conversion onto stream A early (only wo needs it) ---
    cudaEventRecord(ev0, 0);
    cudaStreamWaitEvent(sA, ev0, 0);
    cvt_kernel<<<4096, 256, 0, sA>>>((const float4*)Wo, (uint4*)p_WoT, HD * HIDN / 4);

    // --- main stream: rope table + fused operand pre-rounding + projections ---
    rope_table_kernel<<<NTOK, 64>>>();
    cvt_all_kernel<<<(N4_HS + N4_WQ + 2 * N4_WK) / 256, 256>>>(
        (const float4*)hs, (const float4*)Wq, (const float4*)Wk, (const float4*)Wv);
    proj_kernel<<<dim3(24, 16), 128, GEMM_SMEM>>>();
    cudaEventRecord(evP, 0);

    // --- stream A: GLA chain ---
    cudaStreamWaitEvent(sA, evP, 0);
    gla_pass1_kernel<<<dim3(NCH, NKV, 2), 256, P1_SMEM, sA>>>();
    gla_scan_kernel<<<dim3(NKV, DH), 128, 0, sA>>>();
    gla_pass3_kernel<<<dim3(NCH, NH), 512, smem3, sA>>>();
    cudaEventRecord(evA, sA);

    // --- stream B: causal flash attention (concurrent with GLA chain) ---
    cudaStreamWaitEvent(sB, evP, 0);
    attn_tc_kernel<<<dim3(NTOK / 128, NH), 256, ATTN_SMEM, sB>>>();
    cudaEventRecord(evB, sB);

    // --- join, combine, output projection ---
    cudaStreamWaitEvent(0, evA, 0);
    cudaStreamWaitEvent(0, evB, 0);
    combine_kernel<<<NTOK * HD / 4 / 256, 256>>>();
    wo_kernel<<<dim3(16, 16), 128, GEMM_SMEM>>>(out);
}